// round 2
// baseline (speedup 1.0000x reference)
#include <cuda_runtime.h>
#include <math.h>

#define N_ATOMS 16384
#define APC     64
#define N_CONF  256
#define N_MOL   64
#define DEG     32
#define EDGES   (N_ATOMS * DEG)     // 524288
#define H       128
#define G       50
#define NLAYER  6

// ---------------- scratch (device globals; no runtime allocation) ----------
__device__ float g_ea[(size_t)EDGES * G];   // gaussian-smeared edge attrs
__device__ float g_c[EDGES];                // cosine cutoff per edge
__device__ float g_h[N_ATOMS * H];          // node features
__device__ float g_conf[N_CONF * H];        // per-conformer embedding

__device__ __forceinline__ float ssp(float x) {
    // softplus(x) - log(2)
    float sp = (x > 20.0f) ? x : log1pf(__expf(x));
    return sp - 0.69314718055994531f;
}

// ---------------- edge precompute: distance, cutoff, gaussian smearing -----
__global__ void precompute_kernel(const float* __restrict__ pos,
                                  const int* __restrict__ ei) {
    int e = blockIdx.x * blockDim.x + threadIdx.x;
    if (e >= EDGES) return;
    int r = ei[e];
    int c = ei[EDGES + e];
    float dx = pos[3 * r + 0] - pos[3 * c + 0];
    float dy = pos[3 * r + 1] - pos[3 * c + 1];
    float dz = pos[3 * r + 2] - pos[3 * c + 2];
    float d = sqrtf(dx * dx + dy * dy + dz * dz);
    g_c[e] = 0.5f * (cosf(d * 0.31415926535897931f) + 1.0f);   // pi/10
    const float delta = 10.0f / 49.0f;
    const float coeff = -0.5f / (delta * delta);
    float* dst = g_ea + (size_t)e * G;
#pragma unroll
    for (int k = 0; k < G; k++) {
        float t = d - (float)k * delta;
        dst[k] = expf(coeff * t * t);
    }
}

// ---------------- h0 = emb[z] ---------------------------------------------
__global__ void hinit_kernel(const int* __restrict__ z,
                             const float* __restrict__ emb) {
    int idx = blockIdx.x * blockDim.x + threadIdx.x;
    if (idx >= N_ATOMS * H) return;
    int a = idx >> 7;
    int c = idx & 127;
    g_h[idx] = emb[z[a] * H + c];
}

// ---------------- fused per-conformer interaction layer --------------------
// Block = 1 conformer (64 atoms, 2048 edges), 256 threads.
// SMEM layout (floats):
//   [0, 8192)      s_xf
//   [8192, 16384)  s_agg
//   [16384, ...)   region A (phase-dependent)
//     phase1: s_h(8192) | s_w(16384)
//     phase2: s_w1(6400) | s_w2(16384) | s_ea(3200) | s_u(8192) | row(64) | c(64)
//             s_red overlays s_ea (1024)
//     phase3: s_w(16384) | s_t(8192)
#define SMEM_FLOATS 50688

__global__ void __launch_bounds__(256, 1)
layer_kernel(const int* __restrict__ ei,
             const float* __restrict__ mw1, const float* __restrict__ mb1,
             const float* __restrict__ mw2, const float* __restrict__ mb2,
             const float* __restrict__ cw1, const float* __restrict__ cw2,
             const float* __restrict__ cb2,
             const float* __restrict__ iw,  const float* __restrict__ ib,
             int l) {
    extern __shared__ float sm[];
    const float* W1  = mw1 + (size_t)l * G * H;
    const float* B1  = mb1 + l * H;
    const float* W2  = mw2 + (size_t)l * H * H;
    const float* B2  = mb2 + l * H;
    const float* CW1 = cw1 + (size_t)l * H * H;
    const float* CW2 = cw2 + (size_t)l * H * H;
    const float* CB2 = cb2 + l * H;
    const float* IW  = iw  + (size_t)l * H * H;
    const float* IB  = ib  + l * H;

    const int conf = blockIdx.x;
    const int tid  = threadIdx.x;
    const int warp = tid >> 5;
    const int lane = tid & 31;
    const int c0   = lane * 4;

    float* s_xf  = sm;
    float* s_agg = sm + 8192;
    float* A     = sm + 16384;

    // ================= phase 1: xf = h @ cf_w1, zero agg =================
    {
        float* s_h = A;
        float* s_w = A + 8192;
        const float4* hsrc = (const float4*)(g_h + (size_t)conf * APC * H);
        float4* hdst = (float4*)s_h;
        for (int i = tid; i < APC * H / 4; i += 256) hdst[i] = hsrc[i];
        const float4* wsrc = (const float4*)CW1;
        float4* wdst = (float4*)s_w;
        for (int i = tid; i < H * H / 4; i += 256) wdst[i] = wsrc[i];
        for (int i = tid; i < APC * H; i += 256) s_agg[i] = 0.0f;
        __syncthreads();

        int r0 = warp * 8;
        float acc[8][4];
#pragma unroll
        for (int r = 0; r < 8; r++)
#pragma unroll
            for (int j = 0; j < 4; j++) acc[r][j] = 0.0f;
#pragma unroll 2
        for (int k = 0; k < H; k++) {
            float4 wv = *(const float4*)(s_w + k * H + c0);
#pragma unroll
            for (int r = 0; r < 8; r++) {
                float a = s_h[(r0 + r) * H + k];
                acc[r][0] += a * wv.x; acc[r][1] += a * wv.y;
                acc[r][2] += a * wv.z; acc[r][3] += a * wv.w;
            }
        }
#pragma unroll
        for (int r = 0; r < 8; r++)
            *(float4*)(s_xf + (r0 + r) * H + c0) =
                make_float4(acc[r][0], acc[r][1], acc[r][2], acc[r][3]);
        __syncthreads();   // region A free for phase 2
    }

    // ================= phase 2: edge filter + message + aggregate ========
    {
        float* s_w1  = A;
        float* s_w2  = A + 6400;
        float* s_ea  = A + 22784;
        float* s_u   = A + 25984;
        int*   s_row = (int*)(A + 34176);
        float* s_c   = A + 34240;
        float* s_red = s_ea;   // overlay, safe per the sync pattern below

        {
            const float4* w1s = (const float4*)W1;
            float4* d1 = (float4*)s_w1;
            for (int i = tid; i < G * H / 4; i += 256) d1[i] = w1s[i];
            const float4* w2s = (const float4*)W2;
            float4* d2 = (float4*)s_w2;
            for (int i = tid; i < H * H / 4; i += 256) d2[i] = w2s[i];
        }
        float4 b1v = *(const float4*)(B1 + c0);
        float4 b2v = *(const float4*)(B2 + c0);

        const int ebase = conf * APC * DEG;   // 2048 edges per conformer

        for (int t = 0; t < 32; t++) {
            __syncthreads();   // prev reduction done / weights visible
            {
                const float4* easrc =
                    (const float4*)(g_ea + (size_t)(ebase + t * 64) * G);
                float4* eadst = (float4*)s_ea;
                for (int i = tid; i < 64 * G / 4; i += 256) eadst[i] = easrc[i];
                if (tid < 64) {
                    int e = ebase + t * 64 + tid;
                    s_row[tid] = ei[e] - conf * APC;
                    s_c[tid] = g_c[e];
                }
            }
            __syncthreads();

            // --- GEMM1: T = EA @ W1 + b1, ssp -> s_u ---
            {
                int e0 = warp * 8;
                float acc[8][4];
#pragma unroll
                for (int e = 0; e < 8; e++) {
                    acc[e][0] = b1v.x; acc[e][1] = b1v.y;
                    acc[e][2] = b1v.z; acc[e][3] = b1v.w;
                }
#pragma unroll 2
                for (int k = 0; k < G; k++) {
                    float4 wv = *(const float4*)(s_w1 + k * H + c0);
#pragma unroll
                    for (int e = 0; e < 8; e++) {
                        float a = s_ea[(e0 + e) * G + k];
                        acc[e][0] += a * wv.x; acc[e][1] += a * wv.y;
                        acc[e][2] += a * wv.z; acc[e][3] += a * wv.w;
                    }
                }
#pragma unroll
                for (int e = 0; e < 8; e++) {
                    float4 v;
                    v.x = ssp(acc[e][0]); v.y = ssp(acc[e][1]);
                    v.z = ssp(acc[e][2]); v.w = ssp(acc[e][3]);
                    *(float4*)(s_u + (e0 + e) * H + c0) = v;
                }
            }
            __syncthreads();

            // --- GEMM2: Wf = U @ W2 + b2; msg = xf[row]*Wf*C; warp-reduce ---
            {
                int e0 = warp * 8;
                float acc[8][4];
#pragma unroll
                for (int e = 0; e < 8; e++)
#pragma unroll
                    for (int j = 0; j < 4; j++) acc[e][j] = 0.0f;
#pragma unroll 2
                for (int k = 0; k < H; k++) {
                    float4 wv = *(const float4*)(s_w2 + k * H + c0);
#pragma unroll
                    for (int e = 0; e < 8; e++) {
                        float a = s_u[(e0 + e) * H + k];
                        acc[e][0] += a * wv.x; acc[e][1] += a * wv.y;
                        acc[e][2] += a * wv.z; acc[e][3] += a * wv.w;
                    }
                }
                float s0 = 0.f, s1 = 0.f, s2 = 0.f, s3 = 0.f;
#pragma unroll
                for (int e = 0; e < 8; e++) {
                    int row = s_row[e0 + e];
                    float ce = s_c[e0 + e];
                    float4 xv = *(const float4*)(s_xf + row * H + c0);
                    s0 += xv.x * ((acc[e][0] + b2v.x) * ce);
                    s1 += xv.y * ((acc[e][1] + b2v.y) * ce);
                    s2 += xv.z * ((acc[e][2] + b2v.z) * ce);
                    s3 += xv.w * ((acc[e][3] + b2v.w) * ce);
                }
                *(float4*)(s_red + warp * H + c0) = make_float4(s0, s1, s2, s3);
            }
            __syncthreads();

            // --- reduce 4 warps -> agg (each tile owns atoms 2t, 2t+1) ---
            {
                int slot = tid >> 7;      // 0..1 (atom within tile)
                int col  = tid & 127;
                float v = s_red[(slot * 4 + 0) * H + col]
                        + s_red[(slot * 4 + 1) * H + col]
                        + s_red[(slot * 4 + 2) * H + col]
                        + s_red[(slot * 4 + 3) * H + col];
                s_agg[(t * 2 + slot) * H + col] = v;
            }
        }
        __syncthreads();
    }

    // ================= phase 3: node update ===============================
    {
        float* s_w = A;
        float* s_t = A + 16384;
        {
            const float4* wsrc = (const float4*)CW2;
            float4* wdst = (float4*)s_w;
            for (int i = tid; i < H * H / 4; i += 256) wdst[i] = wsrc[i];
        }
        float4 cb2v = *(const float4*)(CB2 + c0);
        float4 ibv  = *(const float4*)(IB + c0);
        __syncthreads();

        int r0 = warp * 8;
        {
            float acc[8][4];
#pragma unroll
            for (int r = 0; r < 8; r++) {
                acc[r][0] = cb2v.x; acc[r][1] = cb2v.y;
                acc[r][2] = cb2v.z; acc[r][3] = cb2v.w;
            }
#pragma unroll 2
            for (int k = 0; k < H; k++) {
                float4 wv = *(const float4*)(s_w + k * H + c0);
#pragma unroll
                for (int r = 0; r < 8; r++) {
                    float a = s_agg[(r0 + r) * H + k];
                    acc[r][0] += a * wv.x; acc[r][1] += a * wv.y;
                    acc[r][2] += a * wv.z; acc[r][3] += a * wv.w;
                }
            }
#pragma unroll
            for (int r = 0; r < 8; r++) {
                float4 v;
                v.x = ssp(acc[r][0]); v.y = ssp(acc[r][1]);
                v.z = ssp(acc[r][2]); v.w = ssp(acc[r][3]);
                *(float4*)(s_t + (r0 + r) * H + c0) = v;
            }
        }
        __syncthreads();
        {
            const float4* wsrc = (const float4*)IW;
            float4* wdst = (float4*)s_w;
            for (int i = tid; i < H * H / 4; i += 256) wdst[i] = wsrc[i];
        }
        __syncthreads();
        {
            float acc[8][4];
#pragma unroll
            for (int r = 0; r < 8; r++) {
                acc[r][0] = ibv.x; acc[r][1] = ibv.y;
                acc[r][2] = ibv.z; acc[r][3] = ibv.w;
            }
#pragma unroll 2
            for (int k = 0; k < H; k++) {
                float4 wv = *(const float4*)(s_w + k * H + c0);
#pragma unroll
                for (int r = 0; r < 8; r++) {
                    float a = s_t[(r0 + r) * H + k];
                    acc[r][0] += a * wv.x; acc[r][1] += a * wv.y;
                    acc[r][2] += a * wv.z; acc[r][3] += a * wv.w;
                }
            }
#pragma unroll
            for (int r = 0; r < 8; r++) {
                float* hp = g_h + ((size_t)conf * APC + r0 + r) * H + c0;
                float4 old = *(const float4*)hp;
                *(float4*)hp = make_float4(old.x + acc[r][0], old.y + acc[r][1],
                                           old.z + acc[r][2], old.w + acc[r][3]);
            }
        }
    }
}

// ---------------- readout: per-atom MLP + per-conformer sum ----------------
// SMEM floats: s_h(8192) | s_w(16384) | s_t(8192) | s_red(1024) = 33792
__global__ void __launch_bounds__(256, 1)
readout_kernel(const float* __restrict__ ow1, const float* __restrict__ ob1,
               const float* __restrict__ ow2, const float* __restrict__ ob2) {
    extern __shared__ float sm[];
    float* s_h   = sm;
    float* s_w   = sm + 8192;
    float* s_t   = sm + 24576;
    float* s_red = sm + 32768;

    const int conf = blockIdx.x;
    const int tid  = threadIdx.x;
    const int warp = tid >> 5;
    const int lane = tid & 31;
    const int c0   = lane * 4;
    const int r0   = warp * 8;

    {
        const float4* hsrc = (const float4*)(g_h + (size_t)conf * APC * H);
        float4* hdst = (float4*)s_h;
        for (int i = tid; i < APC * H / 4; i += 256) hdst[i] = hsrc[i];
        const float4* wsrc = (const float4*)ow1;
        float4* wdst = (float4*)s_w;
        for (int i = tid; i < H * H / 4; i += 256) wdst[i] = wsrc[i];
    }
    float4 b1v = *(const float4*)(ob1 + c0);
    float4 b2v = *(const float4*)(ob2 + c0);
    __syncthreads();

    {
        float acc[8][4];
#pragma unroll
        for (int r = 0; r < 8; r++) {
            acc[r][0] = b1v.x; acc[r][1] = b1v.y;
            acc[r][2] = b1v.z; acc[r][3] = b1v.w;
        }
#pragma unroll 2
        for (int k = 0; k < H; k++) {
            float4 wv = *(const float4*)(s_w + k * H + c0);
#pragma unroll
            for (int r = 0; r < 8; r++) {
                float a = s_h[(r0 + r) * H + k];
                acc[r][0] += a * wv.x; acc[r][1] += a * wv.y;
                acc[r][2] += a * wv.z; acc[r][3] += a * wv.w;
            }
        }
#pragma unroll
        for (int r = 0; r < 8; r++) {
            float4 v;
            v.x = ssp(acc[r][0]); v.y = ssp(acc[r][1]);
            v.z = ssp(acc[r][2]); v.w = ssp(acc[r][3]);
            *(float4*)(s_t + (r0 + r) * H + c0) = v;
        }
    }
    __syncthreads();
    {
        const float4* wsrc = (const float4*)ow2;
        float4* wdst = (float4*)s_w;
        for (int i = tid; i < H * H / 4; i += 256) wdst[i] = wsrc[i];
    }
    __syncthreads();
    {
        float acc[8][4];
#pragma unroll
        for (int r = 0; r < 8; r++) {
            acc[r][0] = b2v.x; acc[r][1] = b2v.y;
            acc[r][2] = b2v.z; acc[r][3] = b2v.w;
        }
#pragma unroll 2
        for (int k = 0; k < H; k++) {
            float4 wv = *(const float4*)(s_w + k * H + c0);
#pragma unroll
            for (int r = 0; r < 8; r++) {
                float a = s_t[(r0 + r) * H + k];
                acc[r][0] += a * wv.x; acc[r][1] += a * wv.y;
                acc[r][2] += a * wv.z; acc[r][3] += a * wv.w;
            }
        }
        // column partial-sums over this warp's 8 rows
        float s0 = 0.f, s1 = 0.f, s2 = 0.f, s3 = 0.f;
#pragma unroll
        for (int r = 0; r < 8; r++) {
            s0 += acc[r][0]; s1 += acc[r][1]; s2 += acc[r][2]; s3 += acc[r][3];
        }
        *(float4*)(s_red + warp * H + c0) = make_float4(s0, s1, s2, s3);
    }
    __syncthreads();
    if (tid < H) {
        float v = 0.f;
#pragma unroll
        for (int w = 0; w < 8; w++) v += s_red[w * H + tid];
        g_conf[conf * H + tid] = v;
    }
}

// ---------------- final: mol sum + head MLP -------------------------------
// SMEM floats: s_mol(8192) | s_hid(4096) = 12288
__global__ void __launch_bounds__(256, 1)
final_kernel(const float* __restrict__ hw1, const float* __restrict__ hb1,
             const float* __restrict__ hw2, const float* __restrict__ hb2,
             float* __restrict__ out) {
    extern __shared__ float sm[];
    float* s_mol = sm;
    float* s_hid = sm + 8192;
    const int tid = threadIdx.x;

    for (int idx = tid; idx < N_MOL * H; idx += 256) {
        int m = idx >> 7;
        int c = idx & 127;
        float v = g_conf[(m * 4 + 0) * H + c] + g_conf[(m * 4 + 1) * H + c]
                + g_conf[(m * 4 + 2) * H + c] + g_conf[(m * 4 + 3) * H + c];
        s_mol[idx] = v;
    }
    __syncthreads();
    for (int idx = tid; idx < N_MOL * 64; idx += 256) {
        int m = idx >> 6;
        int j = idx & 63;
        float acc = hb1[j];
#pragma unroll 4
        for (int k = 0; k < H; k++) acc += s_mol[m * H + k] * hw1[k * 64 + j];
        s_hid[idx] = ssp(acc);
    }
    __syncthreads();
    if (tid < N_MOL) {
        float acc = hb2[0];
#pragma unroll 4
        for (int j = 0; j < 64; j++) acc += s_hid[tid * 64 + j] * hw2[j];
        out[tid] = acc;
    }
}

// ---------------- launch ---------------------------------------------------
extern "C" void kernel_launch(void* const* d_in, const int* in_sizes, int n_in,
                              void* d_out, int out_size) {
    const int*   z   = (const int*)d_in[0];
    const float* pos = (const float*)d_in[1];
    const int*   ei  = (const int*)d_in[2];
    // d_in[3]=atom_to_conf, d_in[4]=conf_to_mol: layout is deterministic (a/64, c/4)
    const float* emb = (const float*)d_in[5];
    const float* mw1 = (const float*)d_in[6];
    const float* mb1 = (const float*)d_in[7];
    const float* mw2 = (const float*)d_in[8];
    const float* mb2 = (const float*)d_in[9];
    const float* cw1 = (const float*)d_in[10];
    const float* cw2 = (const float*)d_in[11];
    const float* cb2 = (const float*)d_in[12];
    const float* iw  = (const float*)d_in[13];
    const float* ib  = (const float*)d_in[14];
    const float* ow1 = (const float*)d_in[15];
    const float* ob1 = (const float*)d_in[16];
    const float* ow2 = (const float*)d_in[17];
    const float* ob2 = (const float*)d_in[18];
    const float* hw1 = (const float*)d_in[19];
    const float* hb1 = (const float*)d_in[20];
    const float* hw2 = (const float*)d_in[21];
    const float* hb2 = (const float*)d_in[22];
    float* out = (float*)d_out;

    cudaFuncSetAttribute(layer_kernel, cudaFuncAttributeMaxDynamicSharedMemorySize,
                         SMEM_FLOATS * 4);
    cudaFuncSetAttribute(readout_kernel, cudaFuncAttributeMaxDynamicSharedMemorySize,
                         33792 * 4);
    cudaFuncSetAttribute(final_kernel, cudaFuncAttributeMaxDynamicSharedMemorySize,
                         12288 * 4);

    precompute_kernel<<<EDGES / 256, 256>>>(pos, ei);
    hinit_kernel<<<(N_ATOMS * H) / 256, 256>>>(z, emb);
    for (int l = 0; l < NLAYER; l++) {
        layer_kernel<<<N_CONF, 256, SMEM_FLOATS * 4>>>(
            ei, mw1, mb1, mw2, mb2, cw1, cw2, cb2, iw, ib, l);
    }
    readout_kernel<<<N_CONF, 256, 33792 * 4>>>(ow1, ob1, ow2, ob2);
    final_kernel<<<1, 256, 12288 * 4>>>(hw1, hb1, hw2, hb2, out);
}

// round 7
// speedup vs baseline: 2.6101x; 2.6101x over previous
#include <cuda_runtime.h>
#include <cuda_fp16.h>
#include <math.h>
#include <stdint.h>

#define N_ATOMS 16384
#define APC     64
#define N_CONF  256
#define N_MOL   64
#define DEG     32
#define EDGES   (N_ATOMS * DEG)     // 524288
#define H       128
#define G       50
#define GPAD    64
#define NLAYER  6

// ---------------- device scratch (16B aligned for vector access) ----------
__device__ __align__(16) __half g_ea[(size_t)EDGES * GPAD];
__device__ __align__(16) float  g_c[EDGES];
__device__ __align__(16) int    g_rowloc[EDGES];
__device__ __align__(16) float  g_h[N_ATOMS * H];
__device__ __align__(16) __half g_hhf[N_ATOMS * H];
__device__ __align__(16) float  g_xf[N_ATOMS * H];
__device__ __align__(16) float  g_agg[N_ATOMS * H];
__device__ __align__(16) float  g_conf[N_CONF * H];
// transposed fp16 weights: [l][n][k]
__device__ __align__(16) __half g_w1t[NLAYER * H * GPAD];
__device__ __align__(16) __half g_w2t[NLAYER * H * H];
__device__ __align__(16) __half g_cw1t[NLAYER * H * H];
__device__ __align__(16) __half g_cw2t[NLAYER * H * H];
__device__ __align__(16) __half g_iwt[NLAYER * H * H];
__device__ __align__(16) __half g_ow1t[H * H];
__device__ __align__(16) __half g_ow2t[H * H];

__device__ __forceinline__ float ssp(float x) {
    float sp = (x > 20.0f) ? x : log1pf(__expf(x));
    return sp - 0.69314718055994531f;
}

__device__ __forceinline__ uint32_t smem_u32(const void* p) {
    uint32_t a;
    asm("{ .reg .u64 t; cvta.to.shared.u64 t, %1; cvt.u32.u64 %0, t; }" : "=r"(a) : "l"(p));
    return a;
}
__device__ __forceinline__ void ldm_x4(uint32_t& r0, uint32_t& r1, uint32_t& r2, uint32_t& r3,
                                       uint32_t a) {
    asm volatile("ldmatrix.sync.aligned.m8n8.x4.shared.b16 {%0,%1,%2,%3}, [%4];"
                 : "=r"(r0), "=r"(r1), "=r"(r2), "=r"(r3) : "r"(a));
}
__device__ __forceinline__ void ldm_x2(uint32_t& r0, uint32_t& r1, uint32_t a) {
    asm volatile("ldmatrix.sync.aligned.m8n8.x2.shared.b16 {%0,%1}, [%2];"
                 : "=r"(r0), "=r"(r1) : "r"(a));
}
__device__ __forceinline__ void mma16816(float* c, const uint32_t* a, const uint32_t* b) {
    asm volatile(
        "mma.sync.aligned.m16n8k16.row.col.f32.f16.f16.f32 "
        "{%0,%1,%2,%3}, {%4,%5,%6,%7}, {%8,%9}, {%0,%1,%2,%3};"
        : "+f"(c[0]), "+f"(c[1]), "+f"(c[2]), "+f"(c[3])
        : "r"(a[0]), "r"(a[1]), "r"(a[2]), "r"(a[3]), "r"(b[0]), "r"(b[1]));
}
__device__ __forceinline__ uint32_t h2u(float a, float b) {
    __half2 p = __floats2half2_rn(a, b);
    return *(uint32_t*)&p;
}

// ---------------- prep kernels ----------------
__global__ void transpose_w(const float* __restrict__ src, __half* __restrict__ dst,
                            int L, int K, int N, int Kpad) {
    int idx = blockIdx.x * blockDim.x + threadIdx.x;
    int tot = L * N * Kpad;
    if (idx >= tot) return;
    int k = idx % Kpad;
    int n = (idx / Kpad) % N;
    int l = idx / (Kpad * N);
    float v = (k < K) ? src[(size_t)l * K * N + (size_t)k * N + n] : 0.0f;
    dst[idx] = __float2half(v);
}

__global__ void precompute_kernel(const float* __restrict__ pos, const int* __restrict__ ei) {
    int idx = blockIdx.x * blockDim.x + threadIdx.x;
    if (idx >= EDGES * 4) return;
    int e = idx >> 2, q = idx & 3;
    int r = ei[e], c = ei[EDGES + e];
    float dx = pos[3 * r + 0] - pos[3 * c + 0];
    float dy = pos[3 * r + 1] - pos[3 * c + 1];
    float dz = pos[3 * r + 2] - pos[3 * c + 2];
    float d = sqrtf(dx * dx + dy * dy + dz * dz);
    if (q == 0) {
        g_c[e] = 0.5f * (__cosf(d * 0.31415926535897931f) + 1.0f);
        g_rowloc[e] = r & (APC - 1);
    }
    const float delta = 10.0f / 49.0f;
    const float coeff = -0.5f / (delta * delta);
    uint32_t out[8];
#pragma unroll
    for (int i = 0; i < 8; i++) {
        int k0 = q * 16 + 2 * i;
        float t0 = d - (float)k0 * delta;
        float t1 = d - (float)(k0 + 1) * delta;
        float v0 = (k0 < G) ? __expf(coeff * t0 * t0) : 0.0f;
        float v1 = (k0 + 1 < G) ? __expf(coeff * t1 * t1) : 0.0f;
        out[i] = h2u(v0, v1);
    }
    uint4* dst = (uint4*)(g_ea + (size_t)e * GPAD + q * 16);
    dst[0] = make_uint4(out[0], out[1], out[2], out[3]);
    dst[1] = make_uint4(out[4], out[5], out[6], out[7]);
}

__global__ void hinit_kernel(const int* __restrict__ z, const float* __restrict__ emb) {
    int idx = blockIdx.x * blockDim.x + threadIdx.x;
    if (idx >= N_ATOMS * H) return;
    float v = emb[z[idx >> 7] * H + (idx & 127)];
    g_h[idx] = v;
    g_hhf[idx] = __float2half(v);
}

// ---------------- xf = h @ cf_w1[l] : one GEMM, 128-atom tiles ----------------
// smem: sA [128][136]h (34816) | sW [128][136]h (34816)
__global__ void __launch_bounds__(256, 1)
xf_kernel(int l) {
    extern __shared__ char sm[];
    __half* sA = (__half*)sm;
    __half* sW = (__half*)(sm + 34816);
    const int tid = threadIdx.x, w = tid >> 5, lane = tid & 31;
    const int g = lane >> 2, t = lane & 3;
    const int tile = blockIdx.x;

    {
        const uint4* asrc = (const uint4*)(g_hhf + (size_t)tile * 128 * H);
        const uint4* wsrc = (const uint4*)(g_cw1t + (size_t)l * H * H);
        for (int i = tid; i < 2048; i += 256) {
            int r = i >> 4, c = i & 15;
            *(uint4*)(sA + r * 136 + c * 8) = asrc[i];
            *(uint4*)(sW + r * 136 + c * 8) = wsrc[i];
        }
    }
    __syncthreads();

    float C[16][4];
#pragma unroll
    for (int nt = 0; nt < 16; nt++)
#pragma unroll
        for (int j = 0; j < 4; j++) C[nt][j] = 0.0f;

    const int ar = 16 * w + (lane & 15);
    const int ac = (lane >> 4) << 3;
    const int bn = lane & 7;
    const int bk = ((lane >> 3) & 1) * 8;
#pragma unroll
    for (int ks = 0; ks < 8; ks++) {
        uint32_t A[4];
        ldm_x4(A[0], A[1], A[2], A[3], smem_u32(sA + ar * 136 + ks * 16 + ac));
#pragma unroll
        for (int nt = 0; nt < 16; nt++) {
            uint32_t B[2];
            ldm_x2(B[0], B[1], smem_u32(sW + (nt * 8 + bn) * 136 + ks * 16 + bk));
            mma16816(C[nt], A, B);
        }
    }
    const int r0 = tile * 128 + 16 * w + g;
#pragma unroll
    for (int nt = 0; nt < 16; nt++) {
        int col = nt * 8 + 2 * t;
        *(float2*)(g_xf + (size_t)r0 * H + col) = make_float2(C[nt][0], C[nt][1]);
        *(float2*)(g_xf + (size_t)(r0 + 8) * H + col) = make_float2(C[nt][2], C[nt][3]);
    }
}

// ---------------- edge kernel: filter net + message + aggregate ----------------
// smem: sEA [128][72]h 18432 | sW1 [128][72]h 18432 | sW2 [128][136]h 34816 |
//       sXF [64][132]f 33792 | sRed [8][128]f 4096 | row/cut/b1/b2 2048
#define ES_EA   0
#define ES_W1   18432
#define ES_W2   36864
#define ES_XF   71680
#define ES_RED  105472
#define ES_ROW  109568
#define ES_CUT  110080
#define ES_B1   110592
#define ES_B2   111104
#define ES_TOT  111616

__global__ void __launch_bounds__(256, 1)
edge_kernel(const float* __restrict__ mb1, const float* __restrict__ mb2, int l) {
    extern __shared__ char sm[];
    __half* sEA = (__half*)(sm + ES_EA);
    __half* sW1 = (__half*)(sm + ES_W1);
    __half* sW2 = (__half*)(sm + ES_W2);
    float* sXF = (float*)(sm + ES_XF);
    float* sRed = (float*)(sm + ES_RED);
    int* sRow = (int*)(sm + ES_ROW);
    float* sCut = (float*)(sm + ES_CUT);
    float* sB1 = (float*)(sm + ES_B1);
    float* sB2 = (float*)(sm + ES_B2);

    const int tid = threadIdx.x, w = tid >> 5, lane = tid & 31;
    const int g = lane >> 2, t = lane & 3;
    const int tile = blockIdx.x;      // 128 edges
    const int conf = tile >> 4;

    {
        const uint4* easrc = (const uint4*)(g_ea + (size_t)tile * 128 * GPAD);
        const uint4* w1src = (const uint4*)(g_w1t + (size_t)l * H * GPAD);
        for (int i = tid; i < 1024; i += 256) {
            int r = i >> 3, c = i & 7;
            *(uint4*)(sEA + r * 72 + c * 8) = easrc[i];
            *(uint4*)(sW1 + r * 72 + c * 8) = w1src[i];
        }
        const uint4* w2src = (const uint4*)(g_w2t + (size_t)l * H * H);
        for (int i = tid; i < 2048; i += 256) {
            int r = i >> 4, c = i & 15;
            *(uint4*)(sW2 + r * 136 + c * 8) = w2src[i];
        }
        const float4* xfsrc = (const float4*)(g_xf + (size_t)conf * APC * H);
        for (int i = tid; i < 2048; i += 256) {
            int r = i >> 5, c = i & 31;
            *(float4*)(sXF + r * 132 + c * 4) = xfsrc[i];
        }
        if (tid < 128) {
            int e = tile * 128 + tid;
            sRow[tid] = g_rowloc[e];
            sCut[tid] = g_c[e];
            sB1[tid] = mb1[l * H + tid];
            sB2[tid] = mb2[l * H + tid];
        }
    }
    __syncthreads();

    // ---- GEMM1: C1 = EA[16 rows][64] @ W1^T ----
    uint32_t A2[8][4];
    {
        float C1[16][4];
#pragma unroll
        for (int nt = 0; nt < 16; nt++)
#pragma unroll
            for (int j = 0; j < 4; j++) C1[nt][j] = 0.0f;
        const int ar = 16 * w + (lane & 15);
        const int ac = (lane >> 4) << 3;
        const int bn = lane & 7;
        const int bk = ((lane >> 3) & 1) * 8;
#pragma unroll
        for (int ks = 0; ks < 4; ks++) {
            uint32_t A[4];
            ldm_x4(A[0], A[1], A[2], A[3], smem_u32(sEA + ar * 72 + ks * 16 + ac));
#pragma unroll
            for (int nt = 0; nt < 16; nt++) {
                uint32_t B[2];
                ldm_x2(B[0], B[1], smem_u32(sW1 + (nt * 8 + bn) * 72 + ks * 16 + bk));
                mma16816(C1[nt], A, B);
            }
        }
        // ---- u = ssp(C1 + b1) ; in-register repack C-frag -> A-frag ----
#pragma unroll
        for (int nt = 0; nt < 16; nt++) {
            int col = nt * 8 + 2 * t;
            float b0 = sB1[col], b1v = sB1[col + 1];
            float u0 = ssp(C1[nt][0] + b0), u1 = ssp(C1[nt][1] + b1v);
            float u2 = ssp(C1[nt][2] + b0), u3 = ssp(C1[nt][3] + b1v);
            A2[nt >> 1][(nt & 1) * 2 + 0] = h2u(u0, u1);
            A2[nt >> 1][(nt & 1) * 2 + 1] = h2u(u2, u3);
        }
    }

    // ---- GEMM2: C2 = U[16][128] @ W2^T ----
    float C2[16][4];
#pragma unroll
    for (int nt = 0; nt < 16; nt++)
#pragma unroll
        for (int j = 0; j < 4; j++) C2[nt][j] = 0.0f;
    {
        const int bn = lane & 7;
        const int bk = ((lane >> 3) & 1) * 8;
#pragma unroll
        for (int ks = 0; ks < 8; ks++) {
#pragma unroll
            for (int nt = 0; nt < 16; nt++) {
                uint32_t B[2];
                ldm_x2(B[0], B[1], smem_u32(sW2 + (nt * 8 + bn) * 136 + ks * 16 + bk));
                mma16816(C2[nt], A2[ks], B);
            }
        }
    }

    // ---- epilogue: msg = xf[row]*(C2+b2)*C ; column-sum over 32 edges ----
    {
        const int rg = 16 * w + g, rg8 = rg + 8;
        const int rl0 = sRow[rg], rl1 = sRow[rg8];
        const float ce0 = sCut[rg], ce1 = sCut[rg8];
#pragma unroll
        for (int nt = 0; nt < 16; nt++) {
            int col = nt * 8 + 2 * t;
            float b0 = sB2[col], b1v = sB2[col + 1];
            float s0 = sXF[rl0 * 132 + col] * (C2[nt][0] + b0) * ce0
                     + sXF[rl1 * 132 + col] * (C2[nt][2] + b0) * ce1;
            float s1 = sXF[rl0 * 132 + col + 1] * (C2[nt][1] + b1v) * ce0
                     + sXF[rl1 * 132 + col + 1] * (C2[nt][3] + b1v) * ce1;
            s0 += __shfl_xor_sync(0xFFFFFFFFu, s0, 4);
            s0 += __shfl_xor_sync(0xFFFFFFFFu, s0, 8);
            s0 += __shfl_xor_sync(0xFFFFFFFFu, s0, 16);
            s1 += __shfl_xor_sync(0xFFFFFFFFu, s1, 4);
            s1 += __shfl_xor_sync(0xFFFFFFFFu, s1, 8);
            s1 += __shfl_xor_sync(0xFFFFFFFFu, s1, 16);
            if (lane < 4) {
                sRed[w * 128 + col] = s0;
                sRed[w * 128 + col + 1] = s1;
            }
        }
    }
    __syncthreads();
    for (int i = tid; i < 512; i += 256) {
        int a = i >> 7, c = i & 127;
        g_agg[((size_t)tile * 4 + a) * H + c] =
            sRed[(2 * a) * 128 + c] + sRed[(2 * a + 1) * 128 + c];
    }
}

// ---------------- node update: h += ssp(agg@CW2+cb2)@IW + ib ----------------
// smem: sA 34816 | sW 34816 | sB1 512 | sB2 512
__global__ void __launch_bounds__(256, 1)
node_kernel(const float* __restrict__ cb2, const float* __restrict__ ib, int l) {
    extern __shared__ char sm[];
    __half* sA = (__half*)sm;
    __half* sW = (__half*)(sm + 34816);
    float* sB1 = (float*)(sm + 69632);
    float* sB2 = (float*)(sm + 70144);
    const int tid = threadIdx.x, w = tid >> 5, lane = tid & 31;
    const int g = lane >> 2, t = lane & 3;
    const int tile = blockIdx.x;

    {
        const float2* asrc = (const float2*)(g_agg + (size_t)tile * 128 * H);
        for (int i = tid; i < 128 * 64; i += 256) {
            int r = i >> 6, c2 = i & 63;
            float2 v = asrc[i];
            *(uint32_t*)(sA + r * 136 + 2 * c2) = h2u(v.x, v.y);
        }
        const uint4* wsrc = (const uint4*)(g_cw2t + (size_t)l * H * H);
        for (int i = tid; i < 2048; i += 256) {
            int r = i >> 4, c = i & 15;
            *(uint4*)(sW + r * 136 + c * 8) = wsrc[i];
        }
        if (tid < 128) {
            sB1[tid] = cb2[l * H + tid];
            sB2[tid] = ib[l * H + tid];
        }
    }
    __syncthreads();

    uint32_t A2[8][4];
    {
        float C1[16][4];
#pragma unroll
        for (int nt = 0; nt < 16; nt++)
#pragma unroll
            for (int j = 0; j < 4; j++) C1[nt][j] = 0.0f;
        const int ar = 16 * w + (lane & 15);
        const int ac = (lane >> 4) << 3;
        const int bn = lane & 7;
        const int bk = ((lane >> 3) & 1) * 8;
#pragma unroll
        for (int ks = 0; ks < 8; ks++) {
            uint32_t A[4];
            ldm_x4(A[0], A[1], A[2], A[3], smem_u32(sA + ar * 136 + ks * 16 + ac));
#pragma unroll
            for (int nt = 0; nt < 16; nt++) {
                uint32_t B[2];
                ldm_x2(B[0], B[1], smem_u32(sW + (nt * 8 + bn) * 136 + ks * 16 + bk));
                mma16816(C1[nt], A, B);
            }
        }
#pragma unroll
        for (int nt = 0; nt < 16; nt++) {
            int col = nt * 8 + 2 * t;
            float b0 = sB1[col], b1v = sB1[col + 1];
            float u0 = ssp(C1[nt][0] + b0), u1 = ssp(C1[nt][1] + b1v);
            float u2 = ssp(C1[nt][2] + b0), u3 = ssp(C1[nt][3] + b1v);
            A2[nt >> 1][(nt & 1) * 2 + 0] = h2u(u0, u1);
            A2[nt >> 1][(nt & 1) * 2 + 1] = h2u(u2, u3);
        }
    }
    __syncthreads();
    {
        const uint4* wsrc = (const uint4*)(g_iwt + (size_t)l * H * H);
        for (int i = tid; i < 2048; i += 256) {
            int r = i >> 4, c = i & 15;
            *(uint4*)(sW + r * 136 + c * 8) = wsrc[i];
        }
    }
    __syncthreads();

    float C2[16][4];
#pragma unroll
    for (int nt = 0; nt < 16; nt++)
#pragma unroll
        for (int j = 0; j < 4; j++) C2[nt][j] = 0.0f;
    {
        const int bn = lane & 7;
        const int bk = ((lane >> 3) & 1) * 8;
#pragma unroll
        for (int ks = 0; ks < 8; ks++) {
#pragma unroll
            for (int nt = 0; nt < 16; nt++) {
                uint32_t B[2];
                ldm_x2(B[0], B[1], smem_u32(sW + (nt * 8 + bn) * 136 + ks * 16 + bk));
                mma16816(C2[nt], A2[ks], B);
            }
        }
    }
    {
        const int r0 = tile * 128 + 16 * w + g;
#pragma unroll
        for (int nt = 0; nt < 16; nt++) {
            int col = nt * 8 + 2 * t;
            float b0 = sB2[col], b1v = sB2[col + 1];
            float2 h0 = *(float2*)(g_h + (size_t)r0 * H + col);
            float2 h1 = *(float2*)(g_h + (size_t)(r0 + 8) * H + col);
            float n00 = h0.x + C2[nt][0] + b0, n01 = h0.y + C2[nt][1] + b1v;
            float n10 = h1.x + C2[nt][2] + b0, n11 = h1.y + C2[nt][3] + b1v;
            *(float2*)(g_h + (size_t)r0 * H + col) = make_float2(n00, n01);
            *(float2*)(g_h + (size_t)(r0 + 8) * H + col) = make_float2(n10, n11);
            *(uint32_t*)(g_hhf + (size_t)r0 * H + col) = h2u(n00, n01);
            *(uint32_t*)(g_hhf + (size_t)(r0 + 8) * H + col) = h2u(n10, n11);
        }
    }
}

// ---------------- readout: (ssp(h@ow1+ob1)@ow2+ob2), conformer sums ----------
// smem: sA 34816 | sW 34816 | sRed 4096 | sB1 512 | sB2 512
__global__ void __launch_bounds__(256, 1)
readout_kernel(const float* __restrict__ ob1, const float* __restrict__ ob2) {
    extern __shared__ char sm[];
    __half* sA = (__half*)sm;
    __half* sW = (__half*)(sm + 34816);
    float* sRed = (float*)(sm + 69632);
    float* sB1 = (float*)(sm + 73728);
    float* sB2 = (float*)(sm + 74240);
    const int tid = threadIdx.x, w = tid >> 5, lane = tid & 31;
    const int g = lane >> 2, t = lane & 3;
    const int tile = blockIdx.x;    // conformers 2*tile, 2*tile+1

    {
        const uint4* asrc = (const uint4*)(g_hhf + (size_t)tile * 128 * H);
        const uint4* wsrc = (const uint4*)g_ow1t;
        for (int i = tid; i < 2048; i += 256) {
            int r = i >> 4, c = i & 15;
            *(uint4*)(sA + r * 136 + c * 8) = asrc[i];
            *(uint4*)(sW + r * 136 + c * 8) = wsrc[i];
        }
        if (tid < 128) {
            sB1[tid] = ob1[tid];
            sB2[tid] = ob2[tid];
        }
    }
    __syncthreads();

    uint32_t A2[8][4];
    {
        float C1[16][4];
#pragma unroll
        for (int nt = 0; nt < 16; nt++)
#pragma unroll
            for (int j = 0; j < 4; j++) C1[nt][j] = 0.0f;
        const int ar = 16 * w + (lane & 15);
        const int ac = (lane >> 4) << 3;
        const int bn = lane & 7;
        const int bk = ((lane >> 3) & 1) * 8;
#pragma unroll
        for (int ks = 0; ks < 8; ks++) {
            uint32_t A[4];
            ldm_x4(A[0], A[1], A[2], A[3], smem_u32(sA + ar * 136 + ks * 16 + ac));
#pragma unroll
            for (int nt = 0; nt < 16; nt++) {
                uint32_t B[2];
                ldm_x2(B[0], B[1], smem_u32(sW + (nt * 8 + bn) * 136 + ks * 16 + bk));
                mma16816(C1[nt], A, B);
            }
        }
#pragma unroll
        for (int nt = 0; nt < 16; nt++) {
            int col = nt * 8 + 2 * t;
            float b0 = sB1[col], b1v = sB1[col + 1];
            float u0 = ssp(C1[nt][0] + b0), u1 = ssp(C1[nt][1] + b1v);
            float u2 = ssp(C1[nt][2] + b0), u3 = ssp(C1[nt][3] + b1v);
            A2[nt >> 1][(nt & 1) * 2 + 0] = h2u(u0, u1);
            A2[nt >> 1][(nt & 1) * 2 + 1] = h2u(u2, u3);
        }
    }
    __syncthreads();
    {
        const uint4* wsrc = (const uint4*)g_ow2t;
        for (int i = tid; i < 2048; i += 256) {
            int r = i >> 4, c = i & 15;
            *(uint4*)(sW + r * 136 + c * 8) = wsrc[i];
        }
    }
    __syncthreads();

    float C2[16][4];
#pragma unroll
    for (int nt = 0; nt < 16; nt++)
#pragma unroll
        for (int j = 0; j < 4; j++) C2[nt][j] = 0.0f;
    {
        const int bn = lane & 7;
        const int bk = ((lane >> 3) & 1) * 8;
#pragma unroll
        for (int ks = 0; ks < 8; ks++) {
#pragma unroll
            for (int nt = 0; nt < 16; nt++) {
                uint32_t B[2];
                ldm_x2(B[0], B[1], smem_u32(sW + (nt * 8 + bn) * 136 + ks * 16 + bk));
                mma16816(C2[nt], A2[ks], B);
            }
        }
    }
    // per-warp column sums over its 16 rows
    {
#pragma unroll
        for (int nt = 0; nt < 16; nt++) {
            int col = nt * 8 + 2 * t;
            float b0 = sB2[col], b1v = sB2[col + 1];
            float s0 = (C2[nt][0] + b0) + (C2[nt][2] + b0);
            float s1 = (C2[nt][1] + b1v) + (C2[nt][3] + b1v);
            s0 += __shfl_xor_sync(0xFFFFFFFFu, s0, 4);
            s0 += __shfl_xor_sync(0xFFFFFFFFu, s0, 8);
            s0 += __shfl_xor_sync(0xFFFFFFFFu, s0, 16);
            s1 += __shfl_xor_sync(0xFFFFFFFFu, s1, 4);
            s1 += __shfl_xor_sync(0xFFFFFFFFu, s1, 8);
            s1 += __shfl_xor_sync(0xFFFFFFFFu, s1, 16);
            if (lane < 4) {
                sRed[w * 128 + col] = s0;
                sRed[w * 128 + col + 1] = s1;
            }
        }
    }
    __syncthreads();
    for (int i = tid; i < 256; i += 256) {
        int p = i >> 7, c = i & 127;
        float v = sRed[(4 * p + 0) * 128 + c] + sRed[(4 * p + 1) * 128 + c]
                + sRed[(4 * p + 2) * 128 + c] + sRed[(4 * p + 3) * 128 + c];
        g_conf[(size_t)(2 * tile + p) * H + c] = v;
    }
}

// ---------------- final: mol sum + head MLP ----------------
__global__ void __launch_bounds__(256, 1)
final_kernel(const float* __restrict__ hw1, const float* __restrict__ hb1,
             const float* __restrict__ hw2, const float* __restrict__ hb2,
             float* __restrict__ out) {
    extern __shared__ char sm[];
    float* s_mol = (float*)sm;
    float* s_hid = (float*)sm + 8192;
    const int tid = threadIdx.x;
    for (int idx = tid; idx < N_MOL * H; idx += 256) {
        int m = idx >> 7, c = idx & 127;
        s_mol[idx] = g_conf[(m * 4 + 0) * H + c] + g_conf[(m * 4 + 1) * H + c]
                   + g_conf[(m * 4 + 2) * H + c] + g_conf[(m * 4 + 3) * H + c];
    }
    __syncthreads();
    for (int idx = tid; idx < N_MOL * 64; idx += 256) {
        int m = idx >> 6, j = idx & 63;
        float acc = hb1[j];
#pragma unroll 4
        for (int k = 0; k < H; k++) acc += s_mol[m * H + k] * hw1[k * 64 + j];
        s_hid[idx] = ssp(acc);
    }
    __syncthreads();
    if (tid < N_MOL) {
        float acc = hb2[0];
#pragma unroll 4
        for (int j = 0; j < 64; j++) acc += s_hid[tid * 64 + j] * hw2[j];
        out[tid] = acc;
    }
}

// ---------------- launch ----------------
extern "C" void kernel_launch(void* const* d_in, const int* in_sizes, int n_in,
                              void* d_out, int out_size) {
    const int*   z   = (const int*)d_in[0];
    const float* pos = (const float*)d_in[1];
    const int*   ei  = (const int*)d_in[2];
    const float* emb = (const float*)d_in[5];
    const float* mw1 = (const float*)d_in[6];
    const float* mb1 = (const float*)d_in[7];
    const float* mw2 = (const float*)d_in[8];
    const float* mb2 = (const float*)d_in[9];
    const float* cw1 = (const float*)d_in[10];
    const float* cw2 = (const float*)d_in[11];
    const float* cb2 = (const float*)d_in[12];
    const float* iw  = (const float*)d_in[13];
    const float* ib  = (const float*)d_in[14];
    const float* ow1 = (const float*)d_in[15];
    const float* ob1 = (const float*)d_in[16];
    const float* ow2 = (const float*)d_in[17];
    const float* ob2 = (const float*)d_in[18];
    const float* hw1 = (const float*)d_in[19];
    const float* hb1 = (const float*)d_in[20];
    const float* hw2 = (const float*)d_in[21];
    const float* hb2 = (const float*)d_in[22];
    float* out = (float*)d_out;

    __half *d_w1t, *d_w2t, *d_cw1t, *d_cw2t, *d_iwt, *d_ow1t, *d_ow2t;
    cudaGetSymbolAddress((void**)&d_w1t, g_w1t);
    cudaGetSymbolAddress((void**)&d_w2t, g_w2t);
    cudaGetSymbolAddress((void**)&d_cw1t, g_cw1t);
    cudaGetSymbolAddress((void**)&d_cw2t, g_cw2t);
    cudaGetSymbolAddress((void**)&d_iwt, g_iwt);
    cudaGetSymbolAddress((void**)&d_ow1t, g_ow1t);
    cudaGetSymbolAddress((void**)&d_ow2t, g_ow2t);

    cudaFuncSetAttribute(xf_kernel, cudaFuncAttributeMaxDynamicSharedMemorySize, 69632);
    cudaFuncSetAttribute(edge_kernel, cudaFuncAttributeMaxDynamicSharedMemorySize, ES_TOT);
    cudaFuncSetAttribute(node_kernel, cudaFuncAttributeMaxDynamicSharedMemorySize, 70656);
    cudaFuncSetAttribute(readout_kernel, cudaFuncAttributeMaxDynamicSharedMemorySize, 74752);
    cudaFuncSetAttribute(final_kernel, cudaFuncAttributeMaxDynamicSharedMemorySize, 49152);

    transpose_w<<<(NLAYER * H * GPAD + 255) / 256, 256>>>(mw1, d_w1t, NLAYER, G, H, GPAD);
    transpose_w<<<(NLAYER * H * H + 255) / 256, 256>>>(mw2, d_w2t, NLAYER, H, H, H);
    transpose_w<<<(NLAYER * H * H + 255) / 256, 256>>>(cw1, d_cw1t, NLAYER, H, H, H);
    transpose_w<<<(NLAYER * H * H + 255) / 256, 256>>>(cw2, d_cw2t, NLAYER, H, H, H);
    transpose_w<<<(NLAYER * H * H + 255) / 256, 256>>>(iw, d_iwt, NLAYER, H, H, H);
    transpose_w<<<(H * H + 255) / 256, 256>>>(ow1, d_ow1t, 1, H, H, H);
    transpose_w<<<(H * H + 255) / 256, 256>>>(ow2, d_ow2t, 1, H, H, H);

    precompute_kernel<<<(EDGES * 4) / 256, 256>>>(pos, ei);
    hinit_kernel<<<(N_ATOMS * H) / 256, 256>>>(z, emb);

    for (int l = 0; l < NLAYER; l++) {
        xf_kernel<<<N_ATOMS / 128, 256, 69632>>>(l);
        edge_kernel<<<EDGES / 128, 256, ES_TOT>>>(mb1, mb2, l);
        node_kernel<<<N_ATOMS / 128, 256, 70656>>>(cb2, ib, l);
    }
    readout_kernel<<<N_ATOMS / 128, 256, 74752>>>(ob1, ob2);
    final_kernel<<<1, 256, 49152>>>(hw1, hb1, hw2, hb2, out);
}

// round 8
// speedup vs baseline: 2.9410x; 1.1268x over previous
#include <cuda_runtime.h>
#include <cuda_fp16.h>
#include <math.h>
#include <stdint.h>

#define N_ATOMS 16384
#define APC     64
#define N_CONF  256
#define N_MOL   64
#define DEG     32
#define EDGES   (N_ATOMS * DEG)     // 524288
#define H       128
#define G       50
#define GPAD    64
#define NLAYER  6

// ---------------- device scratch ----------------
__device__ __align__(16) __half g_ea[(size_t)EDGES * GPAD];
__device__ __align__(16) float  g_c[EDGES];
__device__ __align__(16) int    g_rowloc[EDGES];
__device__ __align__(16) float  g_h[N_ATOMS * H];
__device__ __align__(16) __half g_hhf[N_ATOMS * H];
__device__ __align__(16) float  g_xf[N_ATOMS * H];
__device__ __align__(16) float  g_agg[N_ATOMS * H];
__device__ __align__(16) float  g_conf[N_CONF * H];
// transposed fp16 weights: [l][n][k]
__device__ __align__(16) __half g_w1t[NLAYER * H * GPAD];
__device__ __align__(16) __half g_w2t[NLAYER * H * H];
__device__ __align__(16) __half g_cw1t[NLAYER * H * H];
__device__ __align__(16) __half g_cw2t[NLAYER * H * H];
__device__ __align__(16) __half g_iwt[NLAYER * H * H];
__device__ __align__(16) __half g_ow1t[H * H];
__device__ __align__(16) __half g_ow2t[H * H];

__device__ __forceinline__ float ssp(float x) {
    float sp = (x > 20.0f) ? x : log1pf(__expf(x));
    return sp - 0.69314718055994531f;
}
__device__ __forceinline__ uint32_t smem_u32(const void* p) {
    uint32_t a;
    asm("{ .reg .u64 t; cvta.to.shared.u64 t, %1; cvt.u32.u64 %0, t; }" : "=r"(a) : "l"(p));
    return a;
}
__device__ __forceinline__ void ldm_x4(uint32_t& r0, uint32_t& r1, uint32_t& r2, uint32_t& r3,
                                       uint32_t a) {
    asm volatile("ldmatrix.sync.aligned.m8n8.x4.shared.b16 {%0,%1,%2,%3}, [%4];"
                 : "=r"(r0), "=r"(r1), "=r"(r2), "=r"(r3) : "r"(a));
}
__device__ __forceinline__ void ldm_x2(uint32_t& r0, uint32_t& r1, uint32_t a) {
    asm volatile("ldmatrix.sync.aligned.m8n8.x2.shared.b16 {%0,%1}, [%2];"
                 : "=r"(r0), "=r"(r1) : "r"(a));
}
__device__ __forceinline__ void mma16816(float* c, const uint32_t* a, const uint32_t* b) {
    asm volatile(
        "mma.sync.aligned.m16n8k16.row.col.f32.f16.f16.f32 "
        "{%0,%1,%2,%3}, {%4,%5,%6,%7}, {%8,%9}, {%0,%1,%2,%3};"
        : "+f"(c[0]), "+f"(c[1]), "+f"(c[2]), "+f"(c[3])
        : "r"(a[0]), "r"(a[1]), "r"(a[2]), "r"(a[3]), "r"(b[0]), "r"(b[1]));
}
__device__ __forceinline__ uint32_t h2u(float a, float b) {
    __half2 p = __floats2half2_rn(a, b);
    return *(uint32_t*)&p;
}

// ---------------- prep: all weight transposes in ONE kernel ----------------
__device__ __forceinline__ void tr1(const float* src, __half* dst, int idx,
                                    int K, int N, int Kpad) {
    int k = idx % Kpad;
    int n = (idx / Kpad) % N;
    int l = idx / (Kpad * N);
    float v = (k < K) ? src[(size_t)l * K * N + (size_t)k * N + n] : 0.0f;
    dst[idx] = __float2half(v);
}
#define S1 (NLAYER * H * GPAD)   // 49152
#define S2 (NLAYER * H * H)      // 98304
#define S6 (H * H)               // 16384
__global__ void prep_weights(const float* mw1, const float* mw2, const float* cw1,
                             const float* cw2, const float* iw,
                             const float* ow1, const float* ow2) {
    int idx = blockIdx.x * blockDim.x + threadIdx.x;
    if (idx < S1) { tr1(mw1, g_w1t, idx, G, H, GPAD); return; }
    idx -= S1;
    if (idx < S2) { tr1(mw2, g_w2t, idx, H, H, H); return; }
    idx -= S2;
    if (idx < S2) { tr1(cw1, g_cw1t, idx, H, H, H); return; }
    idx -= S2;
    if (idx < S2) { tr1(cw2, g_cw2t, idx, H, H, H); return; }
    idx -= S2;
    if (idx < S2) { tr1(iw, g_iwt, idx, H, H, H); return; }
    idx -= S2;
    if (idx < S6) { tr1(ow1, g_ow1t, idx, H, H, H); return; }
    idx -= S6;
    if (idx < S6) { tr1(ow2, g_ow2t, idx, H, H, H); return; }
}

__global__ void precompute_kernel(const float* __restrict__ pos, const int* __restrict__ ei) {
    int idx = blockIdx.x * blockDim.x + threadIdx.x;
    if (idx >= EDGES * 4) return;
    int e = idx >> 2, q = idx & 3;
    int r = ei[e], c = ei[EDGES + e];
    float dx = pos[3 * r + 0] - pos[3 * c + 0];
    float dy = pos[3 * r + 1] - pos[3 * c + 1];
    float dz = pos[3 * r + 2] - pos[3 * c + 2];
    float d = sqrtf(dx * dx + dy * dy + dz * dz);
    if (q == 0) {
        g_c[e] = 0.5f * (__cosf(d * 0.31415926535897931f) + 1.0f);
        g_rowloc[e] = r & (APC - 1);
    }
    const float delta = 10.0f / 49.0f;
    const float coeff = -0.5f / (delta * delta);
    uint32_t out[8];
#pragma unroll
    for (int i = 0; i < 8; i++) {
        int k0 = q * 16 + 2 * i;
        float t0 = d - (float)k0 * delta;
        float t1 = d - (float)(k0 + 1) * delta;
        float v0 = (k0 < G) ? __expf(coeff * t0 * t0) : 0.0f;
        float v1 = (k0 + 1 < G) ? __expf(coeff * t1 * t1) : 0.0f;
        out[i] = h2u(v0, v1);
    }
    uint4* dst = (uint4*)(g_ea + (size_t)e * GPAD + q * 16);
    dst[0] = make_uint4(out[0], out[1], out[2], out[3]);
    dst[1] = make_uint4(out[4], out[5], out[6], out[7]);
}

__global__ void hinit_kernel(const int* __restrict__ z, const float* __restrict__ emb) {
    int idx = blockIdx.x * blockDim.x + threadIdx.x;
    if (idx >= N_ATOMS * H) return;
    float v = emb[z[idx >> 7] * H + (idx & 127)];
    g_h[idx] = v;
    g_hhf[idx] = __float2half(v);
}

// ---------------- xf = h @ cf_w1[0] (layer 0 only; later fused in node) ------
__global__ void __launch_bounds__(256, 1)
xf_kernel(int l) {
    extern __shared__ char sm[];
    __half* sA = (__half*)sm;
    __half* sW = (__half*)(sm + 34816);
    const int tid = threadIdx.x, w = tid >> 5, lane = tid & 31;
    const int g = lane >> 2, t = lane & 3;
    const int tile = blockIdx.x;

    {
        const uint4* asrc = (const uint4*)(g_hhf + (size_t)tile * 128 * H);
        const uint4* wsrc = (const uint4*)(g_cw1t + (size_t)l * H * H);
        for (int i = tid; i < 2048; i += 256) {
            int r = i >> 4, c = i & 15;
            *(uint4*)(sA + r * 136 + c * 8) = asrc[i];
            *(uint4*)(sW + r * 136 + c * 8) = wsrc[i];
        }
    }
    __syncthreads();

    float C[16][4];
#pragma unroll
    for (int nt = 0; nt < 16; nt++)
#pragma unroll
        for (int j = 0; j < 4; j++) C[nt][j] = 0.0f;

    const int ar = 16 * w + (lane & 15);
    const int ac = (lane >> 4) << 3;
    const int bn = lane & 7;
    const int bk = ((lane >> 3) & 1) * 8;
#pragma unroll
    for (int ks = 0; ks < 8; ks++) {
        uint32_t A[4];
        ldm_x4(A[0], A[1], A[2], A[3], smem_u32(sA + ar * 136 + ks * 16 + ac));
#pragma unroll
        for (int nt = 0; nt < 16; nt++) {
            uint32_t B[2];
            ldm_x2(B[0], B[1], smem_u32(sW + (nt * 8 + bn) * 136 + ks * 16 + bk));
            mma16816(C[nt], A, B);
        }
    }
    const int r0 = tile * 128 + 16 * w + g;
#pragma unroll
    for (int nt = 0; nt < 16; nt++) {
        int col = nt * 8 + 2 * t;
        *(float2*)(g_xf + (size_t)r0 * H + col) = make_float2(C[nt][0], C[nt][1]);
        *(float2*)(g_xf + (size_t)(r0 + 8) * H + col) = make_float2(C[nt][2], C[nt][3]);
    }
}

// ---------------- edge kernel: 256 edges/CTA, 32 rows/warp, 1 atom/warp -----
// smem: sEA [256][72]h 36864 | sW1 [128][72]h 18432 | sW2 [128][136]h 34816 |
//       sXF [64] stride133 f 34048 | row 1024 | cut 1024 | b1 512 | b2 512
#define ES_EA   0
#define ES_W1   36864
#define ES_W2   55296
#define ES_XF   90112
#define ES_ROW  124160
#define ES_CUT  125184
#define ES_B1   126208
#define ES_B2   126720
#define ES_TOT  127232

__global__ void __launch_bounds__(256, 1)
edge_kernel(const float* __restrict__ mb1, const float* __restrict__ mb2, int l) {
    extern __shared__ char sm[];
    __half* sEA = (__half*)(sm + ES_EA);
    __half* sW1 = (__half*)(sm + ES_W1);
    __half* sW2 = (__half*)(sm + ES_W2);
    float* sXF = (float*)(sm + ES_XF);
    int* sRow = (int*)(sm + ES_ROW);
    float* sCut = (float*)(sm + ES_CUT);
    float* sB1 = (float*)(sm + ES_B1);
    float* sB2 = (float*)(sm + ES_B2);

    const int tid = threadIdx.x, w = tid >> 5, lane = tid & 31;
    const int g = lane >> 2, t = lane & 3;
    const int tile = blockIdx.x;      // 256 edges
    const int conf = tile >> 3;       // 8 CTAs per conformer

    {
        const uint4* easrc = (const uint4*)(g_ea + (size_t)tile * 256 * GPAD);
        for (int i = tid; i < 2048; i += 256) {
            int r = i >> 3, c = i & 7;
            *(uint4*)(sEA + r * 72 + c * 8) = easrc[i];
        }
        const uint4* w1src = (const uint4*)(g_w1t + (size_t)l * H * GPAD);
        for (int i = tid; i < 1024; i += 256) {
            int r = i >> 3, c = i & 7;
            *(uint4*)(sW1 + r * 72 + c * 8) = w1src[i];
        }
        const uint4* w2src = (const uint4*)(g_w2t + (size_t)l * H * H);
        for (int i = tid; i < 2048; i += 256) {
            int r = i >> 4, c = i & 15;
            *(uint4*)(sW2 + r * 136 + c * 8) = w2src[i];
        }
        const float4* xfsrc = (const float4*)(g_xf + (size_t)conf * APC * H);
        for (int i = tid; i < 2048; i += 256) {
            int r = i >> 5, c4 = i & 31;
            float4 v = xfsrc[i];
            float* d = sXF + r * 133 + c4 * 4;
            d[0] = v.x; d[1] = v.y; d[2] = v.z; d[3] = v.w;
        }
        for (int i = tid; i < 256; i += 256) {
            int e = tile * 256 + i;
            sRow[i] = g_rowloc[e];
            sCut[i] = g_c[e];
        }
        if (tid < 128) {
            sB1[tid] = mb1[l * H + tid];
            sB2[tid] = mb2[l * H + tid];
        }
    }
    __syncthreads();

    const int bn = lane & 7;
    const int bk = ((lane >> 3) & 1) * 8;
    const int ac = (lane >> 4) << 3;

    // ---- A fragments of EA for both 16-row tiles of this warp ----
    uint32_t A1[2][4][4];
#pragma unroll
    for (int i = 0; i < 2; i++) {
        int ar = 32 * w + 16 * i + (lane & 15);
#pragma unroll
        for (int ks = 0; ks < 4; ks++)
            ldm_x4(A1[i][ks][0], A1[i][ks][1], A1[i][ks][2], A1[i][ks][3],
                   smem_u32(sEA + ar * 72 + ks * 16 + ac));
    }

    // ---- GEMM1 in two 64-col halves; convert to A-frags for GEMM2 ----
    uint32_t A2[2][8][4];
#pragma unroll
    for (int half = 0; half < 2; half++) {
        float C1[2][8][4];
#pragma unroll
        for (int i = 0; i < 2; i++)
#pragma unroll
            for (int n = 0; n < 8; n++)
#pragma unroll
                for (int j = 0; j < 4; j++) C1[i][n][j] = 0.0f;
#pragma unroll
        for (int ks = 0; ks < 4; ks++) {
#pragma unroll
            for (int ntl = 0; ntl < 8; ntl++) {
                int nt = half * 8 + ntl;
                uint32_t B[2];
                ldm_x2(B[0], B[1], smem_u32(sW1 + (nt * 8 + bn) * 72 + ks * 16 + bk));
                mma16816(C1[0][ntl], A1[0][ks], B);
                mma16816(C1[1][ntl], A1[1][ks], B);
            }
        }
#pragma unroll
        for (int ntl = 0; ntl < 8; ntl++) {
            int nt = half * 8 + ntl;
            int col = nt * 8 + 2 * t;
            float b0 = sB1[col], b1v = sB1[col + 1];
#pragma unroll
            for (int i = 0; i < 2; i++) {
                float u0 = ssp(C1[i][ntl][0] + b0), u1 = ssp(C1[i][ntl][1] + b1v);
                float u2 = ssp(C1[i][ntl][2] + b0), u3 = ssp(C1[i][ntl][3] + b1v);
                A2[i][nt >> 1][(nt & 1) * 2 + 0] = h2u(u0, u1);
                A2[i][nt >> 1][(nt & 1) * 2 + 1] = h2u(u2, u3);
            }
        }
    }

    // ---- per-slot row metadata (4 rows per lane: i in tiles, j in 8-blocks) --
    int rl[2][2];
    float ce[2][2];
#pragma unroll
    for (int i = 0; i < 2; i++)
#pragma unroll
        for (int j = 0; j < 2; j++) {
            int er = 32 * w + 16 * i + 8 * j + g;
            rl[i][j] = sRow[er];
            ce[i][j] = sCut[er];
        }
    const int atom = tile * 8 + w;    // warp owns exactly one target atom

    // ---- GEMM2 + fused epilogue, two 64-col halves ----
#pragma unroll
    for (int half = 0; half < 2; half++) {
        float C2[2][8][4];
#pragma unroll
        for (int i = 0; i < 2; i++)
#pragma unroll
            for (int n = 0; n < 8; n++)
#pragma unroll
                for (int j = 0; j < 4; j++) C2[i][n][j] = 0.0f;
#pragma unroll
        for (int ks = 0; ks < 8; ks++) {
#pragma unroll
            for (int ntl = 0; ntl < 8; ntl++) {
                int nt = half * 8 + ntl;
                uint32_t B[2];
                ldm_x2(B[0], B[1], smem_u32(sW2 + (nt * 8 + bn) * 136 + ks * 16 + bk));
                mma16816(C2[0][ntl], A2[0][ks], B);
                mma16816(C2[1][ntl], A2[1][ks], B);
            }
        }
        // msg = xf[row]*(C2+b2)*cut ; sum 32 edges (all belong to `atom`)
#pragma unroll
        for (int ntl = 0; ntl < 8; ntl++) {
            int nt = half * 8 + ntl;
            int col = nt * 8 + 2 * t;
            float b0 = sB2[col], b1v = sB2[col + 1];
            float s0 = 0.0f, s1 = 0.0f;
#pragma unroll
            for (int i = 0; i < 2; i++) {
                s0 += sXF[rl[i][0] * 133 + col] * (C2[i][ntl][0] + b0) * ce[i][0]
                    + sXF[rl[i][1] * 133 + col] * (C2[i][ntl][2] + b0) * ce[i][1];
                s1 += sXF[rl[i][0] * 133 + col + 1] * (C2[i][ntl][1] + b1v) * ce[i][0]
                    + sXF[rl[i][1] * 133 + col + 1] * (C2[i][ntl][3] + b1v) * ce[i][1];
            }
            s0 += __shfl_xor_sync(0xFFFFFFFFu, s0, 4);
            s0 += __shfl_xor_sync(0xFFFFFFFFu, s0, 8);
            s0 += __shfl_xor_sync(0xFFFFFFFFu, s0, 16);
            s1 += __shfl_xor_sync(0xFFFFFFFFu, s1, 4);
            s1 += __shfl_xor_sync(0xFFFFFFFFu, s1, 8);
            s1 += __shfl_xor_sync(0xFFFFFFFFu, s1, 16);
            if (lane < 4)
                *(float2*)(g_agg + (size_t)atom * H + col) = make_float2(s0, s1);
        }
    }
}

// ---------------- node update (+ fused next-layer xf) ------------------------
// smem: sA 34816 | sW 34816 | sB1 512 | sB2 512
__global__ void __launch_bounds__(256, 1)
node_kernel(const float* __restrict__ cb2, const float* __restrict__ ib, int l, int do_xf) {
    extern __shared__ char sm[];
    __half* sA = (__half*)sm;
    __half* sW = (__half*)(sm + 34816);
    float* sB1 = (float*)(sm + 69632);
    float* sB2 = (float*)(sm + 70144);
    const int tid = threadIdx.x, w = tid >> 5, lane = tid & 31;
    const int g = lane >> 2, t = lane & 3;
    const int tile = blockIdx.x;

    {
        const float2* asrc = (const float2*)(g_agg + (size_t)tile * 128 * H);
        for (int i = tid; i < 128 * 64; i += 256) {
            int r = i >> 6, c2 = i & 63;
            float2 v = asrc[i];
            *(uint32_t*)(sA + r * 136 + 2 * c2) = h2u(v.x, v.y);
        }
        const uint4* wsrc = (const uint4*)(g_cw2t + (size_t)l * H * H);
        for (int i = tid; i < 2048; i += 256) {
            int r = i >> 4, c = i & 15;
            *(uint4*)(sW + r * 136 + c * 8) = wsrc[i];
        }
        if (tid < 128) {
            sB1[tid] = cb2[l * H + tid];
            sB2[tid] = ib[l * H + tid];
        }
    }
    __syncthreads();

    const int bn = lane & 7;
    const int bk = ((lane >> 3) & 1) * 8;
    const int ac = (lane >> 4) << 3;
    const int ar = 16 * w + (lane & 15);

    uint32_t A2[8][4];
    {
        float C1[16][4];
#pragma unroll
        for (int nt = 0; nt < 16; nt++)
#pragma unroll
            for (int j = 0; j < 4; j++) C1[nt][j] = 0.0f;
#pragma unroll
        for (int ks = 0; ks < 8; ks++) {
            uint32_t A[4];
            ldm_x4(A[0], A[1], A[2], A[3], smem_u32(sA + ar * 136 + ks * 16 + ac));
#pragma unroll
            for (int nt = 0; nt < 16; nt++) {
                uint32_t B[2];
                ldm_x2(B[0], B[1], smem_u32(sW + (nt * 8 + bn) * 136 + ks * 16 + bk));
                mma16816(C1[nt], A, B);
            }
        }
#pragma unroll
        for (int nt = 0; nt < 16; nt++) {
            int col = nt * 8 + 2 * t;
            float b0 = sB1[col], b1v = sB1[col + 1];
            float u0 = ssp(C1[nt][0] + b0), u1 = ssp(C1[nt][1] + b1v);
            float u2 = ssp(C1[nt][2] + b0), u3 = ssp(C1[nt][3] + b1v);
            A2[nt >> 1][(nt & 1) * 2 + 0] = h2u(u0, u1);
            A2[nt >> 1][(nt & 1) * 2 + 1] = h2u(u2, u3);
        }
    }
    __syncthreads();
    {
        const uint4* wsrc = (const uint4*)(g_iwt + (size_t)l * H * H);
        for (int i = tid; i < 2048; i += 256) {
            int r = i >> 4, c = i & 15;
            *(uint4*)(sW + r * 136 + c * 8) = wsrc[i];
        }
    }
    __syncthreads();

    float C2[16][4];
#pragma unroll
    for (int nt = 0; nt < 16; nt++)
#pragma unroll
        for (int j = 0; j < 4; j++) C2[nt][j] = 0.0f;
#pragma unroll
    for (int ks = 0; ks < 8; ks++) {
#pragma unroll
        for (int nt = 0; nt < 16; nt++) {
            uint32_t B[2];
            ldm_x2(B[0], B[1], smem_u32(sW + (nt * 8 + bn) * 136 + ks * 16 + bk));
            mma16816(C2[nt], A2[ks], B);
        }
    }

    // epilogue: h += C2 + ib; also repack updated h into A-frags for fused xf
    uint32_t A3[8][4];
    {
        const int r0 = tile * 128 + 16 * w + g;
#pragma unroll
        for (int nt = 0; nt < 16; nt++) {
            int col = nt * 8 + 2 * t;
            float b0 = sB2[col], b1v = sB2[col + 1];
            float2 h0 = *(float2*)(g_h + (size_t)r0 * H + col);
            float2 h1 = *(float2*)(g_h + (size_t)(r0 + 8) * H + col);
            float n00 = h0.x + C2[nt][0] + b0, n01 = h0.y + C2[nt][1] + b1v;
            float n10 = h1.x + C2[nt][2] + b0, n11 = h1.y + C2[nt][3] + b1v;
            *(float2*)(g_h + (size_t)r0 * H + col) = make_float2(n00, n01);
            *(float2*)(g_h + (size_t)(r0 + 8) * H + col) = make_float2(n10, n11);
            *(uint32_t*)(g_hhf + (size_t)r0 * H + col) = h2u(n00, n01);
            *(uint32_t*)(g_hhf + (size_t)(r0 + 8) * H + col) = h2u(n10, n11);
            A3[nt >> 1][(nt & 1) * 2 + 0] = h2u(n00, n01);
            A3[nt >> 1][(nt & 1) * 2 + 1] = h2u(n10, n11);
        }
    }

    if (!do_xf) return;
    __syncthreads();
    {
        const uint4* wsrc = (const uint4*)(g_cw1t + (size_t)(l + 1) * H * H);
        for (int i = tid; i < 2048; i += 256) {
            int r = i >> 4, c = i & 15;
            *(uint4*)(sW + r * 136 + c * 8) = wsrc[i];
        }
    }
    __syncthreads();

    float C3[16][4];
#pragma unroll
    for (int nt = 0; nt < 16; nt++)
#pragma unroll
        for (int j = 0; j < 4; j++) C3[nt][j] = 0.0f;
#pragma unroll
    for (int ks = 0; ks < 8; ks++) {
#pragma unroll
        for (int nt = 0; nt < 16; nt++) {
            uint32_t B[2];
            ldm_x2(B[0], B[1], smem_u32(sW + (nt * 8 + bn) * 136 + ks * 16 + bk));
            mma16816(C3[nt], A3[ks], B);
        }
    }
    {
        const int r0 = tile * 128 + 16 * w + g;
#pragma unroll
        for (int nt = 0; nt < 16; nt++) {
            int col = nt * 8 + 2 * t;
            *(float2*)(g_xf + (size_t)r0 * H + col) = make_float2(C3[nt][0], C3[nt][1]);
            *(float2*)(g_xf + (size_t)(r0 + 8) * H + col) = make_float2(C3[nt][2], C3[nt][3]);
        }
    }
}

// ---------------- readout ----------------
__global__ void __launch_bounds__(256, 1)
readout_kernel(const float* __restrict__ ob1, const float* __restrict__ ob2) {
    extern __shared__ char sm[];
    __half* sA = (__half*)sm;
    __half* sW = (__half*)(sm + 34816);
    float* sRed = (float*)(sm + 69632);
    float* sB1 = (float*)(sm + 73728);
    float* sB2 = (float*)(sm + 74240);
    const int tid = threadIdx.x, w = tid >> 5, lane = tid & 31;
    const int g = lane >> 2, t = lane & 3;
    const int tile = blockIdx.x;

    {
        const uint4* asrc = (const uint4*)(g_hhf + (size_t)tile * 128 * H);
        const uint4* wsrc = (const uint4*)g_ow1t;
        for (int i = tid; i < 2048; i += 256) {
            int r = i >> 4, c = i & 15;
            *(uint4*)(sA + r * 136 + c * 8) = asrc[i];
            *(uint4*)(sW + r * 136 + c * 8) = wsrc[i];
        }
        if (tid < 128) {
            sB1[tid] = ob1[tid];
            sB2[tid] = ob2[tid];
        }
    }
    __syncthreads();

    const int bn = lane & 7;
    const int bk = ((lane >> 3) & 1) * 8;
    const int ac = (lane >> 4) << 3;
    const int ar = 16 * w + (lane & 15);

    uint32_t A2[8][4];
    {
        float C1[16][4];
#pragma unroll
        for (int nt = 0; nt < 16; nt++)
#pragma unroll
            for (int j = 0; j < 4; j++) C1[nt][j] = 0.0f;
#pragma unroll
        for (int ks = 0; ks < 8; ks++) {
            uint32_t A[4];
            ldm_x4(A[0], A[1], A[2], A[3], smem_u32(sA + ar * 136 + ks * 16 + ac));
#pragma unroll
            for (int nt = 0; nt < 16; nt++) {
                uint32_t B[2];
                ldm_x2(B[0], B[1], smem_u32(sW + (nt * 8 + bn) * 136 + ks * 16 + bk));
                mma16816(C1[nt], A, B);
            }
        }
#pragma unroll
        for (int nt = 0; nt < 16; nt++) {
            int col = nt * 8 + 2 * t;
            float b0 = sB1[col], b1v = sB1[col + 1];
            float u0 = ssp(C1[nt][0] + b0), u1 = ssp(C1[nt][1] + b1v);
            float u2 = ssp(C1[nt][2] + b0), u3 = ssp(C1[nt][3] + b1v);
            A2[nt >> 1][(nt & 1) * 2 + 0] = h2u(u0, u1);
            A2[nt >> 1][(nt & 1) * 2 + 1] = h2u(u2, u3);
        }
    }
    __syncthreads();
    {
        const uint4* wsrc = (const uint4*)g_ow2t;
        for (int i = tid; i < 2048; i += 256) {
            int r = i >> 4, c = i & 15;
            *(uint4*)(sW + r * 136 + c * 8) = wsrc[i];
        }
    }
    __syncthreads();

    float C2[16][4];
#pragma unroll
    for (int nt = 0; nt < 16; nt++)
#pragma unroll
        for (int j = 0; j < 4; j++) C2[nt][j] = 0.0f;
#pragma unroll
    for (int ks = 0; ks < 8; ks++) {
#pragma unroll
        for (int nt = 0; nt < 16; nt++) {
            uint32_t B[2];
            ldm_x2(B[0], B[1], smem_u32(sW + (nt * 8 + bn) * 136 + ks * 16 + bk));
            mma16816(C2[nt], A2[ks], B);
        }
    }
    {
#pragma unroll
        for (int nt = 0; nt < 16; nt++) {
            int col = nt * 8 + 2 * t;
            float b0 = sB2[col], b1v = sB2[col + 1];
            float s0 = (C2[nt][0] + b0) + (C2[nt][2] + b0);
            float s1 = (C2[nt][1] + b1v) + (C2[nt][3] + b1v);
            s0 += __shfl_xor_sync(0xFFFFFFFFu, s0, 4);
            s0 += __shfl_xor_sync(0xFFFFFFFFu, s0, 8);
            s0 += __shfl_xor_sync(0xFFFFFFFFu, s0, 16);
            s1 += __shfl_xor_sync(0xFFFFFFFFu, s1, 4);
            s1 += __shfl_xor_sync(0xFFFFFFFFu, s1, 8);
            s1 += __shfl_xor_sync(0xFFFFFFFFu, s1, 16);
            if (lane < 4) {
                sRed[w * 128 + col] = s0;
                sRed[w * 128 + col + 1] = s1;
            }
        }
    }
    __syncthreads();
    for (int i = tid; i < 256; i += 256) {
        int p = i >> 7, c = i & 127;
        float v = sRed[(4 * p + 0) * 128 + c] + sRed[(4 * p + 1) * 128 + c]
                + sRed[(4 * p + 2) * 128 + c] + sRed[(4 * p + 3) * 128 + c];
        g_conf[(size_t)(2 * tile + p) * H + c] = v;
    }
}

// ---------------- final: mol sum + head MLP ----------------
__global__ void __launch_bounds__(256, 1)
final_kernel(const float* __restrict__ hw1, const float* __restrict__ hb1,
             const float* __restrict__ hw2, const float* __restrict__ hb2,
             float* __restrict__ out) {
    extern __shared__ char sm[];
    float* s_mol = (float*)sm;
    float* s_hid = (float*)sm + 8192;
    const int tid = threadIdx.x;
    for (int idx = tid; idx < N_MOL * H; idx += 256) {
        int m = idx >> 7, c = idx & 127;
        s_mol[idx] = g_conf[(m * 4 + 0) * H + c] + g_conf[(m * 4 + 1) * H + c]
                   + g_conf[(m * 4 + 2) * H + c] + g_conf[(m * 4 + 3) * H + c];
    }
    __syncthreads();
    for (int idx = tid; idx < N_MOL * 64; idx += 256) {
        int m = idx >> 6, j = idx & 63;
        float acc = hb1[j];
#pragma unroll 4
        for (int k = 0; k < H; k++) acc += s_mol[m * H + k] * hw1[k * 64 + j];
        s_hid[idx] = ssp(acc);
    }
    __syncthreads();
    if (tid < N_MOL) {
        float acc = hb2[0];
#pragma unroll 4
        for (int j = 0; j < 64; j++) acc += s_hid[tid * 64 + j] * hw2[j];
        out[tid] = acc;
    }
}

// ---------------- launch ----------------
extern "C" void kernel_launch(void* const* d_in, const int* in_sizes, int n_in,
                              void* d_out, int out_size) {
    const int*   z   = (const int*)d_in[0];
    const float* pos = (const float*)d_in[1];
    const int*   ei  = (const int*)d_in[2];
    const float* emb = (const float*)d_in[5];
    const float* mw1 = (const float*)d_in[6];
    const float* mb1 = (const float*)d_in[7];
    const float* mw2 = (const float*)d_in[8];
    const float* mb2 = (const float*)d_in[9];
    const float* cw1 = (const float*)d_in[10];
    const float* cw2 = (const float*)d_in[11];
    const float* cb2 = (const float*)d_in[12];
    const float* iw  = (const float*)d_in[13];
    const float* ib  = (const float*)d_in[14];
    const float* ow1 = (const float*)d_in[15];
    const float* ob1 = (const float*)d_in[16];
    const float* ow2 = (const float*)d_in[17];
    const float* ob2 = (const float*)d_in[18];
    const float* hw1 = (const float*)d_in[19];
    const float* hb1 = (const float*)d_in[20];
    const float* hw2 = (const float*)d_in[21];
    const float* hb2 = (const float*)d_in[22];
    float* out = (float*)d_out;

    cudaFuncSetAttribute(xf_kernel, cudaFuncAttributeMaxDynamicSharedMemorySize, 69632);
    cudaFuncSetAttribute(edge_kernel, cudaFuncAttributeMaxDynamicSharedMemorySize, ES_TOT);
    cudaFuncSetAttribute(node_kernel, cudaFuncAttributeMaxDynamicSharedMemorySize, 70656);
    cudaFuncSetAttribute(readout_kernel, cudaFuncAttributeMaxDynamicSharedMemorySize, 74752);
    cudaFuncSetAttribute(final_kernel, cudaFuncAttributeMaxDynamicSharedMemorySize, 49152);

    const int WTOT = S1 + 4 * S2 + 2 * S6;
    prep_weights<<<(WTOT + 255) / 256, 256>>>(mw1, mw2, cw1, cw2, iw, ow1, ow2);
    precompute_kernel<<<(EDGES * 4) / 256, 256>>>(pos, ei);
    hinit_kernel<<<(N_ATOMS * H) / 256, 256>>>(z, emb);

    xf_kernel<<<N_ATOMS / 128, 256, 69632>>>(0);
    for (int l = 0; l < NLAYER; l++) {
        edge_kernel<<<EDGES / 256, 256, ES_TOT>>>(mb1, mb2, l);
        node_kernel<<<N_ATOMS / 128, 256, 70656>>>(cb2, ib, l, l < NLAYER - 1);
    }
    readout_kernel<<<N_ATOMS / 128, 256, 74752>>>(ob1, ob2);
    final_kernel<<<1, 256, 49152>>>(hw1, hb1, hw2, hb2, out);
}

// round 9
// speedup vs baseline: 4.2720x; 1.4526x over previous
#include <cuda_runtime.h>
#include <cuda_fp16.h>
#include <math.h>
#include <stdint.h>

#define N_ATOMS 16384
#define APC     64
#define N_CONF  256
#define N_MOL   64
#define DEG     32
#define EDGES   (N_ATOMS * DEG)     // 524288
#define H       128
#define G       50
#define GPAD    64
#define NLAYER  6

// ---------------- device scratch ----------------
__device__ __align__(16) __half g_ea[(size_t)EDGES * GPAD];
__device__ __align__(16) float  g_c[EDGES];
__device__ __align__(16) int    g_rowloc[EDGES];
__device__ __align__(16) float  g_h[N_ATOMS * H];
__device__ __align__(16) __half g_hhf[N_ATOMS * H];
__device__ __align__(16) __half g_xfh[N_ATOMS * H];
__device__ __align__(16) __half g_aggh[N_ATOMS * H];
__device__ __align__(16) float  g_conf[N_CONF * H];
// transposed fp16 weights: [l][n][k]
__device__ __align__(16) __half g_w1t[NLAYER * H * GPAD];
__device__ __align__(16) __half g_w2t[NLAYER * H * H];
__device__ __align__(16) __half g_cw1t[NLAYER * H * H];
__device__ __align__(16) __half g_cw2t[NLAYER * H * H];
__device__ __align__(16) __half g_iwt[NLAYER * H * H];
__device__ __align__(16) __half g_ow1t[H * H];
__device__ __align__(16) __half g_ow2t[H * H];

__device__ __forceinline__ float ssp(float x) {
    float sp = (x > 20.0f) ? x : log1pf(__expf(x));
    return sp - 0.69314718055994531f;
}
__device__ __forceinline__ uint32_t smem_u32(const void* p) {
    uint32_t a;
    asm("{ .reg .u64 t; cvta.to.shared.u64 t, %1; cvt.u32.u64 %0, t; }" : "=r"(a) : "l"(p));
    return a;
}
__device__ __forceinline__ void ldm_x4(uint32_t& r0, uint32_t& r1, uint32_t& r2, uint32_t& r3,
                                       uint32_t a) {
    asm volatile("ldmatrix.sync.aligned.m8n8.x4.shared.b16 {%0,%1,%2,%3}, [%4];"
                 : "=r"(r0), "=r"(r1), "=r"(r2), "=r"(r3) : "r"(a));
}
__device__ __forceinline__ void ldm_x2(uint32_t& r0, uint32_t& r1, uint32_t a) {
    asm volatile("ldmatrix.sync.aligned.m8n8.x2.shared.b16 {%0,%1}, [%2];"
                 : "=r"(r0), "=r"(r1) : "r"(a));
}
__device__ __forceinline__ void mma16816(float* c, const uint32_t* a, const uint32_t* b) {
    asm volatile(
        "mma.sync.aligned.m16n8k16.row.col.f32.f16.f16.f32 "
        "{%0,%1,%2,%3}, {%4,%5,%6,%7}, {%8,%9}, {%0,%1,%2,%3};"
        : "+f"(c[0]), "+f"(c[1]), "+f"(c[2]), "+f"(c[3])
        : "r"(a[0]), "r"(a[1]), "r"(a[2]), "r"(a[3]), "r"(b[0]), "r"(b[1]));
}
__device__ __forceinline__ uint32_t h2u(float a, float b) {
    __half2 p = __floats2half2_rn(a, b);
    return *(uint32_t*)&p;
}
__device__ __forceinline__ float2 xld(const __half* p) {
    __half2 h = *(const __half2*)p;
    return __half22float2(h);
}

// ---------------- prep: all weight transposes in ONE kernel ----------------
__device__ __forceinline__ void tr1(const float* src, __half* dst, int idx,
                                    int K, int N, int Kpad) {
    int k = idx % Kpad;
    int n = (idx / Kpad) % N;
    int l = idx / (Kpad * N);
    float v = (k < K) ? src[(size_t)l * K * N + (size_t)k * N + n] : 0.0f;
    dst[idx] = __float2half(v);
}
#define S1 (NLAYER * H * GPAD)
#define S2 (NLAYER * H * H)
#define S6 (H * H)
__global__ void prep_weights(const float* mw1, const float* mw2, const float* cw1,
                             const float* cw2, const float* iw,
                             const float* ow1, const float* ow2) {
    int idx = blockIdx.x * blockDim.x + threadIdx.x;
    if (idx < S1) { tr1(mw1, g_w1t, idx, G, H, GPAD); return; }
    idx -= S1;
    if (idx < S2) { tr1(mw2, g_w2t, idx, H, H, H); return; }
    idx -= S2;
    if (idx < S2) { tr1(cw1, g_cw1t, idx, H, H, H); return; }
    idx -= S2;
    if (idx < S2) { tr1(cw2, g_cw2t, idx, H, H, H); return; }
    idx -= S2;
    if (idx < S2) { tr1(iw, g_iwt, idx, H, H, H); return; }
    idx -= S2;
    if (idx < S6) { tr1(ow1, g_ow1t, idx, H, H, H); return; }
    idx -= S6;
    if (idx < S6) { tr1(ow2, g_ow2t, idx, H, H, H); return; }
}

// ---------------- edge precompute: recurrence-based gaussians ---------------
// E_k = exp(c(d-k*delta)^2); seed at k0 = round(d/delta), march outward.
// Ratio of consecutive ratios is constant q = exp(2*c*delta^2).
__global__ void precompute_kernel(const float* __restrict__ pos, const int* __restrict__ ei) {
    __shared__ __half sE[128 * 72];
    const int tid = threadIdx.x;
    const int e = blockIdx.x * 128 + tid;
    int r = ei[e], c = ei[EDGES + e];
    float dx = pos[3 * r + 0] - pos[3 * c + 0];
    float dy = pos[3 * r + 1] - pos[3 * c + 1];
    float dz = pos[3 * r + 2] - pos[3 * c + 2];
    float d = sqrtf(dx * dx + dy * dy + dz * dz);
    g_c[e] = 0.5f * (__cosf(d * 0.31415926535897931f) + 1.0f);
    g_rowloc[e] = r & (APC - 1);

    const float delta = 10.0f / 49.0f;
    const float cf = -0.5f / (delta * delta);
    const float q = expf(2.0f * cf * delta * delta);
    int k0 = (int)(d / delta + 0.5f);
    if (k0 > 49) k0 = 49;
    float t0 = d - (float)k0 * delta;

    __half* row = sE + tid * 72;
#pragma unroll
    for (int k = 50; k < 64; k++) row[k] = __float2half(0.0f);
    float E0 = expf(cf * t0 * t0);
    row[k0] = __float2half(E0);
    float u = expf(cf * (delta * delta - 2.0f * delta * t0));
    float E = E0;
    for (int k = k0 + 1; k <= 49; k++) { E *= u; u *= q; row[k] = __float2half(E); }
    float v = expf(cf * (delta * delta + 2.0f * delta * t0));
    E = E0;
    for (int k = k0 - 1; k >= 0; k--) { E *= v; v *= q; row[k] = __float2half(E); }
    __syncthreads();

    uint4* dst = (uint4*)(g_ea + (size_t)blockIdx.x * 128 * GPAD);
    for (int i = tid; i < 1024; i += 128) {
        int rr = i >> 3, cc = i & 7;
        dst[i] = *(uint4*)(sE + rr * 72 + cc * 8);
    }
}

__global__ void hinit_kernel(const int* __restrict__ z, const float* __restrict__ emb) {
    int idx = blockIdx.x * blockDim.x + threadIdx.x;
    if (idx >= N_ATOMS * H) return;
    float v = emb[z[idx >> 7] * H + (idx & 127)];
    g_h[idx] = v;
    g_hhf[idx] = __float2half(v);
}

// ---------------- xf = h @ cf_w1[0] (layer 0 only) ----------------
__global__ void __launch_bounds__(256, 1)
xf_kernel(int l) {
    extern __shared__ char sm[];
    __half* sA = (__half*)sm;
    __half* sW = (__half*)(sm + 34816);
    const int tid = threadIdx.x, w = tid >> 5, lane = tid & 31;
    const int g = lane >> 2, t = lane & 3;
    const int tile = blockIdx.x;

    {
        const uint4* asrc = (const uint4*)(g_hhf + (size_t)tile * 128 * H);
        const uint4* wsrc = (const uint4*)(g_cw1t + (size_t)l * H * H);
        for (int i = tid; i < 2048; i += 256) {
            int r = i >> 4, c = i & 15;
            *(uint4*)(sA + r * 136 + c * 8) = asrc[i];
            *(uint4*)(sW + r * 136 + c * 8) = wsrc[i];
        }
    }
    __syncthreads();

    float C[16][4];
#pragma unroll
    for (int nt = 0; nt < 16; nt++)
#pragma unroll
        for (int j = 0; j < 4; j++) C[nt][j] = 0.0f;

    const int ar = 16 * w + (lane & 15);
    const int ac = (lane >> 4) << 3;
    const int bn = lane & 7;
    const int bk = ((lane >> 3) & 1) * 8;
#pragma unroll
    for (int ks = 0; ks < 8; ks++) {
        uint32_t A[4];
        ldm_x4(A[0], A[1], A[2], A[3], smem_u32(sA + ar * 136 + ks * 16 + ac));
#pragma unroll
        for (int nt = 0; nt < 16; nt++) {
            uint32_t B[2];
            ldm_x2(B[0], B[1], smem_u32(sW + (nt * 8 + bn) * 136 + ks * 16 + bk));
            mma16816(C[nt], A, B);
        }
    }
    const int r0 = tile * 128 + 16 * w + g;
#pragma unroll
    for (int nt = 0; nt < 16; nt++) {
        int col = nt * 8 + 2 * t;
        *(uint32_t*)(g_xfh + (size_t)r0 * H + col) = h2u(C[nt][0], C[nt][1]);
        *(uint32_t*)(g_xfh + (size_t)(r0 + 8) * H + col) = h2u(C[nt][2], C[nt][3]);
    }
}

// ---------------- edge kernel: 256 edges/CTA, 32 rows/warp, 1 atom/warp -----
// smem: sEA [256][72]h 36864 | sW1 [128][72]h 18432 | sW2 [128][136]h 34816 |
//       sXF [64][136]h 17408 | row 1024 | cut 1024 | b1 512 | b2 512
#define ES_EA   0
#define ES_W1   36864
#define ES_W2   55296
#define ES_XF   90112
#define ES_ROW  107520
#define ES_CUT  108544
#define ES_B1   109568
#define ES_B2   110080
#define ES_TOT  110592

__global__ void __launch_bounds__(256, 2)
edge_kernel(const float* __restrict__ mb1, const float* __restrict__ mb2, int l) {
    extern __shared__ char sm[];
    __half* sEA = (__half*)(sm + ES_EA);
    __half* sW1 = (__half*)(sm + ES_W1);
    __half* sW2 = (__half*)(sm + ES_W2);
    __half* sXF = (__half*)(sm + ES_XF);
    int* sRow = (int*)(sm + ES_ROW);
    float* sCut = (float*)(sm + ES_CUT);
    float* sB1 = (float*)(sm + ES_B1);
    float* sB2 = (float*)(sm + ES_B2);

    const int tid = threadIdx.x, w = tid >> 5, lane = tid & 31;
    const int g = lane >> 2, t = lane & 3;
    const int tile = blockIdx.x;      // 256 edges
    const int conf = tile >> 3;

    {
        const uint4* easrc = (const uint4*)(g_ea + (size_t)tile * 256 * GPAD);
        for (int i = tid; i < 2048; i += 256) {
            int r = i >> 3, c = i & 7;
            *(uint4*)(sEA + r * 72 + c * 8) = easrc[i];
        }
        const uint4* w1src = (const uint4*)(g_w1t + (size_t)l * H * GPAD);
        for (int i = tid; i < 1024; i += 256) {
            int r = i >> 3, c = i & 7;
            *(uint4*)(sW1 + r * 72 + c * 8) = w1src[i];
        }
        const uint4* w2src = (const uint4*)(g_w2t + (size_t)l * H * H);
        for (int i = tid; i < 2048; i += 256) {
            int r = i >> 4, c = i & 15;
            *(uint4*)(sW2 + r * 136 + c * 8) = w2src[i];
        }
        const uint4* xfsrc = (const uint4*)(g_xfh + (size_t)conf * APC * H);
        for (int i = tid; i < 1024; i += 256) {
            int r = i >> 4, c = i & 15;
            *(uint4*)(sXF + r * 136 + c * 8) = xfsrc[i];
        }
        {
            int e = tile * 256 + tid;
            sRow[tid] = g_rowloc[e];
            sCut[tid] = g_c[e];
        }
        if (tid < 128) {
            sB1[tid] = mb1[l * H + tid];
            sB2[tid] = mb2[l * H + tid];
        }
    }
    __syncthreads();

    const int bn = lane & 7;
    const int bk = ((lane >> 3) & 1) * 8;
    const int ac = (lane >> 4) << 3;

    // A fragments of EA (two 16-row tiles per warp)
    uint32_t A1[2][4][4];
#pragma unroll
    for (int i = 0; i < 2; i++) {
        int ar = 32 * w + 16 * i + (lane & 15);
#pragma unroll
        for (int ks = 0; ks < 4; ks++)
            ldm_x4(A1[i][ks][0], A1[i][ks][1], A1[i][ks][2], A1[i][ks][3],
                   smem_u32(sEA + ar * 72 + ks * 16 + ac));
    }

    // GEMM1 in quarter-N chunks -> A2 fragments
    uint32_t A2[2][8][4];
#pragma unroll
    for (int q = 0; q < 4; q++) {
        float C1[2][4][4];
#pragma unroll
        for (int i = 0; i < 2; i++)
#pragma unroll
            for (int n = 0; n < 4; n++)
#pragma unroll
                for (int j = 0; j < 4; j++) C1[i][n][j] = 0.0f;
#pragma unroll
        for (int ks = 0; ks < 4; ks++) {
#pragma unroll
            for (int j = 0; j < 4; j++) {
                int nt = q * 4 + j;
                uint32_t B[2];
                ldm_x2(B[0], B[1], smem_u32(sW1 + (nt * 8 + bn) * 72 + ks * 16 + bk));
                mma16816(C1[0][j], A1[0][ks], B);
                mma16816(C1[1][j], A1[1][ks], B);
            }
        }
#pragma unroll
        for (int j = 0; j < 4; j++) {
            int nt = q * 4 + j;
            int col = nt * 8 + 2 * t;
            float b0 = sB1[col], b1v = sB1[col + 1];
#pragma unroll
            for (int i = 0; i < 2; i++) {
                float u0 = ssp(C1[i][j][0] + b0), u1 = ssp(C1[i][j][1] + b1v);
                float u2 = ssp(C1[i][j][2] + b0), u3 = ssp(C1[i][j][3] + b1v);
                A2[i][nt >> 1][(nt & 1) * 2 + 0] = h2u(u0, u1);
                A2[i][nt >> 1][(nt & 1) * 2 + 1] = h2u(u2, u3);
            }
        }
    }

    // per-slot row metadata
    int rl[2][2];
    float ce[2][2];
#pragma unroll
    for (int i = 0; i < 2; i++)
#pragma unroll
        for (int j = 0; j < 2; j++) {
            int er = 32 * w + 16 * i + 8 * j + g;
            rl[i][j] = sRow[er];
            ce[i][j] = sCut[er];
        }
    const int atom = tile * 8 + w;

    // GEMM2 in quarter-N chunks + fused epilogue
#pragma unroll
    for (int q = 0; q < 4; q++) {
        float C2[2][4][4];
#pragma unroll
        for (int i = 0; i < 2; i++)
#pragma unroll
            for (int n = 0; n < 4; n++)
#pragma unroll
                for (int j = 0; j < 4; j++) C2[i][n][j] = 0.0f;
#pragma unroll
        for (int ks = 0; ks < 8; ks++) {
#pragma unroll
            for (int j = 0; j < 4; j++) {
                int nt = q * 4 + j;
                uint32_t B[2];
                ldm_x2(B[0], B[1], smem_u32(sW2 + (nt * 8 + bn) * 136 + ks * 16 + bk));
                mma16816(C2[0][j], A2[0][ks], B);
                mma16816(C2[1][j], A2[1][ks], B);
            }
        }
#pragma unroll
        for (int j = 0; j < 4; j++) {
            int nt = q * 4 + j;
            int col = nt * 8 + 2 * t;
            float b0 = sB2[col], b1v = sB2[col + 1];
            float s0 = 0.0f, s1 = 0.0f;
#pragma unroll
            for (int i = 0; i < 2; i++) {
                float2 xa = xld(sXF + rl[i][0] * 136 + col);
                float2 xb = xld(sXF + rl[i][1] * 136 + col);
                s0 += xa.x * (C2[i][j][0] + b0) * ce[i][0]
                    + xb.x * (C2[i][j][2] + b0) * ce[i][1];
                s1 += xa.y * (C2[i][j][1] + b1v) * ce[i][0]
                    + xb.y * (C2[i][j][3] + b1v) * ce[i][1];
            }
            s0 += __shfl_xor_sync(0xFFFFFFFFu, s0, 4);
            s0 += __shfl_xor_sync(0xFFFFFFFFu, s0, 8);
            s0 += __shfl_xor_sync(0xFFFFFFFFu, s0, 16);
            s1 += __shfl_xor_sync(0xFFFFFFFFu, s1, 4);
            s1 += __shfl_xor_sync(0xFFFFFFFFu, s1, 8);
            s1 += __shfl_xor_sync(0xFFFFFFFFu, s1, 16);
            if (lane < 4)
                *(uint32_t*)(g_aggh + (size_t)atom * H + col) = h2u(s0, s1);
        }
    }
}

// ---------------- node update (+ fused next-layer xf) ------------------------
__global__ void __launch_bounds__(256, 1)
node_kernel(const float* __restrict__ cb2, const float* __restrict__ ib, int l, int do_xf) {
    extern __shared__ char sm[];
    __half* sA = (__half*)sm;
    __half* sW = (__half*)(sm + 34816);
    float* sB1 = (float*)(sm + 69632);
    float* sB2 = (float*)(sm + 70144);
    const int tid = threadIdx.x, w = tid >> 5, lane = tid & 31;
    const int g = lane >> 2, t = lane & 3;
    const int tile = blockIdx.x;

    {
        const uint4* asrc = (const uint4*)(g_aggh + (size_t)tile * 128 * H);
        const uint4* wsrc = (const uint4*)(g_cw2t + (size_t)l * H * H);
        for (int i = tid; i < 2048; i += 256) {
            int r = i >> 4, c = i & 15;
            *(uint4*)(sA + r * 136 + c * 8) = asrc[i];
            *(uint4*)(sW + r * 136 + c * 8) = wsrc[i];
        }
        if (tid < 128) {
            sB1[tid] = cb2[l * H + tid];
            sB2[tid] = ib[l * H + tid];
        }
    }
    __syncthreads();

    const int bn = lane & 7;
    const int bk = ((lane >> 3) & 1) * 8;
    const int ac = (lane >> 4) << 3;
    const int ar = 16 * w + (lane & 15);

    uint32_t A2[8][4];
    {
        float C1[16][4];
#pragma unroll
        for (int nt = 0; nt < 16; nt++)
#pragma unroll
            for (int j = 0; j < 4; j++) C1[nt][j] = 0.0f;
#pragma unroll
        for (int ks = 0; ks < 8; ks++) {
            uint32_t A[4];
            ldm_x4(A[0], A[1], A[2], A[3], smem_u32(sA + ar * 136 + ks * 16 + ac));
#pragma unroll
            for (int nt = 0; nt < 16; nt++) {
                uint32_t B[2];
                ldm_x2(B[0], B[1], smem_u32(sW + (nt * 8 + bn) * 136 + ks * 16 + bk));
                mma16816(C1[nt], A, B);
            }
        }
#pragma unroll
        for (int nt = 0; nt < 16; nt++) {
            int col = nt * 8 + 2 * t;
            float b0 = sB1[col], b1v = sB1[col + 1];
            float u0 = ssp(C1[nt][0] + b0), u1 = ssp(C1[nt][1] + b1v);
            float u2 = ssp(C1[nt][2] + b0), u3 = ssp(C1[nt][3] + b1v);
            A2[nt >> 1][(nt & 1) * 2 + 0] = h2u(u0, u1);
            A2[nt >> 1][(nt & 1) * 2 + 1] = h2u(u2, u3);
        }
    }
    __syncthreads();
    {
        const uint4* wsrc = (const uint4*)(g_iwt + (size_t)l * H * H);
        for (int i = tid; i < 2048; i += 256) {
            int r = i >> 4, c = i & 15;
            *(uint4*)(sW + r * 136 + c * 8) = wsrc[i];
        }
    }
    __syncthreads();

    float C2[16][4];
#pragma unroll
    for (int nt = 0; nt < 16; nt++)
#pragma unroll
        for (int j = 0; j < 4; j++) C2[nt][j] = 0.0f;
#pragma unroll
    for (int ks = 0; ks < 8; ks++) {
#pragma unroll
        for (int nt = 0; nt < 16; nt++) {
            uint32_t B[2];
            ldm_x2(B[0], B[1], smem_u32(sW + (nt * 8 + bn) * 136 + ks * 16 + bk));
            mma16816(C2[nt], A2[ks], B);
        }
    }

    uint32_t A3[8][4];
    {
        const int r0 = tile * 128 + 16 * w + g;
#pragma unroll
        for (int nt = 0; nt < 16; nt++) {
            int col = nt * 8 + 2 * t;
            float b0 = sB2[col], b1v = sB2[col + 1];
            float2 h0 = *(float2*)(g_h + (size_t)r0 * H + col);
            float2 h1 = *(float2*)(g_h + (size_t)(r0 + 8) * H + col);
            float n00 = h0.x + C2[nt][0] + b0, n01 = h0.y + C2[nt][1] + b1v;
            float n10 = h1.x + C2[nt][2] + b0, n11 = h1.y + C2[nt][3] + b1v;
            *(float2*)(g_h + (size_t)r0 * H + col) = make_float2(n00, n01);
            *(float2*)(g_h + (size_t)(r0 + 8) * H + col) = make_float2(n10, n11);
            *(uint32_t*)(g_hhf + (size_t)r0 * H + col) = h2u(n00, n01);
            *(uint32_t*)(g_hhf + (size_t)(r0 + 8) * H + col) = h2u(n10, n11);
            A3[nt >> 1][(nt & 1) * 2 + 0] = h2u(n00, n01);
            A3[nt >> 1][(nt & 1) * 2 + 1] = h2u(n10, n11);
        }
    }

    if (!do_xf) return;
    __syncthreads();
    {
        const uint4* wsrc = (const uint4*)(g_cw1t + (size_t)(l + 1) * H * H);
        for (int i = tid; i < 2048; i += 256) {
            int r = i >> 4, c = i & 15;
            *(uint4*)(sW + r * 136 + c * 8) = wsrc[i];
        }
    }
    __syncthreads();

    float C3[16][4];
#pragma unroll
    for (int nt = 0; nt < 16; nt++)
#pragma unroll
        for (int j = 0; j < 4; j++) C3[nt][j] = 0.0f;
#pragma unroll
    for (int ks = 0; ks < 8; ks++) {
#pragma unroll
        for (int nt = 0; nt < 16; nt++) {
            uint32_t B[2];
            ldm_x2(B[0], B[1], smem_u32(sW + (nt * 8 + bn) * 136 + ks * 16 + bk));
            mma16816(C3[nt], A3[ks], B);
        }
    }
    {
        const int r0 = tile * 128 + 16 * w + g;
#pragma unroll
        for (int nt = 0; nt < 16; nt++) {
            int col = nt * 8 + 2 * t;
            *(uint32_t*)(g_xfh + (size_t)r0 * H + col) = h2u(C3[nt][0], C3[nt][1]);
            *(uint32_t*)(g_xfh + (size_t)(r0 + 8) * H + col) = h2u(C3[nt][2], C3[nt][3]);
        }
    }
}

// ---------------- readout ----------------
__global__ void __launch_bounds__(256, 1)
readout_kernel(const float* __restrict__ ob1, const float* __restrict__ ob2) {
    extern __shared__ char sm[];
    __half* sA = (__half*)sm;
    __half* sW = (__half*)(sm + 34816);
    float* sRed = (float*)(sm + 69632);
    float* sB1 = (float*)(sm + 73728);
    float* sB2 = (float*)(sm + 74240);
    const int tid = threadIdx.x, w = tid >> 5, lane = tid & 31;
    const int g = lane >> 2, t = lane & 3;
    const int tile = blockIdx.x;

    {
        const uint4* asrc = (const uint4*)(g_hhf + (size_t)tile * 128 * H);
        const uint4* wsrc = (const uint4*)g_ow1t;
        for (int i = tid; i < 2048; i += 256) {
            int r = i >> 4, c = i & 15;
            *(uint4*)(sA + r * 136 + c * 8) = asrc[i];
            *(uint4*)(sW + r * 136 + c * 8) = wsrc[i];
        }
        if (tid < 128) {
            sB1[tid] = ob1[tid];
            sB2[tid] = ob2[tid];
        }
    }
    __syncthreads();

    const int bn = lane & 7;
    const int bk = ((lane >> 3) & 1) * 8;
    const int ac = (lane >> 4) << 3;
    const int ar = 16 * w + (lane & 15);

    uint32_t A2[8][4];
    {
        float C1[16][4];
#pragma unroll
        for (int nt = 0; nt < 16; nt++)
#pragma unroll
            for (int j = 0; j < 4; j++) C1[nt][j] = 0.0f;
#pragma unroll
        for (int ks = 0; ks < 8; ks++) {
            uint32_t A[4];
            ldm_x4(A[0], A[1], A[2], A[3], smem_u32(sA + ar * 136 + ks * 16 + ac));
#pragma unroll
            for (int nt = 0; nt < 16; nt++) {
                uint32_t B[2];
                ldm_x2(B[0], B[1], smem_u32(sW + (nt * 8 + bn) * 136 + ks * 16 + bk));
                mma16816(C1[nt], A, B);
            }
        }
#pragma unroll
        for (int nt = 0; nt < 16; nt++) {
            int col = nt * 8 + 2 * t;
            float b0 = sB1[col], b1v = sB1[col + 1];
            float u0 = ssp(C1[nt][0] + b0), u1 = ssp(C1[nt][1] + b1v);
            float u2 = ssp(C1[nt][2] + b0), u3 = ssp(C1[nt][3] + b1v);
            A2[nt >> 1][(nt & 1) * 2 + 0] = h2u(u0, u1);
            A2[nt >> 1][(nt & 1) * 2 + 1] = h2u(u2, u3);
        }
    }
    __syncthreads();
    {
        const uint4* wsrc = (const uint4*)g_ow2t;
        for (int i = tid; i < 2048; i += 256) {
            int r = i >> 4, c = i & 15;
            *(uint4*)(sW + r * 136 + c * 8) = wsrc[i];
        }
    }
    __syncthreads();

    float C2[16][4];
#pragma unroll
    for (int nt = 0; nt < 16; nt++)
#pragma unroll
        for (int j = 0; j < 4; j++) C2[nt][j] = 0.0f;
#pragma unroll
    for (int ks = 0; ks < 8; ks++) {
#pragma unroll
        for (int nt = 0; nt < 16; nt++) {
            uint32_t B[2];
            ldm_x2(B[0], B[1], smem_u32(sW + (nt * 8 + bn) * 136 + ks * 16 + bk));
            mma16816(C2[nt], A2[ks], B);
        }
    }
    {
#pragma unroll
        for (int nt = 0; nt < 16; nt++) {
            int col = nt * 8 + 2 * t;
            float b0 = sB2[col], b1v = sB2[col + 1];
            float s0 = (C2[nt][0] + b0) + (C2[nt][2] + b0);
            float s1 = (C2[nt][1] + b1v) + (C2[nt][3] + b1v);
            s0 += __shfl_xor_sync(0xFFFFFFFFu, s0, 4);
            s0 += __shfl_xor_sync(0xFFFFFFFFu, s0, 8);
            s0 += __shfl_xor_sync(0xFFFFFFFFu, s0, 16);
            s1 += __shfl_xor_sync(0xFFFFFFFFu, s1, 4);
            s1 += __shfl_xor_sync(0xFFFFFFFFu, s1, 8);
            s1 += __shfl_xor_sync(0xFFFFFFFFu, s1, 16);
            if (lane < 4) {
                sRed[w * 128 + col] = s0;
                sRed[w * 128 + col + 1] = s1;
            }
        }
    }
    __syncthreads();
    for (int i = tid; i < 256; i += 256) {
        int p = i >> 7, c = i & 127;
        float v = sRed[(4 * p + 0) * 128 + c] + sRed[(4 * p + 1) * 128 + c]
                + sRed[(4 * p + 2) * 128 + c] + sRed[(4 * p + 3) * 128 + c];
        g_conf[(size_t)(2 * tile + p) * H + c] = v;
    }
}

// ---------------- final: mol sum + head MLP ----------------
__global__ void __launch_bounds__(256, 1)
final_kernel(const float* __restrict__ hw1, const float* __restrict__ hb1,
             const float* __restrict__ hw2, const float* __restrict__ hb2,
             float* __restrict__ out) {
    extern __shared__ char sm[];
    float* s_mol = (float*)sm;
    float* s_hid = (float*)sm + 8192;
    const int tid = threadIdx.x;
    for (int idx = tid; idx < N_MOL * H; idx += 256) {
        int m = idx >> 7, c = idx & 127;
        s_mol[idx] = g_conf[(m * 4 + 0) * H + c] + g_conf[(m * 4 + 1) * H + c]
                   + g_conf[(m * 4 + 2) * H + c] + g_conf[(m * 4 + 3) * H + c];
    }
    __syncthreads();
    for (int idx = tid; idx < N_MOL * 64; idx += 256) {
        int m = idx >> 6, j = idx & 63;
        float acc = hb1[j];
#pragma unroll 4
        for (int k = 0; k < H; k++) acc += s_mol[m * H + k] * hw1[k * 64 + j];
        s_hid[idx] = ssp(acc);
    }
    __syncthreads();
    if (tid < N_MOL) {
        float acc = hb2[0];
#pragma unroll 4
        for (int j = 0; j < 64; j++) acc += s_hid[tid * 64 + j] * hw2[j];
        out[tid] = acc;
    }
}

// ---------------- launch ----------------
extern "C" void kernel_launch(void* const* d_in, const int* in_sizes, int n_in,
                              void* d_out, int out_size) {
    const int*   z   = (const int*)d_in[0];
    const float* pos = (const float*)d_in[1];
    const int*   ei  = (const int*)d_in[2];
    const float* emb = (const float*)d_in[5];
    const float* mw1 = (const float*)d_in[6];
    const float* mb1 = (const float*)d_in[7];
    const float* mw2 = (const float*)d_in[8];
    const float* mb2 = (const float*)d_in[9];
    const float* cw1 = (const float*)d_in[10];
    const float* cw2 = (const float*)d_in[11];
    const float* cb2 = (const float*)d_in[12];
    const float* iw  = (const float*)d_in[13];
    const float* ib  = (const float*)d_in[14];
    const float* ow1 = (const float*)d_in[15];
    const float* ob1 = (const float*)d_in[16];
    const float* ow2 = (const float*)d_in[17];
    const float* ob2 = (const float*)d_in[18];
    const float* hw1 = (const float*)d_in[19];
    const float* hb1 = (const float*)d_in[20];
    const float* hw2 = (const float*)d_in[21];
    const float* hb2 = (const float*)d_in[22];
    float* out = (float*)d_out;

    cudaFuncSetAttribute(xf_kernel, cudaFuncAttributeMaxDynamicSharedMemorySize, 69632);
    cudaFuncSetAttribute(edge_kernel, cudaFuncAttributeMaxDynamicSharedMemorySize, ES_TOT);
    cudaFuncSetAttribute(node_kernel, cudaFuncAttributeMaxDynamicSharedMemorySize, 70656);
    cudaFuncSetAttribute(readout_kernel, cudaFuncAttributeMaxDynamicSharedMemorySize, 74752);
    cudaFuncSetAttribute(final_kernel, cudaFuncAttributeMaxDynamicSharedMemorySize, 49152);

    const int WTOT = S1 + 4 * S2 + 2 * S6;
    prep_weights<<<(WTOT + 255) / 256, 256>>>(mw1, mw2, cw1, cw2, iw, ow1, ow2);
    precompute_kernel<<<EDGES / 128, 128>>>(pos, ei);
    hinit_kernel<<<(N_ATOMS * H) / 256, 256>>>(z, emb);

    xf_kernel<<<N_ATOMS / 128, 256, 69632>>>(0);
    for (int l = 0; l < NLAYER; l++) {
        edge_kernel<<<EDGES / 256, 256, ES_TOT>>>(mb1, mb2, l);
        node_kernel<<<N_ATOMS / 128, 256, 70656>>>(cb2, ib, l, l < NLAYER - 1);
    }
    readout_kernel<<<N_ATOMS / 128, 256, 74752>>>(ob1, ob2);
    final_kernel<<<1, 256, 49152>>>(hw1, hb1, hw2, hb2, out);
}

// round 10
// speedup vs baseline: 6.3401x; 1.4841x over previous
#include <cuda_runtime.h>
#include <cuda_fp16.h>
#include <math.h>
#include <stdint.h>

#define N_ATOMS 16384
#define APC     64
#define N_CONF  256
#define N_MOL   64
#define DEG     32
#define EDGES   (N_ATOMS * DEG)     // 524288
#define H       128
#define G       50
#define GPAD    64
#define NLAYER  6

// ---------------- device scratch ----------------
__device__ __align__(16) __half g_ea[(size_t)EDGES * GPAD];
__device__ __align__(16) float  g_c[EDGES];
__device__ __align__(16) int    g_rowloc[EDGES];
__device__ __align__(16) float  g_h[N_ATOMS * H];
__device__ __align__(16) __half g_hhf[N_ATOMS * H];
__device__ __align__(16) __half g_xfh[N_ATOMS * H];
__device__ __align__(16) __half g_aggh[N_ATOMS * H];
__device__ __align__(16) float  g_conf[N_CONF * H];
// transposed fp16 weights: [l][n][k]
__device__ __align__(16) __half g_w1t[NLAYER * H * GPAD];
__device__ __align__(16) __half g_w2t[NLAYER * H * H];
__device__ __align__(16) __half g_cw1t[NLAYER * H * H];
__device__ __align__(16) __half g_cw2t[NLAYER * H * H];
__device__ __align__(16) __half g_iwt[NLAYER * H * H];
__device__ __align__(16) __half g_ow1t[H * H];
__device__ __align__(16) __half g_ow2t[H * H];

// fast stable softplus(x) - log(2): 3 MUFU, no branches
__device__ __forceinline__ float ssp(float x) {
    float m = fmaxf(x, 0.0f);
    return m + __logf(__expf(x - m) + __expf(-m)) - 0.69314718055994531f;
}
__device__ __forceinline__ uint32_t smem_u32(const void* p) {
    uint32_t a;
    asm("{ .reg .u64 t; cvta.to.shared.u64 t, %1; cvt.u32.u64 %0, t; }" : "=r"(a) : "l"(p));
    return a;
}
__device__ __forceinline__ void ldm_x4(uint32_t& r0, uint32_t& r1, uint32_t& r2, uint32_t& r3,
                                       uint32_t a) {
    asm volatile("ldmatrix.sync.aligned.m8n8.x4.shared.b16 {%0,%1,%2,%3}, [%4];"
                 : "=r"(r0), "=r"(r1), "=r"(r2), "=r"(r3) : "r"(a));
}
__device__ __forceinline__ void ldm_x2(uint32_t& r0, uint32_t& r1, uint32_t a) {
    asm volatile("ldmatrix.sync.aligned.m8n8.x2.shared.b16 {%0,%1}, [%2];"
                 : "=r"(r0), "=r"(r1) : "r"(a));
}
__device__ __forceinline__ void mma16816(float* c, const uint32_t* a, const uint32_t* b) {
    asm volatile(
        "mma.sync.aligned.m16n8k16.row.col.f32.f16.f16.f32 "
        "{%0,%1,%2,%3}, {%4,%5,%6,%7}, {%8,%9}, {%0,%1,%2,%3};"
        : "+f"(c[0]), "+f"(c[1]), "+f"(c[2]), "+f"(c[3])
        : "r"(a[0]), "r"(a[1]), "r"(a[2]), "r"(a[3]), "r"(b[0]), "r"(b[1]));
}
__device__ __forceinline__ uint32_t h2u(float a, float b) {
    __half2 p = __floats2half2_rn(a, b);
    return *(uint32_t*)&p;
}
__device__ __forceinline__ float2 xld(const __half* p) {
    __half2 h = *(const __half2*)p;
    return __half22float2(h);
}

// ---------------- prep: all weight transposes in ONE kernel ----------------
__device__ __forceinline__ void tr1(const float* src, __half* dst, int idx,
                                    int K, int N, int Kpad) {
    int k = idx % Kpad;
    int n = (idx / Kpad) % N;
    int l = idx / (Kpad * N);
    float v = (k < K) ? src[(size_t)l * K * N + (size_t)k * N + n] : 0.0f;
    dst[idx] = __float2half(v);
}
#define S1 (NLAYER * H * GPAD)
#define S2 (NLAYER * H * H)
#define S6 (H * H)
__global__ void prep_weights(const float* mw1, const float* mw2, const float* cw1,
                             const float* cw2, const float* iw,
                             const float* ow1, const float* ow2) {
    int idx = blockIdx.x * blockDim.x + threadIdx.x;
    if (idx < S1) { tr1(mw1, g_w1t, idx, G, H, GPAD); return; }
    idx -= S1;
    if (idx < S2) { tr1(mw2, g_w2t, idx, H, H, H); return; }
    idx -= S2;
    if (idx < S2) { tr1(cw1, g_cw1t, idx, H, H, H); return; }
    idx -= S2;
    if (idx < S2) { tr1(cw2, g_cw2t, idx, H, H, H); return; }
    idx -= S2;
    if (idx < S2) { tr1(iw, g_iwt, idx, H, H, H); return; }
    idx -= S2;
    if (idx < S6) { tr1(ow1, g_ow1t, idx, H, H, H); return; }
    idx -= S6;
    if (idx < S6) { tr1(ow2, g_ow2t, idx, H, H, H); return; }
}

// ---------------- edge precompute: recurrence-based gaussians ---------------
__global__ void precompute_kernel(const float* __restrict__ pos, const int* __restrict__ ei) {
    __shared__ __half sE[128 * 72];
    const int tid = threadIdx.x;
    const int e = blockIdx.x * 128 + tid;
    int r = ei[e], c = ei[EDGES + e];
    float dx = pos[3 * r + 0] - pos[3 * c + 0];
    float dy = pos[3 * r + 1] - pos[3 * c + 1];
    float dz = pos[3 * r + 2] - pos[3 * c + 2];
    float d = sqrtf(dx * dx + dy * dy + dz * dz);
    g_c[e] = 0.5f * (__cosf(d * 0.31415926535897931f) + 1.0f);
    g_rowloc[e] = r & (APC - 1);

    const float delta = 10.0f / 49.0f;
    const float cf = -0.5f / (delta * delta);
    const float q = expf(2.0f * cf * delta * delta);
    int k0 = (int)(d / delta + 0.5f);
    if (k0 > 49) k0 = 49;
    float t0 = d - (float)k0 * delta;

    __half* row = sE + tid * 72;
#pragma unroll
    for (int k = 50; k < 64; k++) row[k] = __float2half(0.0f);
    float E0 = expf(cf * t0 * t0);
    row[k0] = __float2half(E0);
    float u = expf(cf * (delta * delta - 2.0f * delta * t0));
    float E = E0;
    for (int k = k0 + 1; k <= 49; k++) { E *= u; u *= q; row[k] = __float2half(E); }
    float v = expf(cf * (delta * delta + 2.0f * delta * t0));
    E = E0;
    for (int k = k0 - 1; k >= 0; k--) { E *= v; v *= q; row[k] = __float2half(E); }
    __syncthreads();

    uint4* dst = (uint4*)(g_ea + (size_t)blockIdx.x * 128 * GPAD);
    for (int i = tid; i < 1024; i += 128) {
        int rr = i >> 3, cc = i & 7;
        dst[i] = *(uint4*)(sE + rr * 72 + cc * 8);
    }
}

__global__ void hinit_kernel(const int* __restrict__ z, const float* __restrict__ emb) {
    int idx = blockIdx.x * blockDim.x + threadIdx.x;
    if (idx >= N_ATOMS * H) return;
    float v = emb[z[idx >> 7] * H + (idx & 127)];
    g_h[idx] = v;
    g_hhf[idx] = __float2half(v);
}

// ---------------- xf = h @ cf_w1[0] (layer 0 only) ----------------
__global__ void __launch_bounds__(256, 1)
xf_kernel(int l) {
    extern __shared__ char sm[];
    __half* sA = (__half*)sm;
    __half* sW = (__half*)(sm + 34816);
    const int tid = threadIdx.x, w = tid >> 5, lane = tid & 31;
    const int g = lane >> 2, t = lane & 3;
    const int tile = blockIdx.x;

    {
        const uint4* asrc = (const uint4*)(g_hhf + (size_t)tile * 128 * H);
        const uint4* wsrc = (const uint4*)(g_cw1t + (size_t)l * H * H);
        for (int i = tid; i < 2048; i += 256) {
            int r = i >> 4, c = i & 15;
            *(uint4*)(sA + r * 136 + c * 8) = asrc[i];
            *(uint4*)(sW + r * 136 + c * 8) = wsrc[i];
        }
    }
    __syncthreads();

    float C[16][4];
#pragma unroll
    for (int nt = 0; nt < 16; nt++)
#pragma unroll
        for (int j = 0; j < 4; j++) C[nt][j] = 0.0f;

    const int ar = 16 * w + (lane & 15);
    const int ac = (lane >> 4) << 3;
    const int bn = lane & 7;
    const int bk = ((lane >> 3) & 1) * 8;
#pragma unroll
    for (int ks = 0; ks < 8; ks++) {
        uint32_t A[4];
        ldm_x4(A[0], A[1], A[2], A[3], smem_u32(sA + ar * 136 + ks * 16 + ac));
#pragma unroll
        for (int nt = 0; nt < 16; nt++) {
            uint32_t B[2];
            ldm_x2(B[0], B[1], smem_u32(sW + (nt * 8 + bn) * 136 + ks * 16 + bk));
            mma16816(C[nt], A, B);
        }
    }
    const int r0 = tile * 128 + 16 * w + g;
#pragma unroll
    for (int nt = 0; nt < 16; nt++) {
        int col = nt * 8 + 2 * t;
        *(uint32_t*)(g_xfh + (size_t)r0 * H + col) = h2u(C[nt][0], C[nt][1]);
        *(uint32_t*)(g_xfh + (size_t)(r0 + 8) * H + col) = h2u(C[nt][2], C[nt][3]);
    }
}

// ---------------- edge kernel: 256 edges/CTA, EA A-frags direct from L2 -----
// smem: sW1 [128][72]h 18432 | sW2 [128][136]h 34816 | sXF [64][136]h 17408 |
//       row 1024 | cut 1024 | b1 512 | b2 512  => 73728 total
#define ES_W1   0
#define ES_W2   18432
#define ES_XF   53248
#define ES_ROW  70656
#define ES_CUT  71680
#define ES_B1   72704
#define ES_B2   73216
#define ES_TOT  73728

__global__ void __launch_bounds__(256, 2)
edge_kernel(const float* __restrict__ mb1, const float* __restrict__ mb2, int l) {
    extern __shared__ char sm[];
    __half* sW1 = (__half*)(sm + ES_W1);
    __half* sW2 = (__half*)(sm + ES_W2);
    __half* sXF = (__half*)(sm + ES_XF);
    int* sRow = (int*)(sm + ES_ROW);
    float* sCut = (float*)(sm + ES_CUT);
    float* sB1 = (float*)(sm + ES_B1);
    float* sB2 = (float*)(sm + ES_B2);

    const int tid = threadIdx.x, w = tid >> 5, lane = tid & 31;
    const int g = lane >> 2, t = lane & 3;
    const int tile = blockIdx.x;      // 256 edges
    const int conf = tile >> 3;

    {
        const uint4* w1src = (const uint4*)(g_w1t + (size_t)l * H * GPAD);
        for (int i = tid; i < 1024; i += 256) {
            int r = i >> 3, c = i & 7;
            *(uint4*)(sW1 + r * 72 + c * 8) = w1src[i];
        }
        const uint4* w2src = (const uint4*)(g_w2t + (size_t)l * H * H);
        for (int i = tid; i < 2048; i += 256) {
            int r = i >> 4, c = i & 15;
            *(uint4*)(sW2 + r * 136 + c * 8) = w2src[i];
        }
        const uint4* xfsrc = (const uint4*)(g_xfh + (size_t)conf * APC * H);
        for (int i = tid; i < 1024; i += 256) {
            int r = i >> 4, c = i & 15;
            *(uint4*)(sXF + r * 136 + c * 8) = xfsrc[i];
        }
        {
            int e = tile * 256 + tid;
            sRow[tid] = g_rowloc[e];
            sCut[tid] = g_c[e];
        }
        if (tid < 128) {
            sB1[tid] = mb1[l * H + tid];
            sB2[tid] = mb2[l * H + tid];
        }
    }

    // A fragments of EA loaded DIRECTLY from global (L2-resident, 64MB)
    // reg r of frag (i,ks): row = 32w+16i+g+8*(r&1), col = 16ks+2t+8*(r>>1)
    uint32_t A1[2][4][4];
    {
        const int e_base = tile * 256 + 32 * w;
#pragma unroll
        for (int i = 0; i < 2; i++)
#pragma unroll
            for (int ks = 0; ks < 4; ks++)
#pragma unroll
                for (int r = 0; r < 4; r++) {
                    int row = 16 * i + g + 8 * (r & 1);
                    int col = 16 * ks + 2 * t + 8 * (r >> 1);
                    A1[i][ks][r] = *(const uint32_t*)(g_ea + (size_t)(e_base + row) * GPAD + col);
                }
    }
    __syncthreads();

    const int bn = lane & 7;
    const int bk = ((lane >> 3) & 1) * 8;

    // GEMM1 in quarter-N chunks -> A2 fragments
    uint32_t A2[2][8][4];
#pragma unroll
    for (int q = 0; q < 4; q++) {
        float C1[2][4][4];
#pragma unroll
        for (int i = 0; i < 2; i++)
#pragma unroll
            for (int n = 0; n < 4; n++)
#pragma unroll
                for (int j = 0; j < 4; j++) C1[i][n][j] = 0.0f;
#pragma unroll
        for (int ks = 0; ks < 4; ks++) {
#pragma unroll
            for (int j = 0; j < 4; j++) {
                int nt = q * 4 + j;
                uint32_t B[2];
                ldm_x2(B[0], B[1], smem_u32(sW1 + (nt * 8 + bn) * 72 + ks * 16 + bk));
                mma16816(C1[0][j], A1[0][ks], B);
                mma16816(C1[1][j], A1[1][ks], B);
            }
        }
#pragma unroll
        for (int j = 0; j < 4; j++) {
            int nt = q * 4 + j;
            int col = nt * 8 + 2 * t;
            float b0 = sB1[col], b1v = sB1[col + 1];
#pragma unroll
            for (int i = 0; i < 2; i++) {
                float u0 = ssp(C1[i][j][0] + b0), u1 = ssp(C1[i][j][1] + b1v);
                float u2 = ssp(C1[i][j][2] + b0), u3 = ssp(C1[i][j][3] + b1v);
                A2[i][nt >> 1][(nt & 1) * 2 + 0] = h2u(u0, u1);
                A2[i][nt >> 1][(nt & 1) * 2 + 1] = h2u(u2, u3);
            }
        }
    }

    // per-slot row metadata
    int rl[2][2];
    float ce[2][2];
#pragma unroll
    for (int i = 0; i < 2; i++)
#pragma unroll
        for (int j = 0; j < 2; j++) {
            int er = 32 * w + 16 * i + 8 * j + g;
            rl[i][j] = sRow[er];
            ce[i][j] = sCut[er];
        }
    const int atom = tile * 8 + w;

    // GEMM2 in quarter-N chunks + fused epilogue
#pragma unroll
    for (int q = 0; q < 4; q++) {
        float C2[2][4][4];
#pragma unroll
        for (int i = 0; i < 2; i++)
#pragma unroll
            for (int n = 0; n < 4; n++)
#pragma unroll
                for (int j = 0; j < 4; j++) C2[i][n][j] = 0.0f;
#pragma unroll
        for (int ks = 0; ks < 8; ks++) {
#pragma unroll
            for (int j = 0; j < 4; j++) {
                int nt = q * 4 + j;
                uint32_t B[2];
                ldm_x2(B[0], B[1], smem_u32(sW2 + (nt * 8 + bn) * 136 + ks * 16 + bk));
                mma16816(C2[0][j], A2[0][ks], B);
                mma16816(C2[1][j], A2[1][ks], B);
            }
        }
#pragma unroll
        for (int j = 0; j < 4; j++) {
            int nt = q * 4 + j;
            int col = nt * 8 + 2 * t;
            float b0 = sB2[col], b1v = sB2[col + 1];
            float s0 = 0.0f, s1 = 0.0f;
#pragma unroll
            for (int i = 0; i < 2; i++) {
                float2 xa = xld(sXF + rl[i][0] * 136 + col);
                float2 xb = xld(sXF + rl[i][1] * 136 + col);
                s0 += xa.x * (C2[i][j][0] + b0) * ce[i][0]
                    + xb.x * (C2[i][j][2] + b0) * ce[i][1];
                s1 += xa.y * (C2[i][j][1] + b1v) * ce[i][0]
                    + xb.y * (C2[i][j][3] + b1v) * ce[i][1];
            }
            s0 += __shfl_xor_sync(0xFFFFFFFFu, s0, 4);
            s0 += __shfl_xor_sync(0xFFFFFFFFu, s0, 8);
            s0 += __shfl_xor_sync(0xFFFFFFFFu, s0, 16);
            s1 += __shfl_xor_sync(0xFFFFFFFFu, s1, 4);
            s1 += __shfl_xor_sync(0xFFFFFFFFu, s1, 8);
            s1 += __shfl_xor_sync(0xFFFFFFFFu, s1, 16);
            if (lane < 4)
                *(uint32_t*)(g_aggh + (size_t)atom * H + col) = h2u(s0, s1);
        }
    }
}

// ---------------- node update (+ fused next-layer xf) ------------------------
__global__ void __launch_bounds__(256, 1)
node_kernel(const float* __restrict__ cb2, const float* __restrict__ ib, int l, int do_xf) {
    extern __shared__ char sm[];
    __half* sA = (__half*)sm;
    __half* sW = (__half*)(sm + 34816);
    float* sB1 = (float*)(sm + 69632);
    float* sB2 = (float*)(sm + 70144);
    const int tid = threadIdx.x, w = tid >> 5, lane = tid & 31;
    const int g = lane >> 2, t = lane & 3;
    const int tile = blockIdx.x;

    {
        const uint4* asrc = (const uint4*)(g_aggh + (size_t)tile * 128 * H);
        const uint4* wsrc = (const uint4*)(g_cw2t + (size_t)l * H * H);
        for (int i = tid; i < 2048; i += 256) {
            int r = i >> 4, c = i & 15;
            *(uint4*)(sA + r * 136 + c * 8) = asrc[i];
            *(uint4*)(sW + r * 136 + c * 8) = wsrc[i];
        }
        if (tid < 128) {
            sB1[tid] = cb2[l * H + tid];
            sB2[tid] = ib[l * H + tid];
        }
    }
    __syncthreads();

    const int bn = lane & 7;
    const int bk = ((lane >> 3) & 1) * 8;
    const int ac = (lane >> 4) << 3;
    const int ar = 16 * w + (lane & 15);

    uint32_t A2[8][4];
    {
        float C1[16][4];
#pragma unroll
        for (int nt = 0; nt < 16; nt++)
#pragma unroll
            for (int j = 0; j < 4; j++) C1[nt][j] = 0.0f;
#pragma unroll
        for (int ks = 0; ks < 8; ks++) {
            uint32_t A[4];
            ldm_x4(A[0], A[1], A[2], A[3], smem_u32(sA + ar * 136 + ks * 16 + ac));
#pragma unroll
            for (int nt = 0; nt < 16; nt++) {
                uint32_t B[2];
                ldm_x2(B[0], B[1], smem_u32(sW + (nt * 8 + bn) * 136 + ks * 16 + bk));
                mma16816(C1[nt], A, B);
            }
        }
#pragma unroll
        for (int nt = 0; nt < 16; nt++) {
            int col = nt * 8 + 2 * t;
            float b0 = sB1[col], b1v = sB1[col + 1];
            float u0 = ssp(C1[nt][0] + b0), u1 = ssp(C1[nt][1] + b1v);
            float u2 = ssp(C1[nt][2] + b0), u3 = ssp(C1[nt][3] + b1v);
            A2[nt >> 1][(nt & 1) * 2 + 0] = h2u(u0, u1);
            A2[nt >> 1][(nt & 1) * 2 + 1] = h2u(u2, u3);
        }
    }
    __syncthreads();
    {
        const uint4* wsrc = (const uint4*)(g_iwt + (size_t)l * H * H);
        for (int i = tid; i < 2048; i += 256) {
            int r = i >> 4, c = i & 15;
            *(uint4*)(sW + r * 136 + c * 8) = wsrc[i];
        }
    }
    __syncthreads();

    float C2[16][4];
#pragma unroll
    for (int nt = 0; nt < 16; nt++)
#pragma unroll
        for (int j = 0; j < 4; j++) C2[nt][j] = 0.0f;
#pragma unroll
    for (int ks = 0; ks < 8; ks++) {
#pragma unroll
        for (int nt = 0; nt < 16; nt++) {
            uint32_t B[2];
            ldm_x2(B[0], B[1], smem_u32(sW + (nt * 8 + bn) * 136 + ks * 16 + bk));
            mma16816(C2[nt], A2[ks], B);
        }
    }

    uint32_t A3[8][4];
    {
        const int r0 = tile * 128 + 16 * w + g;
#pragma unroll
        for (int nt = 0; nt < 16; nt++) {
            int col = nt * 8 + 2 * t;
            float b0 = sB2[col], b1v = sB2[col + 1];
            float2 h0 = *(float2*)(g_h + (size_t)r0 * H + col);
            float2 h1 = *(float2*)(g_h + (size_t)(r0 + 8) * H + col);
            float n00 = h0.x + C2[nt][0] + b0, n01 = h0.y + C2[nt][1] + b1v;
            float n10 = h1.x + C2[nt][2] + b0, n11 = h1.y + C2[nt][3] + b1v;
            *(float2*)(g_h + (size_t)r0 * H + col) = make_float2(n00, n01);
            *(float2*)(g_h + (size_t)(r0 + 8) * H + col) = make_float2(n10, n11);
            *(uint32_t*)(g_hhf + (size_t)r0 * H + col) = h2u(n00, n01);
            *(uint32_t*)(g_hhf + (size_t)(r0 + 8) * H + col) = h2u(n10, n11);
            A3[nt >> 1][(nt & 1) * 2 + 0] = h2u(n00, n01);
            A3[nt >> 1][(nt & 1) * 2 + 1] = h2u(n10, n11);
        }
    }

    if (!do_xf) return;
    __syncthreads();
    {
        const uint4* wsrc = (const uint4*)(g_cw1t + (size_t)(l + 1) * H * H);
        for (int i = tid; i < 2048; i += 256) {
            int r = i >> 4, c = i & 15;
            *(uint4*)(sW + r * 136 + c * 8) = wsrc[i];
        }
    }
    __syncthreads();

    float C3[16][4];
#pragma unroll
    for (int nt = 0; nt < 16; nt++)
#pragma unroll
        for (int j = 0; j < 4; j++) C3[nt][j] = 0.0f;
#pragma unroll
    for (int ks = 0; ks < 8; ks++) {
#pragma unroll
        for (int nt = 0; nt < 16; nt++) {
            uint32_t B[2];
            ldm_x2(B[0], B[1], smem_u32(sW + (nt * 8 + bn) * 136 + ks * 16 + bk));
            mma16816(C3[nt], A3[ks], B);
        }
    }
    {
        const int r0 = tile * 128 + 16 * w + g;
#pragma unroll
        for (int nt = 0; nt < 16; nt++) {
            int col = nt * 8 + 2 * t;
            *(uint32_t*)(g_xfh + (size_t)r0 * H + col) = h2u(C3[nt][0], C3[nt][1]);
            *(uint32_t*)(g_xfh + (size_t)(r0 + 8) * H + col) = h2u(C3[nt][2], C3[nt][3]);
        }
    }
}

// ---------------- readout ----------------
__global__ void __launch_bounds__(256, 1)
readout_kernel(const float* __restrict__ ob1, const float* __restrict__ ob2) {
    extern __shared__ char sm[];
    __half* sA = (__half*)sm;
    __half* sW = (__half*)(sm + 34816);
    float* sRed = (float*)(sm + 69632);
    float* sB1 = (float*)(sm + 73728);
    float* sB2 = (float*)(sm + 74240);
    const int tid = threadIdx.x, w = tid >> 5, lane = tid & 31;
    const int g = lane >> 2, t = lane & 3;
    const int tile = blockIdx.x;

    {
        const uint4* asrc = (const uint4*)(g_hhf + (size_t)tile * 128 * H);
        const uint4* wsrc = (const uint4*)g_ow1t;
        for (int i = tid; i < 2048; i += 256) {
            int r = i >> 4, c = i & 15;
            *(uint4*)(sA + r * 136 + c * 8) = asrc[i];
            *(uint4*)(sW + r * 136 + c * 8) = wsrc[i];
        }
        if (tid < 128) {
            sB1[tid] = ob1[tid];
            sB2[tid] = ob2[tid];
        }
    }
    __syncthreads();

    const int bn = lane & 7;
    const int bk = ((lane >> 3) & 1) * 8;
    const int ac = (lane >> 4) << 3;
    const int ar = 16 * w + (lane & 15);

    uint32_t A2[8][4];
    {
        float C1[16][4];
#pragma unroll
        for (int nt = 0; nt < 16; nt++)
#pragma unroll
            for (int j = 0; j < 4; j++) C1[nt][j] = 0.0f;
#pragma unroll
        for (int ks = 0; ks < 8; ks++) {
            uint32_t A[4];
            ldm_x4(A[0], A[1], A[2], A[3], smem_u32(sA + ar * 136 + ks * 16 + ac));
#pragma unroll
            for (int nt = 0; nt < 16; nt++) {
                uint32_t B[2];
                ldm_x2(B[0], B[1], smem_u32(sW + (nt * 8 + bn) * 136 + ks * 16 + bk));
                mma16816(C1[nt], A, B);
            }
        }
#pragma unroll
        for (int nt = 0; nt < 16; nt++) {
            int col = nt * 8 + 2 * t;
            float b0 = sB1[col], b1v = sB1[col + 1];
            float u0 = ssp(C1[nt][0] + b0), u1 = ssp(C1[nt][1] + b1v);
            float u2 = ssp(C1[nt][2] + b0), u3 = ssp(C1[nt][3] + b1v);
            A2[nt >> 1][(nt & 1) * 2 + 0] = h2u(u0, u1);
            A2[nt >> 1][(nt & 1) * 2 + 1] = h2u(u2, u3);
        }
    }
    __syncthreads();
    {
        const uint4* wsrc = (const uint4*)g_ow2t;
        for (int i = tid; i < 2048; i += 256) {
            int r = i >> 4, c = i & 15;
            *(uint4*)(sW + r * 136 + c * 8) = wsrc[i];
        }
    }
    __syncthreads();

    float C2[16][4];
#pragma unroll
    for (int nt = 0; nt < 16; nt++)
#pragma unroll
        for (int j = 0; j < 4; j++) C2[nt][j] = 0.0f;
#pragma unroll
    for (int ks = 0; ks < 8; ks++) {
#pragma unroll
        for (int nt = 0; nt < 16; nt++) {
            uint32_t B[2];
            ldm_x2(B[0], B[1], smem_u32(sW + (nt * 8 + bn) * 136 + ks * 16 + bk));
            mma16816(C2[nt], A2[ks], B);
        }
    }
    {
#pragma unroll
        for (int nt = 0; nt < 16; nt++) {
            int col = nt * 8 + 2 * t;
            float b0 = sB2[col], b1v = sB2[col + 1];
            float s0 = (C2[nt][0] + b0) + (C2[nt][2] + b0);
            float s1 = (C2[nt][1] + b1v) + (C2[nt][3] + b1v);
            s0 += __shfl_xor_sync(0xFFFFFFFFu, s0, 4);
            s0 += __shfl_xor_sync(0xFFFFFFFFu, s0, 8);
            s0 += __shfl_xor_sync(0xFFFFFFFFu, s0, 16);
            s1 += __shfl_xor_sync(0xFFFFFFFFu, s1, 4);
            s1 += __shfl_xor_sync(0xFFFFFFFFu, s1, 8);
            s1 += __shfl_xor_sync(0xFFFFFFFFu, s1, 16);
            if (lane < 4) {
                sRed[w * 128 + col] = s0;
                sRed[w * 128 + col + 1] = s1;
            }
        }
    }
    __syncthreads();
    for (int i = tid; i < 256; i += 256) {
        int p = i >> 7, c = i & 127;
        float v = sRed[(4 * p + 0) * 128 + c] + sRed[(4 * p + 1) * 128 + c]
                + sRed[(4 * p + 2) * 128 + c] + sRed[(4 * p + 3) * 128 + c];
        g_conf[(size_t)(2 * tile + p) * H + c] = v;
    }
}

// ---------------- final: mol sum + head MLP ----------------
__global__ void __launch_bounds__(256, 1)
final_kernel(const float* __restrict__ hw1, const float* __restrict__ hb1,
             const float* __restrict__ hw2, const float* __restrict__ hb2,
             float* __restrict__ out) {
    extern __shared__ char sm[];
    float* s_mol = (float*)sm;
    float* s_hid = (float*)sm + 8192;
    const int tid = threadIdx.x;
    for (int idx = tid; idx < N_MOL * H; idx += 256) {
        int m = idx >> 7, c = idx & 127;
        s_mol[idx] = g_conf[(m * 4 + 0) * H + c] + g_conf[(m * 4 + 1) * H + c]
                   + g_conf[(m * 4 + 2) * H + c] + g_conf[(m * 4 + 3) * H + c];
    }
    __syncthreads();
    for (int idx = tid; idx < N_MOL * 64; idx += 256) {
        int m = idx >> 6, j = idx & 63;
        float acc = hb1[j];
#pragma unroll 4
        for (int k = 0; k < H; k++) acc += s_mol[m * H + k] * hw1[k * 64 + j];
        s_hid[idx] = ssp(acc);
    }
    __syncthreads();
    if (tid < N_MOL) {
        float acc = hb2[0];
#pragma unroll 4
        for (int j = 0; j < 64; j++) acc += s_hid[tid * 64 + j] * hw2[j];
        out[tid] = acc;
    }
}

// ---------------- launch ----------------
extern "C" void kernel_launch(void* const* d_in, const int* in_sizes, int n_in,
                              void* d_out, int out_size) {
    const int*   z   = (const int*)d_in[0];
    const float* pos = (const float*)d_in[1];
    const int*   ei  = (const int*)d_in[2];
    const float* emb = (const float*)d_in[5];
    const float* mw1 = (const float*)d_in[6];
    const float* mb1 = (const float*)d_in[7];
    const float* mw2 = (const float*)d_in[8];
    const float* mb2 = (const float*)d_in[9];
    const float* cw1 = (const float*)d_in[10];
    const float* cw2 = (const float*)d_in[11];
    const float* cb2 = (const float*)d_in[12];
    const float* iw  = (const float*)d_in[13];
    const float* ib  = (const float*)d_in[14];
    const float* ow1 = (const float*)d_in[15];
    const float* ob1 = (const float*)d_in[16];
    const float* ow2 = (const float*)d_in[17];
    const float* ob2 = (const float*)d_in[18];
    const float* hw1 = (const float*)d_in[19];
    const float* hb1 = (const float*)d_in[20];
    const float* hw2 = (const float*)d_in[21];
    const float* hb2 = (const float*)d_in[22];
    float* out = (float*)d_out;

    cudaFuncSetAttribute(xf_kernel, cudaFuncAttributeMaxDynamicSharedMemorySize, 69632);
    cudaFuncSetAttribute(edge_kernel, cudaFuncAttributeMaxDynamicSharedMemorySize, ES_TOT);
    cudaFuncSetAttribute(node_kernel, cudaFuncAttributeMaxDynamicSharedMemorySize, 70656);
    cudaFuncSetAttribute(readout_kernel, cudaFuncAttributeMaxDynamicSharedMemorySize, 74752);
    cudaFuncSetAttribute(final_kernel, cudaFuncAttributeMaxDynamicSharedMemorySize, 49152);

    const int WTOT = S1 + 4 * S2 + 2 * S6;
    prep_weights<<<(WTOT + 255) / 256, 256>>>(mw1, mw2, cw1, cw2, iw, ow1, ow2);
    precompute_kernel<<<EDGES / 128, 128>>>(pos, ei);
    hinit_kernel<<<(N_ATOMS * H) / 256, 256>>>(z, emb);

    xf_kernel<<<N_ATOMS / 128, 256, 69632>>>(0);
    for (int l = 0; l < NLAYER; l++) {
        edge_kernel<<<EDGES / 256, 256, ES_TOT>>>(mb1, mb2, l);
        node_kernel<<<N_ATOMS / 128, 256, 70656>>>(cb2, ib, l, l < NLAYER - 1);
    }
    readout_kernel<<<N_ATOMS / 128, 256, 74752>>>(ob1, ob2);
    final_kernel<<<1, 256, 49152>>>(hw1, hb1, hw2, hb2, out);
}

// round 13
// speedup vs baseline: 19.3244x; 3.0480x over previous
#include <cuda_runtime.h>
#include <cuda_fp16.h>
#include <math.h>
#include <stdint.h>

#define N_ATOMS 16384
#define APC     64
#define N_CONF  256
#define N_MOL   64
#define DEG     32
#define EDGES   (N_ATOMS * DEG)     // 524288
#define H       128
#define G       50
#define GPAD    64
#define NLAYER  6
#define TAB     8192
#define DMAX    8.66025404f         // 5*sqrt(3)

// ---------------- device scratch ----------------
__device__ __align__(16) __half g_gt[TAB * GPAD];              // gauss at knots
__device__ __align__(16) __half g_wtab[NLAYER * TAB * H];      // filter table
__device__ __align__(16) uint32_t g_em[EDGES];                 // idx|row<<13|fq<<19
__device__ __align__(16) float  g_h[N_ATOMS * H];
__device__ __align__(16) __half g_hhf[N_ATOMS * H];
__device__ __align__(16) __half g_xfh[N_ATOMS * H];
__device__ __align__(16) __half g_aggh[N_ATOMS * H];
__device__ __align__(16) float  g_conf[N_CONF * H];
// transposed fp16 weights: [l][n][k]
__device__ __align__(16) __half g_w1t[NLAYER * H * GPAD];
__device__ __align__(16) __half g_w2t[NLAYER * H * H];
__device__ __align__(16) __half g_cw1t[NLAYER * H * H];
__device__ __align__(16) __half g_cw2t[NLAYER * H * H];
__device__ __align__(16) __half g_iwt[NLAYER * H * H];
__device__ __align__(16) __half g_ow1t[H * H];
__device__ __align__(16) __half g_ow2t[H * H];

// fast stable softplus(x) - log(2)
__device__ __forceinline__ float ssp(float x) {
    float m = fmaxf(x, 0.0f);
    return m + __logf(__expf(x - m) + __expf(-m)) - 0.69314718055994531f;
}
// accurate version (table build only)
__device__ __forceinline__ float ssp_acc(float x) {
    float m = fmaxf(x, 0.0f);
    return m + log1pf(expf(-fabsf(x))) - 0.69314718055994531f;
}
__device__ __forceinline__ uint32_t smem_u32(const void* p) {
    uint32_t a;
    asm("{ .reg .u64 t; cvta.to.shared.u64 t, %1; cvt.u32.u64 %0, t; }" : "=r"(a) : "l"(p));
    return a;
}
__device__ __forceinline__ void ldm_x4(uint32_t& r0, uint32_t& r1, uint32_t& r2, uint32_t& r3,
                                       uint32_t a) {
    asm volatile("ldmatrix.sync.aligned.m8n8.x4.shared.b16 {%0,%1,%2,%3}, [%4];"
                 : "=r"(r0), "=r"(r1), "=r"(r2), "=r"(r3) : "r"(a));
}
__device__ __forceinline__ void ldm_x2(uint32_t& r0, uint32_t& r1, uint32_t a) {
    asm volatile("ldmatrix.sync.aligned.m8n8.x2.shared.b16 {%0,%1}, [%2];"
                 : "=r"(r0), "=r"(r1) : "r"(a));
}
__device__ __forceinline__ void mma16816(float* c, const uint32_t* a, const uint32_t* b) {
    asm volatile(
        "mma.sync.aligned.m16n8k16.row.col.f32.f16.f16.f32 "
        "{%0,%1,%2,%3}, {%4,%5,%6,%7}, {%8,%9}, {%0,%1,%2,%3};"
        : "+f"(c[0]), "+f"(c[1]), "+f"(c[2]), "+f"(c[3])
        : "r"(a[0]), "r"(a[1]), "r"(a[2]), "r"(a[3]), "r"(b[0]), "r"(b[1]));
}
__device__ __forceinline__ uint32_t h2u(float a, float b) {
    __half2 p = __floats2half2_rn(a, b);
    return *(uint32_t*)&p;
}
__device__ __forceinline__ float2 u2f2(uint32_t u) {
    __half2 h = *(__half2*)&u;
    return __half22float2(h);
}

// ---------------- prep: all weight transposes in ONE kernel ----------------
__device__ __forceinline__ void tr1(const float* src, __half* dst, int idx,
                                    int K, int N, int Kpad) {
    int k = idx % Kpad;
    int n = (idx / Kpad) % N;
    int l = idx / (Kpad * N);
    float v = (k < K) ? src[(size_t)l * K * N + (size_t)k * N + n] : 0.0f;
    dst[idx] = __float2half(v);
}
#define S1 (NLAYER * H * GPAD)
#define S2 (NLAYER * H * H)
#define S6 (H * H)
__global__ void prep_weights(const float* mw1, const float* mw2, const float* cw1,
                             const float* cw2, const float* iw,
                             const float* ow1, const float* ow2) {
    int idx = blockIdx.x * blockDim.x + threadIdx.x;
    if (idx < S1) { tr1(mw1, g_w1t, idx, G, H, GPAD); return; }
    idx -= S1;
    if (idx < S2) { tr1(mw2, g_w2t, idx, H, H, H); return; }
    idx -= S2;
    if (idx < S2) { tr1(cw1, g_cw1t, idx, H, H, H); return; }
    idx -= S2;
    if (idx < S2) { tr1(cw2, g_cw2t, idx, H, H, H); return; }
    idx -= S2;
    if (idx < S2) { tr1(iw, g_iwt, idx, H, H, H); return; }
    idx -= S2;
    if (idx < S6) { tr1(ow1, g_ow1t, idx, H, H, H); return; }
    idx -= S6;
    if (idx < S6) { tr1(ow2, g_ow2t, idx, H, H, H); return; }
}

// ---------------- gaussians at table knots ----------------
__global__ void gauss_tab_kernel() {
    int k = blockIdx.x;
    int c = threadIdx.x;
    float d = (float)k * (DMAX / (float)TAB);
    const float delta = 10.0f / 49.0f;
    const float coeff = -0.5f / (delta * delta);
    float t = d - (float)c * delta;
    float v = (c < G) ? expf(coeff * t * t) : 0.0f;
    g_gt[k * GPAD + c] = __float2half(v);
}

// ---------------- table build: T_l(d) = (MLP_l(gauss(d)) + b2) * cutoff(d) ---
// Each CTA owns 256 knots (32 rows per warp). grid = NLAYER * (TAB/256).
#define TS_W1   0
#define TS_W2   18432
#define TS_B1   53248
#define TS_B2   53760
#define TS_TOT  54272
__global__ void __launch_bounds__(256, 2)
tab_kernel(const float* __restrict__ mb1, const float* __restrict__ mb2) {
    extern __shared__ char sm[];
    __half* sW1 = (__half*)(sm + TS_W1);
    __half* sW2 = (__half*)(sm + TS_W2);
    float* sB1 = (float*)(sm + TS_B1);
    float* sB2 = (float*)(sm + TS_B2);

    const int tid = threadIdx.x, w = tid >> 5, lane = tid & 31;
    const int g = lane >> 2, t = lane & 3;
    const int l = blockIdx.x >> 5;           // layer (32 blocks per layer)
    const int kb = (blockIdx.x & 31) * 256;  // knot base: 256 knots per CTA

    {
        const uint4* w1src = (const uint4*)(g_w1t + (size_t)l * H * GPAD);
        for (int i = tid; i < 1024; i += 256) {
            int r = i >> 3, c = i & 7;
            *(uint4*)(sW1 + r * 72 + c * 8) = w1src[i];
        }
        const uint4* w2src = (const uint4*)(g_w2t + (size_t)l * H * H);
        for (int i = tid; i < 2048; i += 256) {
            int r = i >> 4, c = i & 15;
            *(uint4*)(sW2 + r * 136 + c * 8) = w2src[i];
        }
        if (tid < 128) {
            sB1[tid] = mb1[l * H + tid];
            sB2[tid] = mb2[l * H + tid];
        }
    }
    __syncthreads();

    // A fragments of gauss rows, direct from global (rows kb .. kb+255, in range)
    uint32_t A1[2][4][4];
#pragma unroll
    for (int i = 0; i < 2; i++)
#pragma unroll
        for (int ks = 0; ks < 4; ks++)
#pragma unroll
            for (int r = 0; r < 4; r++) {
                int row = kb + 32 * w + 16 * i + g + 8 * (r & 1);
                int col = 16 * ks + 2 * t + 8 * (r >> 1);
                A1[i][ks][r] = *(const uint32_t*)(g_gt + (size_t)row * GPAD + col);
            }

    const int bn = lane & 7;
    const int bk = ((lane >> 3) & 1) * 8;

    uint32_t A2[2][8][4];
#pragma unroll
    for (int q = 0; q < 4; q++) {
        float C1[2][4][4];
#pragma unroll
        for (int i = 0; i < 2; i++)
#pragma unroll
            for (int n = 0; n < 4; n++)
#pragma unroll
                for (int j = 0; j < 4; j++) C1[i][n][j] = 0.0f;
#pragma unroll
        for (int ks = 0; ks < 4; ks++) {
#pragma unroll
            for (int j = 0; j < 4; j++) {
                int nt = q * 4 + j;
                uint32_t B[2];
                ldm_x2(B[0], B[1], smem_u32(sW1 + (nt * 8 + bn) * 72 + ks * 16 + bk));
                mma16816(C1[0][j], A1[0][ks], B);
                mma16816(C1[1][j], A1[1][ks], B);
            }
        }
#pragma unroll
        for (int j = 0; j < 4; j++) {
            int nt = q * 4 + j;
            int col = nt * 8 + 2 * t;
            float b0 = sB1[col], b1v = sB1[col + 1];
#pragma unroll
            for (int i = 0; i < 2; i++) {
                float u0 = ssp_acc(C1[i][j][0] + b0), u1 = ssp_acc(C1[i][j][1] + b1v);
                float u2 = ssp_acc(C1[i][j][2] + b0), u3 = ssp_acc(C1[i][j][3] + b1v);
                A2[i][nt >> 1][(nt & 1) * 2 + 0] = h2u(u0, u1);
                A2[i][nt >> 1][(nt & 1) * 2 + 1] = h2u(u2, u3);
            }
        }
    }

    float cut[2][2];
#pragma unroll
    for (int i = 0; i < 2; i++)
#pragma unroll
        for (int j = 0; j < 2; j++) {
            int rowk = kb + 32 * w + 16 * i + 8 * j + g;
            float dd = (float)rowk * (DMAX / (float)TAB);
            cut[i][j] = 0.5f * (cosf(dd * 0.31415926535f) + 1.0f);
        }

#pragma unroll
    for (int q = 0; q < 4; q++) {
        float C2[2][4][4];
#pragma unroll
        for (int i = 0; i < 2; i++)
#pragma unroll
            for (int n = 0; n < 4; n++)
#pragma unroll
                for (int j = 0; j < 4; j++) C2[i][n][j] = 0.0f;
#pragma unroll
        for (int ks = 0; ks < 8; ks++) {
#pragma unroll
            for (int j = 0; j < 4; j++) {
                int nt = q * 4 + j;
                uint32_t B[2];
                ldm_x2(B[0], B[1], smem_u32(sW2 + (nt * 8 + bn) * 136 + ks * 16 + bk));
                mma16816(C2[0][j], A2[0][ks], B);
                mma16816(C2[1][j], A2[1][ks], B);
            }
        }
#pragma unroll
        for (int j = 0; j < 4; j++) {
            int nt = q * 4 + j;
            int col = nt * 8 + 2 * t;
            float b0 = sB2[col], b1v = sB2[col + 1];
#pragma unroll
            for (int i = 0; i < 2; i++) {
                int rowk = kb + 32 * w + 16 * i + g;
                float v0 = (C2[i][j][0] + b0) * cut[i][0];
                float v1 = (C2[i][j][1] + b1v) * cut[i][0];
                float v2 = (C2[i][j][2] + b0) * cut[i][1];
                float v3 = (C2[i][j][3] + b1v) * cut[i][1];
                __half* base = g_wtab + (size_t)l * TAB * H;
                *(uint32_t*)(base + (size_t)rowk * H + col) = h2u(v0, v1);
                *(uint32_t*)(base + (size_t)(rowk + 8) * H + col) = h2u(v2, v3);
            }
        }
    }
}

// ---------------- edge metadata: d -> (idx, frac), row ----------------
__global__ void epre_kernel(const float* __restrict__ pos, const int* __restrict__ ei) {
    int e = blockIdx.x * blockDim.x + threadIdx.x;
    if (e >= EDGES) return;
    int r = ei[e], c = ei[EDGES + e];
    float dx = pos[3 * r + 0] - pos[3 * c + 0];
    float dy = pos[3 * r + 1] - pos[3 * c + 1];
    float dz = pos[3 * r + 2] - pos[3 * c + 2];
    float d = sqrtf(dx * dx + dy * dy + dz * dz);
    float x = d * ((float)TAB / DMAX);
    int idx = (int)x;
    if (idx > TAB - 2) idx = TAB - 2;
    if (idx < 0) idx = 0;
    float frac = x - (float)idx;
    int fq = (int)(frac * 8192.0f);
    if (fq > 8191) fq = 8191;
    if (fq < 0) fq = 0;
    g_em[e] = (uint32_t)idx | ((uint32_t)(r & (APC - 1)) << 13) | ((uint32_t)fq << 19);
}

__global__ void hinit_kernel(const int* __restrict__ z, const float* __restrict__ emb) {
    int idx = blockIdx.x * blockDim.x + threadIdx.x;
    if (idx >= N_ATOMS * H) return;
    float v = emb[z[idx >> 7] * H + (idx & 127)];
    g_h[idx] = v;
    g_hhf[idx] = __float2half(v);
}

// ---------------- xf = h @ cf_w1[0] (layer 0 only) ----------------
__global__ void __launch_bounds__(256, 1)
xf_kernel(int l) {
    extern __shared__ char sm[];
    __half* sA = (__half*)sm;
    __half* sW = (__half*)(sm + 34816);
    const int tid = threadIdx.x, w = tid >> 5, lane = tid & 31;
    const int g = lane >> 2, t = lane & 3;
    const int tile = blockIdx.x;

    {
        const uint4* asrc = (const uint4*)(g_hhf + (size_t)tile * 128 * H);
        const uint4* wsrc = (const uint4*)(g_cw1t + (size_t)l * H * H);
        for (int i = tid; i < 2048; i += 256) {
            int r = i >> 4, c = i & 15;
            *(uint4*)(sA + r * 136 + c * 8) = asrc[i];
            *(uint4*)(sW + r * 136 + c * 8) = wsrc[i];
        }
    }
    __syncthreads();

    float C[16][4];
#pragma unroll
    for (int nt = 0; nt < 16; nt++)
#pragma unroll
        for (int j = 0; j < 4; j++) C[nt][j] = 0.0f;

    const int ar = 16 * w + (lane & 15);
    const int ac = (lane >> 4) << 3;
    const int bn = lane & 7;
    const int bk = ((lane >> 3) & 1) * 8;
#pragma unroll
    for (int ks = 0; ks < 8; ks++) {
        uint32_t A[4];
        ldm_x4(A[0], A[1], A[2], A[3], smem_u32(sA + ar * 136 + ks * 16 + ac));
#pragma unroll
        for (int nt = 0; nt < 16; nt++) {
            uint32_t B[2];
            ldm_x2(B[0], B[1], smem_u32(sW + (nt * 8 + bn) * 136 + ks * 16 + bk));
            mma16816(C[nt], A, B);
        }
    }
    const int r0 = tile * 128 + 16 * w + g;
#pragma unroll
    for (int nt = 0; nt < 16; nt++) {
        int col = nt * 8 + 2 * t;
        *(uint32_t*)(g_xfh + (size_t)r0 * H + col) = h2u(C[nt][0], C[nt][1]);
        *(uint32_t*)(g_xfh + (size_t)(r0 + 8) * H + col) = h2u(C[nt][2], C[nt][3]);
    }
}

// ---------------- edge kernel: table-lerp message + aggregate ----------------
__global__ void __launch_bounds__(256)
edge_kernel(int l) {
    __shared__ __half sXF[64 * 136];
    const int tid = threadIdx.x, w = tid >> 5, lane = tid & 31;
    const int tile = blockIdx.x;          // 8 atoms
    const int conf = tile >> 3;

    {
        const uint4* xfsrc = (const uint4*)(g_xfh + (size_t)conf * APC * H);
        for (int i = tid; i < 1024; i += 256) {
            int r = i >> 4, c = i & 15;
            *(uint4*)(sXF + r * 136 + c * 8) = xfsrc[i];
        }
    }
    __syncthreads();
    const int atom = tile * 8 + w;
    const uint32_t mymeta = g_em[atom * DEG + lane];

    const __half* Tl = g_wtab + (size_t)l * TAB * H;
    float a0 = 0.f, a1 = 0.f, a2 = 0.f, a3 = 0.f;

#pragma unroll
    for (int e = 0; e < DEG; e++) {
        uint32_t m = __shfl_sync(0xFFFFFFFFu, mymeta, e);
        int idx = m & 8191;
        int row = (m >> 13) & 63;
        float fr = (float)(m >> 19) * (1.0f / 8192.0f);
        const __half* t0p = Tl + (size_t)idx * H + lane * 4;
        uint2 q0 = *(const uint2*)t0p;
        uint2 q1 = *(const uint2*)(t0p + H);
        uint2 xv = *(const uint2*)(sXF + row * 136 + lane * 4);
        float2 t0a = u2f2(q0.x), t0b = u2f2(q0.y);
        float2 t1a = u2f2(q1.x), t1b = u2f2(q1.y);
        float2 xa = u2f2(xv.x), xb = u2f2(xv.y);
        float w0 = fmaf(fr, t1a.x - t0a.x, t0a.x);
        float w1 = fmaf(fr, t1a.y - t0a.y, t0a.y);
        float w2 = fmaf(fr, t1b.x - t0b.x, t0b.x);
        float w3 = fmaf(fr, t1b.y - t0b.y, t0b.y);
        a0 = fmaf(xa.x, w0, a0);
        a1 = fmaf(xa.y, w1, a1);
        a2 = fmaf(xb.x, w2, a2);
        a3 = fmaf(xb.y, w3, a3);
    }
    *(uint2*)(g_aggh + (size_t)atom * H + lane * 4) =
        make_uint2(h2u(a0, a1), h2u(a2, a3));
}

// ---------------- node update (+ fused next-layer xf) ------------------------
__global__ void __launch_bounds__(256, 1)
node_kernel(const float* __restrict__ cb2, const float* __restrict__ ib, int l, int do_xf) {
    extern __shared__ char sm[];
    __half* sA = (__half*)sm;
    __half* sW = (__half*)(sm + 34816);
    float* sB1 = (float*)(sm + 69632);
    float* sB2 = (float*)(sm + 70144);
    const int tid = threadIdx.x, w = tid >> 5, lane = tid & 31;
    const int g = lane >> 2, t = lane & 3;
    const int tile = blockIdx.x;

    {
        const uint4* asrc = (const uint4*)(g_aggh + (size_t)tile * 128 * H);
        const uint4* wsrc = (const uint4*)(g_cw2t + (size_t)l * H * H);
        for (int i = tid; i < 2048; i += 256) {
            int r = i >> 4, c = i & 15;
            *(uint4*)(sA + r * 136 + c * 8) = asrc[i];
            *(uint4*)(sW + r * 136 + c * 8) = wsrc[i];
        }
        if (tid < 128) {
            sB1[tid] = cb2[l * H + tid];
            sB2[tid] = ib[l * H + tid];
        }
    }
    __syncthreads();

    const int bn = lane & 7;
    const int bk = ((lane >> 3) & 1) * 8;
    const int ac = (lane >> 4) << 3;
    const int ar = 16 * w + (lane & 15);

    uint32_t A2[8][4];
    {
        float C1[16][4];
#pragma unroll
        for (int nt = 0; nt < 16; nt++)
#pragma unroll
            for (int j = 0; j < 4; j++) C1[nt][j] = 0.0f;
#pragma unroll
        for (int ks = 0; ks < 8; ks++) {
            uint32_t A[4];
            ldm_x4(A[0], A[1], A[2], A[3], smem_u32(sA + ar * 136 + ks * 16 + ac));
#pragma unroll
            for (int nt = 0; nt < 16; nt++) {
                uint32_t B[2];
                ldm_x2(B[0], B[1], smem_u32(sW + (nt * 8 + bn) * 136 + ks * 16 + bk));
                mma16816(C1[nt], A, B);
            }
        }
#pragma unroll
        for (int nt = 0; nt < 16; nt++) {
            int col = nt * 8 + 2 * t;
            float b0 = sB1[col], b1v = sB1[col + 1];
            float u0 = ssp(C1[nt][0] + b0), u1 = ssp(C1[nt][1] + b1v);
            float u2 = ssp(C1[nt][2] + b0), u3 = ssp(C1[nt][3] + b1v);
            A2[nt >> 1][(nt & 1) * 2 + 0] = h2u(u0, u1);
            A2[nt >> 1][(nt & 1) * 2 + 1] = h2u(u2, u3);
        }
    }
    __syncthreads();
    {
        const uint4* wsrc = (const uint4*)(g_iwt + (size_t)l * H * H);
        for (int i = tid; i < 2048; i += 256) {
            int r = i >> 4, c = i & 15;
            *(uint4*)(sW + r * 136 + c * 8) = wsrc[i];
        }
    }
    __syncthreads();

    float C2[16][4];
#pragma unroll
    for (int nt = 0; nt < 16; nt++)
#pragma unroll
        for (int j = 0; j < 4; j++) C2[nt][j] = 0.0f;
#pragma unroll
    for (int ks = 0; ks < 8; ks++) {
#pragma unroll
        for (int nt = 0; nt < 16; nt++) {
            uint32_t B[2];
            ldm_x2(B[0], B[1], smem_u32(sW + (nt * 8 + bn) * 136 + ks * 16 + bk));
            mma16816(C2[nt], A2[ks], B);
        }
    }

    uint32_t A3[8][4];
    {
        const int r0 = tile * 128 + 16 * w + g;
#pragma unroll
        for (int nt = 0; nt < 16; nt++) {
            int col = nt * 8 + 2 * t;
            float b0 = sB2[col], b1v = sB2[col + 1];
            float2 h0 = *(float2*)(g_h + (size_t)r0 * H + col);
            float2 h1 = *(float2*)(g_h + (size_t)(r0 + 8) * H + col);
            float n00 = h0.x + C2[nt][0] + b0, n01 = h0.y + C2[nt][1] + b1v;
            float n10 = h1.x + C2[nt][2] + b0, n11 = h1.y + C2[nt][3] + b1v;
            *(float2*)(g_h + (size_t)r0 * H + col) = make_float2(n00, n01);
            *(float2*)(g_h + (size_t)(r0 + 8) * H + col) = make_float2(n10, n11);
            *(uint32_t*)(g_hhf + (size_t)r0 * H + col) = h2u(n00, n01);
            *(uint32_t*)(g_hhf + (size_t)(r0 + 8) * H + col) = h2u(n10, n11);
            A3[nt >> 1][(nt & 1) * 2 + 0] = h2u(n00, n01);
            A3[nt >> 1][(nt & 1) * 2 + 1] = h2u(n10, n11);
        }
    }

    if (!do_xf) return;
    __syncthreads();
    {
        const uint4* wsrc = (const uint4*)(g_cw1t + (size_t)(l + 1) * H * H);
        for (int i = tid; i < 2048; i += 256) {
            int r = i >> 4, c = i & 15;
            *(uint4*)(sW + r * 136 + c * 8) = wsrc[i];
        }
    }
    __syncthreads();

    float C3[16][4];
#pragma unroll
    for (int nt = 0; nt < 16; nt++)
#pragma unroll
        for (int j = 0; j < 4; j++) C3[nt][j] = 0.0f;
#pragma unroll
    for (int ks = 0; ks < 8; ks++) {
#pragma unroll
        for (int nt = 0; nt < 16; nt++) {
            uint32_t B[2];
            ldm_x2(B[0], B[1], smem_u32(sW + (nt * 8 + bn) * 136 + ks * 16 + bk));
            mma16816(C3[nt], A3[ks], B);
        }
    }
    {
        const int r0 = tile * 128 + 16 * w + g;
#pragma unroll
        for (int nt = 0; nt < 16; nt++) {
            int col = nt * 8 + 2 * t;
            *(uint32_t*)(g_xfh + (size_t)r0 * H + col) = h2u(C3[nt][0], C3[nt][1]);
            *(uint32_t*)(g_xfh + (size_t)(r0 + 8) * H + col) = h2u(C3[nt][2], C3[nt][3]);
        }
    }
}

// ---------------- readout ----------------
__global__ void __launch_bounds__(256, 1)
readout_kernel(const float* __restrict__ ob1, const float* __restrict__ ob2) {
    extern __shared__ char sm[];
    __half* sA = (__half*)sm;
    __half* sW = (__half*)(sm + 34816);
    float* sRed = (float*)(sm + 69632);
    float* sB1 = (float*)(sm + 73728);
    float* sB2 = (float*)(sm + 74240);
    const int tid = threadIdx.x, w = tid >> 5, lane = tid & 31;
    const int g = lane >> 2, t = lane & 3;
    const int tile = blockIdx.x;

    {
        const uint4* asrc = (const uint4*)(g_hhf + (size_t)tile * 128 * H);
        const uint4* wsrc = (const uint4*)g_ow1t;
        for (int i = tid; i < 2048; i += 256) {
            int r = i >> 4, c = i & 15;
            *(uint4*)(sA + r * 136 + c * 8) = asrc[i];
            *(uint4*)(sW + r * 136 + c * 8) = wsrc[i];
        }
        if (tid < 128) {
            sB1[tid] = ob1[tid];
            sB2[tid] = ob2[tid];
        }
    }
    __syncthreads();

    const int bn = lane & 7;
    const int bk = ((lane >> 3) & 1) * 8;
    const int ac = (lane >> 4) << 3;
    const int ar = 16 * w + (lane & 15);

    uint32_t A2[8][4];
    {
        float C1[16][4];
#pragma unroll
        for (int nt = 0; nt < 16; nt++)
#pragma unroll
            for (int j = 0; j < 4; j++) C1[nt][j] = 0.0f;
#pragma unroll
        for (int ks = 0; ks < 8; ks++) {
            uint32_t A[4];
            ldm_x4(A[0], A[1], A[2], A[3], smem_u32(sA + ar * 136 + ks * 16 + ac));
#pragma unroll
            for (int nt = 0; nt < 16; nt++) {
                uint32_t B[2];
                ldm_x2(B[0], B[1], smem_u32(sW + (nt * 8 + bn) * 136 + ks * 16 + bk));
                mma16816(C1[nt], A, B);
            }
        }
#pragma unroll
        for (int nt = 0; nt < 16; nt++) {
            int col = nt * 8 + 2 * t;
            float b0 = sB1[col], b1v = sB1[col + 1];
            float u0 = ssp(C1[nt][0] + b0), u1 = ssp(C1[nt][1] + b1v);
            float u2 = ssp(C1[nt][2] + b0), u3 = ssp(C1[nt][3] + b1v);
            A2[nt >> 1][(nt & 1) * 2 + 0] = h2u(u0, u1);
            A2[nt >> 1][(nt & 1) * 2 + 1] = h2u(u2, u3);
        }
    }
    __syncthreads();
    {
        const uint4* wsrc = (const uint4*)g_ow2t;
        for (int i = tid; i < 2048; i += 256) {
            int r = i >> 4, c = i & 15;
            *(uint4*)(sW + r * 136 + c * 8) = wsrc[i];
        }
    }
    __syncthreads();

    float C2[16][4];
#pragma unroll
    for (int nt = 0; nt < 16; nt++)
#pragma unroll
        for (int j = 0; j < 4; j++) C2[nt][j] = 0.0f;
#pragma unroll
    for (int ks = 0; ks < 8; ks++) {
#pragma unroll
        for (int nt = 0; nt < 16; nt++) {
            uint32_t B[2];
            ldm_x2(B[0], B[1], smem_u32(sW + (nt * 8 + bn) * 136 + ks * 16 + bk));
            mma16816(C2[nt], A2[ks], B);
        }
    }
    {
#pragma unroll
        for (int nt = 0; nt < 16; nt++) {
            int col = nt * 8 + 2 * t;
            float b0 = sB2[col], b1v = sB2[col + 1];
            float s0 = (C2[nt][0] + b0) + (C2[nt][2] + b0);
            float s1 = (C2[nt][1] + b1v) + (C2[nt][3] + b1v);
            s0 += __shfl_xor_sync(0xFFFFFFFFu, s0, 4);
            s0 += __shfl_xor_sync(0xFFFFFFFFu, s0, 8);
            s0 += __shfl_xor_sync(0xFFFFFFFFu, s0, 16);
            s1 += __shfl_xor_sync(0xFFFFFFFFu, s1, 4);
            s1 += __shfl_xor_sync(0xFFFFFFFFu, s1, 8);
            s1 += __shfl_xor_sync(0xFFFFFFFFu, s1, 16);
            if (lane < 4) {
                sRed[w * 128 + col] = s0;
                sRed[w * 128 + col + 1] = s1;
            }
        }
    }
    __syncthreads();
    for (int i = tid; i < 256; i += 256) {
        int p = i >> 7, c = i & 127;
        float v = sRed[(4 * p + 0) * 128 + c] + sRed[(4 * p + 1) * 128 + c]
                + sRed[(4 * p + 2) * 128 + c] + sRed[(4 * p + 3) * 128 + c];
        g_conf[(size_t)(2 * tile + p) * H + c] = v;
    }
}

// ---------------- final: mol sum + head MLP ----------------
__global__ void __launch_bounds__(256, 1)
final_kernel(const float* __restrict__ hw1, const float* __restrict__ hb1,
             const float* __restrict__ hw2, const float* __restrict__ hb2,
             float* __restrict__ out) {
    extern __shared__ char sm[];
    float* s_mol = (float*)sm;
    float* s_hid = (float*)sm + 8192;
    const int tid = threadIdx.x;
    for (int idx = tid; idx < N_MOL * H; idx += 256) {
        int m = idx >> 7, c = idx & 127;
        s_mol[idx] = g_conf[(m * 4 + 0) * H + c] + g_conf[(m * 4 + 1) * H + c]
                   + g_conf[(m * 4 + 2) * H + c] + g_conf[(m * 4 + 3) * H + c];
    }
    __syncthreads();
    for (int idx = tid; idx < N_MOL * 64; idx += 256) {
        int m = idx >> 6, j = idx & 63;
        float acc = hb1[j];
#pragma unroll 4
        for (int k = 0; k < H; k++) acc += s_mol[m * H + k] * hw1[k * 64 + j];
        s_hid[idx] = ssp(acc);
    }
    __syncthreads();
    if (tid < N_MOL) {
        float acc = hb2[0];
#pragma unroll 4
        for (int j = 0; j < 64; j++) acc += s_hid[tid * 64 + j] * hw2[j];
        out[tid] = acc;
    }
}

// ---------------- launch ----------------
extern "C" void kernel_launch(void* const* d_in, const int* in_sizes, int n_in,
                              void* d_out, int out_size) {
    const int*   z   = (const int*)d_in[0];
    const float* pos = (const float*)d_in[1];
    const int*   ei  = (const int*)d_in[2];
    const float* emb = (const float*)d_in[5];
    const float* mw1 = (const float*)d_in[6];
    const float* mb1 = (const float*)d_in[7];
    const float* mw2 = (const float*)d_in[8];
    const float* mb2 = (const float*)d_in[9];
    const float* cw1 = (const float*)d_in[10];
    const float* cw2 = (const float*)d_in[11];
    const float* cb2 = (const float*)d_in[12];
    const float* iw  = (const float*)d_in[13];
    const float* ib  = (const float*)d_in[14];
    const float* ow1 = (const float*)d_in[15];
    const float* ob1 = (const float*)d_in[16];
    const float* ow2 = (const float*)d_in[17];
    const float* ob2 = (const float*)d_in[18];
    const float* hw1 = (const float*)d_in[19];
    const float* hb1 = (const float*)d_in[20];
    const float* hw2 = (const float*)d_in[21];
    const float* hb2 = (const float*)d_in[22];
    float* out = (float*)d_out;

    cudaFuncSetAttribute(tab_kernel, cudaFuncAttributeMaxDynamicSharedMemorySize, TS_TOT);
    cudaFuncSetAttribute(xf_kernel, cudaFuncAttributeMaxDynamicSharedMemorySize, 69632);
    cudaFuncSetAttribute(node_kernel, cudaFuncAttributeMaxDynamicSharedMemorySize, 70656);
    cudaFuncSetAttribute(readout_kernel, cudaFuncAttributeMaxDynamicSharedMemorySize, 74752);
    cudaFuncSetAttribute(final_kernel, cudaFuncAttributeMaxDynamicSharedMemorySize, 49152);

    const int WTOT = S1 + 4 * S2 + 2 * S6;
    prep_weights<<<(WTOT + 255) / 256, 256>>>(mw1, mw2, cw1, cw2, iw, ow1, ow2);
    gauss_tab_kernel<<<TAB, 64>>>();
    tab_kernel<<<NLAYER * (TAB / 256), 256, TS_TOT>>>(mb1, mb2);
    epre_kernel<<<EDGES / 256, 256>>>(pos, ei);
    hinit_kernel<<<(N_ATOMS * H) / 256, 256>>>(z, emb);

    xf_kernel<<<N_ATOMS / 128, 256, 69632>>>(0);
    for (int l = 0; l < NLAYER; l++) {
        edge_kernel<<<EDGES / 256, 256>>>(l);
        node_kernel<<<N_ATOMS / 128, 256, 70656>>>(cb2, ib, l, l < NLAYER - 1);
    }
    readout_kernel<<<N_ATOMS / 128, 256, 74752>>>(ob1, ob2);
    final_kernel<<<1, 256, 49152>>>(hw1, hb1, hw2, hb2, out);
}

// round 14
// speedup vs baseline: 20.5114x; 1.0614x over previous
#include <cuda_runtime.h>
#include <cuda_fp16.h>
#include <math.h>
#include <stdint.h>

#define N_ATOMS 16384
#define APC     64
#define N_CONF  256
#define N_MOL   64
#define DEG     32
#define EDGES   (N_ATOMS * DEG)     // 524288
#define H       128
#define G       50
#define GPAD    64
#define NLAYER  6
#define TAB     8192
#define DMAX    8.66025404f         // 5*sqrt(3)

// ---------------- device scratch ----------------
__device__ __align__(16) __half g_gt[TAB * GPAD];
__device__ __align__(16) __half g_wtab[NLAYER * TAB * H];
__device__ __align__(16) uint32_t g_em[EDGES];
__device__ __align__(16) float  g_h[N_ATOMS * H];
__device__ __align__(16) __half g_hhf[N_ATOMS * H];
__device__ __align__(16) __half g_xfh[N_ATOMS * H];
__device__ __align__(16) __half g_aggh[N_ATOMS * H];
__device__ __align__(16) float  g_conf[N_CONF * H];
__device__ __align__(16) __half g_w1t[NLAYER * H * GPAD];
__device__ __align__(16) __half g_w2t[NLAYER * H * H];
__device__ __align__(16) __half g_cw1t[NLAYER * H * H];
__device__ __align__(16) __half g_cw2t[NLAYER * H * H];
__device__ __align__(16) __half g_iwt[NLAYER * H * H];
__device__ __align__(16) __half g_ow1t[H * H];
__device__ __align__(16) __half g_ow2t[H * H];

__device__ __forceinline__ float ssp(float x) {
    float m = fmaxf(x, 0.0f);
    return m + __logf(__expf(x - m) + __expf(-m)) - 0.69314718055994531f;
}
__device__ __forceinline__ float ssp_acc(float x) {
    float m = fmaxf(x, 0.0f);
    return m + log1pf(expf(-fabsf(x))) - 0.69314718055994531f;
}
__device__ __forceinline__ uint32_t smem_u32(const void* p) {
    uint32_t a;
    asm("{ .reg .u64 t; cvta.to.shared.u64 t, %1; cvt.u32.u64 %0, t; }" : "=r"(a) : "l"(p));
    return a;
}
__device__ __forceinline__ void ldm_x4(uint32_t& r0, uint32_t& r1, uint32_t& r2, uint32_t& r3,
                                       uint32_t a) {
    asm volatile("ldmatrix.sync.aligned.m8n8.x4.shared.b16 {%0,%1,%2,%3}, [%4];"
                 : "=r"(r0), "=r"(r1), "=r"(r2), "=r"(r3) : "r"(a));
}
__device__ __forceinline__ void ldm_x2(uint32_t& r0, uint32_t& r1, uint32_t a) {
    asm volatile("ldmatrix.sync.aligned.m8n8.x2.shared.b16 {%0,%1}, [%2];"
                 : "=r"(r0), "=r"(r1) : "r"(a));
}
__device__ __forceinline__ void mma16816(float* c, const uint32_t* a, const uint32_t* b) {
    asm volatile(
        "mma.sync.aligned.m16n8k16.row.col.f32.f16.f16.f32 "
        "{%0,%1,%2,%3}, {%4,%5,%6,%7}, {%8,%9}, {%0,%1,%2,%3};"
        : "+f"(c[0]), "+f"(c[1]), "+f"(c[2]), "+f"(c[3])
        : "r"(a[0]), "r"(a[1]), "r"(a[2]), "r"(a[3]), "r"(b[0]), "r"(b[1]));
}
__device__ __forceinline__ uint32_t h2u(float a, float b) {
    __half2 p = __floats2half2_rn(a, b);
    return *(uint32_t*)&p;
}
__device__ __forceinline__ float2 u2f2(uint32_t u) {
    __half2 h = *(__half2*)&u;
    return __half22float2(h);
}
__device__ __forceinline__ void sts32(uint32_t addr, uint32_t v) {
    asm volatile("st.shared.b32 [%0], %1;" :: "r"(addr), "r"(v));
}

// ---------------- prep: weight transposes ----------------
__device__ __forceinline__ void tr1(const float* src, __half* dst, int idx,
                                    int K, int N, int Kpad) {
    int k = idx % Kpad;
    int n = (idx / Kpad) % N;
    int l = idx / (Kpad * N);
    float v = (k < K) ? src[(size_t)l * K * N + (size_t)k * N + n] : 0.0f;
    dst[idx] = __float2half(v);
}
#define S1 (NLAYER * H * GPAD)
#define S2 (NLAYER * H * H)
#define S6 (H * H)
__global__ void prep_weights(const float* mw1, const float* mw2, const float* cw1,
                             const float* cw2, const float* iw,
                             const float* ow1, const float* ow2) {
    int idx = blockIdx.x * blockDim.x + threadIdx.x;
    if (idx < S1) { tr1(mw1, g_w1t, idx, G, H, GPAD); return; }
    idx -= S1;
    if (idx < S2) { tr1(mw2, g_w2t, idx, H, H, H); return; }
    idx -= S2;
    if (idx < S2) { tr1(cw1, g_cw1t, idx, H, H, H); return; }
    idx -= S2;
    if (idx < S2) { tr1(cw2, g_cw2t, idx, H, H, H); return; }
    idx -= S2;
    if (idx < S2) { tr1(iw, g_iwt, idx, H, H, H); return; }
    idx -= S2;
    if (idx < S6) { tr1(ow1, g_ow1t, idx, H, H, H); return; }
    idx -= S6;
    if (idx < S6) { tr1(ow2, g_ow2t, idx, H, H, H); return; }
}

__global__ void gauss_tab_kernel() {
    int k = blockIdx.x;
    int c = threadIdx.x;
    float d = (float)k * (DMAX / (float)TAB);
    const float delta = 10.0f / 49.0f;
    const float coeff = -0.5f / (delta * delta);
    float t = d - (float)c * delta;
    float v = (c < G) ? expf(coeff * t * t) : 0.0f;
    g_gt[k * GPAD + c] = __float2half(v);
}

// ---------------- table build (verified R13 indexing: 256 knots/CTA) --------
#define TS_W1   0
#define TS_W2   18432
#define TS_B1   53248
#define TS_B2   53760
#define TS_TOT  54272
__global__ void __launch_bounds__(256, 2)
tab_kernel(const float* __restrict__ mb1, const float* __restrict__ mb2) {
    extern __shared__ char sm[];
    __half* sW1 = (__half*)(sm + TS_W1);
    __half* sW2 = (__half*)(sm + TS_W2);
    float* sB1 = (float*)(sm + TS_B1);
    float* sB2 = (float*)(sm + TS_B2);

    const int tid = threadIdx.x, w = tid >> 5, lane = tid & 31;
    const int g = lane >> 2, t = lane & 3;
    const int l = blockIdx.x >> 5;
    const int kb = (blockIdx.x & 31) * 256;

    {
        const uint4* w1src = (const uint4*)(g_w1t + (size_t)l * H * GPAD);
        for (int i = tid; i < 1024; i += 256) {
            int r = i >> 3, c = i & 7;
            *(uint4*)(sW1 + r * 72 + c * 8) = w1src[i];
        }
        const uint4* w2src = (const uint4*)(g_w2t + (size_t)l * H * H);
        for (int i = tid; i < 2048; i += 256) {
            int r = i >> 4, c = i & 15;
            *(uint4*)(sW2 + r * 136 + c * 8) = w2src[i];
        }
        if (tid < 128) {
            sB1[tid] = mb1[l * H + tid];
            sB2[tid] = mb2[l * H + tid];
        }
    }
    __syncthreads();

    uint32_t A1[2][4][4];
#pragma unroll
    for (int i = 0; i < 2; i++)
#pragma unroll
        for (int ks = 0; ks < 4; ks++)
#pragma unroll
            for (int r = 0; r < 4; r++) {
                int row = kb + 32 * w + 16 * i + g + 8 * (r & 1);
                int col = 16 * ks + 2 * t + 8 * (r >> 1);
                A1[i][ks][r] = *(const uint32_t*)(g_gt + (size_t)row * GPAD + col);
            }

    const int bn = lane & 7;
    const int bk = ((lane >> 3) & 1) * 8;

    uint32_t A2[2][8][4];
#pragma unroll
    for (int q = 0; q < 4; q++) {
        float C1[2][4][4];
#pragma unroll
        for (int i = 0; i < 2; i++)
#pragma unroll
            for (int n = 0; n < 4; n++)
#pragma unroll
                for (int j = 0; j < 4; j++) C1[i][n][j] = 0.0f;
#pragma unroll
        for (int ks = 0; ks < 4; ks++) {
#pragma unroll
            for (int j = 0; j < 4; j++) {
                int nt = q * 4 + j;
                uint32_t B[2];
                ldm_x2(B[0], B[1], smem_u32(sW1 + (nt * 8 + bn) * 72 + ks * 16 + bk));
                mma16816(C1[0][j], A1[0][ks], B);
                mma16816(C1[1][j], A1[1][ks], B);
            }
        }
#pragma unroll
        for (int j = 0; j < 4; j++) {
            int nt = q * 4 + j;
            int col = nt * 8 + 2 * t;
            float b0 = sB1[col], b1v = sB1[col + 1];
#pragma unroll
            for (int i = 0; i < 2; i++) {
                float u0 = ssp_acc(C1[i][j][0] + b0), u1 = ssp_acc(C1[i][j][1] + b1v);
                float u2 = ssp_acc(C1[i][j][2] + b0), u3 = ssp_acc(C1[i][j][3] + b1v);
                A2[i][nt >> 1][(nt & 1) * 2 + 0] = h2u(u0, u1);
                A2[i][nt >> 1][(nt & 1) * 2 + 1] = h2u(u2, u3);
            }
        }
    }

    float cut[2][2];
#pragma unroll
    for (int i = 0; i < 2; i++)
#pragma unroll
        for (int j = 0; j < 2; j++) {
            int rowk = kb + 32 * w + 16 * i + 8 * j + g;
            float dd = (float)rowk * (DMAX / (float)TAB);
            cut[i][j] = 0.5f * (cosf(dd * 0.31415926535f) + 1.0f);
        }

#pragma unroll
    for (int q = 0; q < 4; q++) {
        float C2[2][4][4];
#pragma unroll
        for (int i = 0; i < 2; i++)
#pragma unroll
            for (int n = 0; n < 4; n++)
#pragma unroll
                for (int j = 0; j < 4; j++) C2[i][n][j] = 0.0f;
#pragma unroll
        for (int ks = 0; ks < 8; ks++) {
#pragma unroll
            for (int j = 0; j < 4; j++) {
                int nt = q * 4 + j;
                uint32_t B[2];
                ldm_x2(B[0], B[1], smem_u32(sW2 + (nt * 8 + bn) * 136 + ks * 16 + bk));
                mma16816(C2[0][j], A2[0][ks], B);
                mma16816(C2[1][j], A2[1][ks], B);
            }
        }
#pragma unroll
        for (int j = 0; j < 4; j++) {
            int nt = q * 4 + j;
            int col = nt * 8 + 2 * t;
            float b0 = sB2[col], b1v = sB2[col + 1];
#pragma unroll
            for (int i = 0; i < 2; i++) {
                int rowk = kb + 32 * w + 16 * i + g;
                float v0 = (C2[i][j][0] + b0) * cut[i][0];
                float v1 = (C2[i][j][1] + b1v) * cut[i][0];
                float v2 = (C2[i][j][2] + b0) * cut[i][1];
                float v3 = (C2[i][j][3] + b1v) * cut[i][1];
                __half* base = g_wtab + (size_t)l * TAB * H;
                *(uint32_t*)(base + (size_t)rowk * H + col) = h2u(v0, v1);
                *(uint32_t*)(base + (size_t)(rowk + 8) * H + col) = h2u(v2, v3);
            }
        }
    }
}

// ---------------- edge metadata ----------------
__global__ void epre_kernel(const float* __restrict__ pos, const int* __restrict__ ei) {
    int e = blockIdx.x * blockDim.x + threadIdx.x;
    if (e >= EDGES) return;
    int r = ei[e], c = ei[EDGES + e];
    float dx = pos[3 * r + 0] - pos[3 * c + 0];
    float dy = pos[3 * r + 1] - pos[3 * c + 1];
    float dz = pos[3 * r + 2] - pos[3 * c + 2];
    float d = sqrtf(dx * dx + dy * dy + dz * dz);
    float x = d * ((float)TAB / DMAX);
    int idx = (int)x;
    if (idx > TAB - 2) idx = TAB - 2;
    if (idx < 0) idx = 0;
    float frac = x - (float)idx;
    int fq = (int)(frac * 8192.0f);
    if (fq > 8191) fq = 8191;
    if (fq < 0) fq = 0;
    g_em[e] = (uint32_t)idx | ((uint32_t)(r & (APC - 1)) << 13) | ((uint32_t)fq << 19);
}

__global__ void hinit_kernel(const int* __restrict__ z, const float* __restrict__ emb) {
    int idx = blockIdx.x * blockDim.x + threadIdx.x;
    if (idx >= N_ATOMS * H) return;
    float v = emb[z[idx >> 7] * H + (idx & 127)];
    g_h[idx] = v;
    g_hhf[idx] = __float2half(v);
}

// ---------------- xf (layer 0): 512 threads, N-halves ----------------
__global__ void __launch_bounds__(512, 1)
xf_kernel(int l) {
    extern __shared__ char sm[];
    __half* sA = (__half*)sm;
    __half* sW = (__half*)(sm + 34816);
    const int tid = threadIdx.x, w = tid >> 5, lane = tid & 31;
    const int wp = w >> 1, wh = w & 1;
    const int g = lane >> 2, t = lane & 3;
    const int tile = blockIdx.x;

    {
        const uint4* asrc = (const uint4*)(g_hhf + (size_t)tile * 128 * H);
        const uint4* wsrc = (const uint4*)(g_cw1t + (size_t)l * H * H);
        for (int i = tid; i < 2048; i += 512) {
            int r = i >> 4, c = i & 15;
            *(uint4*)(sA + r * 136 + c * 8) = asrc[i];
            *(uint4*)(sW + r * 136 + c * 8) = wsrc[i];
        }
    }
    __syncthreads();

    const int ar = 16 * wp + (lane & 15);
    const int ac = (lane >> 4) << 3;
    const int bn = lane & 7;
    const int bk = ((lane >> 3) & 1) * 8;
    const int ntb = wh * 8;

    float C[8][4];
#pragma unroll
    for (int j = 0; j < 8; j++)
#pragma unroll
        for (int q = 0; q < 4; q++) C[j][q] = 0.0f;
#pragma unroll
    for (int ks = 0; ks < 8; ks++) {
        uint32_t A[4];
        ldm_x4(A[0], A[1], A[2], A[3], smem_u32(sA + ar * 136 + ks * 16 + ac));
#pragma unroll
        for (int j = 0; j < 8; j++) {
            uint32_t B[2];
            ldm_x2(B[0], B[1], smem_u32(sW + ((ntb + j) * 8 + bn) * 136 + ks * 16 + bk));
            mma16816(C[j], A, B);
        }
    }
    const int r0 = tile * 128 + 16 * wp + g;
#pragma unroll
    for (int j = 0; j < 8; j++) {
        int col = (ntb + j) * 8 + 2 * t;
        *(uint32_t*)(g_xfh + (size_t)r0 * H + col) = h2u(C[j][0], C[j][1]);
        *(uint32_t*)(g_xfh + (size_t)(r0 + 8) * H + col) = h2u(C[j][2], C[j][3]);
    }
}

// ---------------- edge kernel: table-lerp (unchanged from R13) --------------
__global__ void __launch_bounds__(256)
edge_kernel(int l) {
    __shared__ __half sXF[64 * 136];
    const int tid = threadIdx.x, w = tid >> 5, lane = tid & 31;
    const int tile = blockIdx.x;
    const int conf = tile >> 3;

    {
        const uint4* xfsrc = (const uint4*)(g_xfh + (size_t)conf * APC * H);
        for (int i = tid; i < 1024; i += 256) {
            int r = i >> 4, c = i & 15;
            *(uint4*)(sXF + r * 136 + c * 8) = xfsrc[i];
        }
    }
    __syncthreads();
    const int atom = tile * 8 + w;
    const uint32_t mymeta = g_em[atom * DEG + lane];

    const __half* Tl = g_wtab + (size_t)l * TAB * H;
    float a0 = 0.f, a1 = 0.f, a2 = 0.f, a3 = 0.f;

#pragma unroll
    for (int e = 0; e < DEG; e++) {
        uint32_t m = __shfl_sync(0xFFFFFFFFu, mymeta, e);
        int idx = m & 8191;
        int row = (m >> 13) & 63;
        float fr = (float)(m >> 19) * (1.0f / 8192.0f);
        const __half* t0p = Tl + (size_t)idx * H + lane * 4;
        uint2 q0 = *(const uint2*)t0p;
        uint2 q1 = *(const uint2*)(t0p + H);
        uint2 xv = *(const uint2*)(sXF + row * 136 + lane * 4);
        float2 t0a = u2f2(q0.x), t0b = u2f2(q0.y);
        float2 t1a = u2f2(q1.x), t1b = u2f2(q1.y);
        float2 xa = u2f2(xv.x), xb = u2f2(xv.y);
        float w0 = fmaf(fr, t1a.x - t0a.x, t0a.x);
        float w1 = fmaf(fr, t1a.y - t0a.y, t0a.y);
        float w2 = fmaf(fr, t1b.x - t0b.x, t0b.x);
        float w3 = fmaf(fr, t1b.y - t0b.y, t0b.y);
        a0 = fmaf(xa.x, w0, a0);
        a1 = fmaf(xa.y, w1, a1);
        a2 = fmaf(xb.x, w2, a2);
        a3 = fmaf(xb.y, w3, a3);
    }
    *(uint2*)(g_aggh + (size_t)atom * H + lane * 4) =
        make_uint2(h2u(a0, a1), h2u(a2, a3));
}

// ---------------- node: 512 threads, smem-chained 3 GEMMs -------------------
// smem: sA 34816 | sU 34816 | sW1 34816 | sW2 34816 | sW3 34816 | b1 512 | b2 512
#define NS_A   0
#define NS_U   34816
#define NS_W1  69632
#define NS_W2  104448
#define NS_W3  139264
#define NS_B1  174080
#define NS_B2  174592
#define NS_TOT 175104
__global__ void __launch_bounds__(512, 1)
node_kernel(const float* __restrict__ cb2, const float* __restrict__ ib, int l, int do_xf) {
    extern __shared__ char sm[];
    __half* sA = (__half*)(sm + NS_A);
    __half* sU = (__half*)(sm + NS_U);
    __half* sW1 = (__half*)(sm + NS_W1);
    __half* sW2 = (__half*)(sm + NS_W2);
    __half* sW3 = (__half*)(sm + NS_W3);
    float* sB1 = (float*)(sm + NS_B1);
    float* sB2 = (float*)(sm + NS_B2);
    const int tid = threadIdx.x, w = tid >> 5, lane = tid & 31;
    const int wp = w >> 1, wh = w & 1;
    const int g = lane >> 2, t = lane & 3;
    const int tile = blockIdx.x;

    {
        const uint4* asrc = (const uint4*)(g_aggh + (size_t)tile * 128 * H);
        const uint4* w1src = (const uint4*)(g_cw2t + (size_t)l * H * H);
        const uint4* w2src = (const uint4*)(g_iwt + (size_t)l * H * H);
        for (int i = tid; i < 2048; i += 512) {
            int r = i >> 4, c = i & 15;
            *(uint4*)(sA + r * 136 + c * 8) = asrc[i];
            *(uint4*)(sW1 + r * 136 + c * 8) = w1src[i];
            *(uint4*)(sW2 + r * 136 + c * 8) = w2src[i];
        }
        if (do_xf) {
            const uint4* w3src = (const uint4*)(g_cw1t + (size_t)(l + 1) * H * H);
            for (int i = tid; i < 2048; i += 512) {
                int r = i >> 4, c = i & 15;
                *(uint4*)(sW3 + r * 136 + c * 8) = w3src[i];
            }
        }
        if (tid < 128) {
            sB1[tid] = cb2[l * H + tid];
            sB2[tid] = ib[l * H + tid];
        }
    }
    __syncthreads();

    const int ar = 16 * wp + (lane & 15);
    const int ac = (lane >> 4) << 3;
    const int bn = lane & 7;
    const int bk = ((lane >> 3) & 1) * 8;
    const int ntb = wh * 8;
    const uint32_t sUb = smem_u32(sU);

    // ---- G1: agg @ cw2 -> ssp -> sU ----
    {
        float C1[8][4];
#pragma unroll
        for (int j = 0; j < 8; j++)
#pragma unroll
            for (int q = 0; q < 4; q++) C1[j][q] = 0.0f;
#pragma unroll
        for (int ks = 0; ks < 8; ks++) {
            uint32_t A[4];
            ldm_x4(A[0], A[1], A[2], A[3], smem_u32(sA + ar * 136 + ks * 16 + ac));
#pragma unroll
            for (int j = 0; j < 8; j++) {
                uint32_t B[2];
                ldm_x2(B[0], B[1], smem_u32(sW1 + ((ntb + j) * 8 + bn) * 136 + ks * 16 + bk));
                mma16816(C1[j], A, B);
            }
        }
#pragma unroll
        for (int j = 0; j < 8; j++) {
            int col = (ntb + j) * 8 + 2 * t;
            float b0 = sB1[col], b1v = sB1[col + 1];
            float u0 = ssp(C1[j][0] + b0), u1 = ssp(C1[j][1] + b1v);
            float u2 = ssp(C1[j][2] + b0), u3 = ssp(C1[j][3] + b1v);
            sts32(sUb + ((16 * wp + g) * 136 + col) * 2, h2u(u0, u1));
            sts32(sUb + ((16 * wp + 8 + g) * 136 + col) * 2, h2u(u2, u3));
        }
    }
    __syncthreads();

    // ---- G2: U @ iw -> h update; hnew also back to sU ----
    float C2[8][4];
#pragma unroll
    for (int j = 0; j < 8; j++)
#pragma unroll
        for (int q = 0; q < 4; q++) C2[j][q] = 0.0f;
#pragma unroll
    for (int ks = 0; ks < 8; ks++) {
        uint32_t A[4];
        ldm_x4(A[0], A[1], A[2], A[3], smem_u32(sU + ar * 136 + ks * 16 + ac));
#pragma unroll
        for (int j = 0; j < 8; j++) {
            uint32_t B[2];
            ldm_x2(B[0], B[1], smem_u32(sW2 + ((ntb + j) * 8 + bn) * 136 + ks * 16 + bk));
            mma16816(C2[j], A, B);
        }
    }
    __syncthreads();    // all G2 ldmatrix reads of sU done before overwrite
    {
        const int r0 = tile * 128 + 16 * wp + g;
#pragma unroll
        for (int j = 0; j < 8; j++) {
            int col = (ntb + j) * 8 + 2 * t;
            float b0 = sB2[col], b1v = sB2[col + 1];
            float2 h0 = *(float2*)(g_h + (size_t)r0 * H + col);
            float2 h1 = *(float2*)(g_h + (size_t)(r0 + 8) * H + col);
            float n00 = h0.x + C2[j][0] + b0, n01 = h0.y + C2[j][1] + b1v;
            float n10 = h1.x + C2[j][2] + b0, n11 = h1.y + C2[j][3] + b1v;
            *(float2*)(g_h + (size_t)r0 * H + col) = make_float2(n00, n01);
            *(float2*)(g_h + (size_t)(r0 + 8) * H + col) = make_float2(n10, n11);
            uint32_t p0 = h2u(n00, n01), p1 = h2u(n10, n11);
            *(uint32_t*)(g_hhf + (size_t)r0 * H + col) = p0;
            *(uint32_t*)(g_hhf + (size_t)(r0 + 8) * H + col) = p1;
            sts32(sUb + ((16 * wp + g) * 136 + col) * 2, p0);
            sts32(sUb + ((16 * wp + 8 + g) * 136 + col) * 2, p1);
        }
    }
    if (!do_xf) return;
    __syncthreads();

    // ---- G3: hnew @ cw1[l+1] -> xf ----
    {
        float C3[8][4];
#pragma unroll
        for (int j = 0; j < 8; j++)
#pragma unroll
            for (int q = 0; q < 4; q++) C3[j][q] = 0.0f;
#pragma unroll
        for (int ks = 0; ks < 8; ks++) {
            uint32_t A[4];
            ldm_x4(A[0], A[1], A[2], A[3], smem_u32(sU + ar * 136 + ks * 16 + ac));
#pragma unroll
            for (int j = 0; j < 8; j++) {
                uint32_t B[2];
                ldm_x2(B[0], B[1], smem_u32(sW3 + ((ntb + j) * 8 + bn) * 136 + ks * 16 + bk));
                mma16816(C3[j], A, B);
            }
        }
        const int r0 = tile * 128 + 16 * wp + g;
#pragma unroll
        for (int j = 0; j < 8; j++) {
            int col = (ntb + j) * 8 + 2 * t;
            *(uint32_t*)(g_xfh + (size_t)r0 * H + col) = h2u(C3[j][0], C3[j][1]);
            *(uint32_t*)(g_xfh + (size_t)(r0 + 8) * H + col) = h2u(C3[j][2], C3[j][3]);
        }
    }
}

// ---------------- readout: 512 threads, smem-chained 2 GEMMs ----------------
// smem: sA 34816 | sU 34816 | sW1 34816 | sW2 34816 | sRed 8192 | b1 512 | b2 512
#define RS_A   0
#define RS_U   34816
#define RS_W1  69632
#define RS_W2  104448
#define RS_RED 139264
#define RS_B1  147456
#define RS_B2  147968
#define RS_TOT 148480
__global__ void __launch_bounds__(512, 1)
readout_kernel(const float* __restrict__ ob1, const float* __restrict__ ob2) {
    extern __shared__ char sm[];
    __half* sA = (__half*)(sm + RS_A);
    __half* sU = (__half*)(sm + RS_U);
    __half* sW1 = (__half*)(sm + RS_W1);
    __half* sW2 = (__half*)(sm + RS_W2);
    float* sRed = (float*)(sm + RS_RED);
    float* sB1 = (float*)(sm + RS_B1);
    float* sB2 = (float*)(sm + RS_B2);
    const int tid = threadIdx.x, w = tid >> 5, lane = tid & 31;
    const int wp = w >> 1, wh = w & 1;
    const int g = lane >> 2, t = lane & 3;
    const int tile = blockIdx.x;
    const uint32_t sUb = smem_u32(sU);

    {
        const uint4* asrc = (const uint4*)(g_hhf + (size_t)tile * 128 * H);
        const uint4* w1src = (const uint4*)g_ow1t;
        const uint4* w2src = (const uint4*)g_ow2t;
        for (int i = tid; i < 2048; i += 512) {
            int r = i >> 4, c = i & 15;
            *(uint4*)(sA + r * 136 + c * 8) = asrc[i];
            *(uint4*)(sW1 + r * 136 + c * 8) = w1src[i];
            *(uint4*)(sW2 + r * 136 + c * 8) = w2src[i];
        }
        for (int i = tid; i < 2048; i += 512) sRed[i] = 0.0f;
        if (tid < 128) {
            sB1[tid] = ob1[tid];
            sB2[tid] = ob2[tid];
        }
    }
    __syncthreads();

    const int ar = 16 * wp + (lane & 15);
    const int ac = (lane >> 4) << 3;
    const int bn = lane & 7;
    const int bk = ((lane >> 3) & 1) * 8;
    const int ntb = wh * 8;

    // G1 -> ssp -> sU
    {
        float C1[8][4];
#pragma unroll
        for (int j = 0; j < 8; j++)
#pragma unroll
            for (int q = 0; q < 4; q++) C1[j][q] = 0.0f;
#pragma unroll
        for (int ks = 0; ks < 8; ks++) {
            uint32_t A[4];
            ldm_x4(A[0], A[1], A[2], A[3], smem_u32(sA + ar * 136 + ks * 16 + ac));
#pragma unroll
            for (int j = 0; j < 8; j++) {
                uint32_t B[2];
                ldm_x2(B[0], B[1], smem_u32(sW1 + ((ntb + j) * 8 + bn) * 136 + ks * 16 + bk));
                mma16816(C1[j], A, B);
            }
        }
#pragma unroll
        for (int j = 0; j < 8; j++) {
            int col = (ntb + j) * 8 + 2 * t;
            float b0 = sB1[col], b1v = sB1[col + 1];
            float u0 = ssp(C1[j][0] + b0), u1 = ssp(C1[j][1] + b1v);
            float u2 = ssp(C1[j][2] + b0), u3 = ssp(C1[j][3] + b1v);
            sts32(sUb + ((16 * wp + g) * 136 + col) * 2, h2u(u0, u1));
            sts32(sUb + ((16 * wp + 8 + g) * 136 + col) * 2, h2u(u2, u3));
        }
    }
    __syncthreads();

    // G2 -> +bias -> per-warp 16-row column sums -> sRed
    {
        float C2[8][4];
#pragma unroll
        for (int j = 0; j < 8; j++)
#pragma unroll
            for (int q = 0; q < 4; q++) C2[j][q] = 0.0f;
#pragma unroll
        for (int ks = 0; ks < 8; ks++) {
            uint32_t A[4];
            ldm_x4(A[0], A[1], A[2], A[3], smem_u32(sU + ar * 136 + ks * 16 + ac));
#pragma unroll
            for (int j = 0; j < 8; j++) {
                uint32_t B[2];
                ldm_x2(B[0], B[1], smem_u32(sW2 + ((ntb + j) * 8 + bn) * 136 + ks * 16 + bk));
                mma16816(C2[j], A, B);
            }
        }
#pragma unroll
        for (int j = 0; j < 8; j++) {
            int col = (ntb + j) * 8 + 2 * t;
            float b0 = sB2[col], b1v = sB2[col + 1];
            float s0 = (C2[j][0] + b0) + (C2[j][2] + b0);
            float s1 = (C2[j][1] + b1v) + (C2[j][3] + b1v);
            s0 += __shfl_xor_sync(0xFFFFFFFFu, s0, 4);
            s0 += __shfl_xor_sync(0xFFFFFFFFu, s0, 8);
            s0 += __shfl_xor_sync(0xFFFFFFFFu, s0, 16);
            s1 += __shfl_xor_sync(0xFFFFFFFFu, s1, 4);
            s1 += __shfl_xor_sync(0xFFFFFFFFu, s1, 8);
            s1 += __shfl_xor_sync(0xFFFFFFFFu, s1, 16);
            if (lane < 4) {
                sRed[w * 128 + col] = s0;
                sRed[w * 128 + col + 1] = s1;
            }
        }
    }
    __syncthreads();
    for (int i = tid; i < 256; i += 512) {
        int p = i >> 7, c = i & 127;
        float v = 0.0f;
#pragma unroll
        for (int k = 0; k < 8; k++) v += sRed[(p * 8 + k) * 128 + c];
        g_conf[(size_t)(2 * tile + p) * H + c] = v;
    }
}

// ---------------- final: mol sum + head MLP ----------------
__global__ void __launch_bounds__(256, 1)
final_kernel(const float* __restrict__ hw1, const float* __restrict__ hb1,
             const float* __restrict__ hw2, const float* __restrict__ hb2,
             float* __restrict__ out) {
    extern __shared__ char sm[];
    float* s_mol = (float*)sm;
    float* s_hid = (float*)sm + 8192;
    const int tid = threadIdx.x;
    for (int idx = tid; idx < N_MOL * H; idx += 256) {
        int m = idx >> 7, c = idx & 127;
        s_mol[idx] = g_conf[(m * 4 + 0) * H + c] + g_conf[(m * 4 + 1) * H + c]
                   + g_conf[(m * 4 + 2) * H + c] + g_conf[(m * 4 + 3) * H + c];
    }
    __syncthreads();
    for (int idx = tid; idx < N_MOL * 64; idx += 256) {
        int m = idx >> 6, j = idx & 63;
        float acc = hb1[j];
#pragma unroll 4
        for (int k = 0; k < H; k++) acc += s_mol[m * H + k] * hw1[k * 64 + j];
        s_hid[idx] = ssp(acc);
    }
    __syncthreads();
    if (tid < N_MOL) {
        float acc = hb2[0];
#pragma unroll 4
        for (int j = 0; j < 64; j++) acc += s_hid[tid * 64 + j] * hw2[j];
        out[tid] = acc;
    }
}

// ---------------- launch ----------------
extern "C" void kernel_launch(void* const* d_in, const int* in_sizes, int n_in,
                              void* d_out, int out_size) {
    const int*   z   = (const int*)d_in[0];
    const float* pos = (const float*)d_in[1];
    const int*   ei  = (const int*)d_in[2];
    const float* emb = (const float*)d_in[5];
    const float* mw1 = (const float*)d_in[6];
    const float* mb1 = (const float*)d_in[7];
    const float* mw2 = (const float*)d_in[8];
    const float* mb2 = (const float*)d_in[9];
    const float* cw1 = (const float*)d_in[10];
    const float* cw2 = (const float*)d_in[11];
    const float* cb2 = (const float*)d_in[12];
    const float* iw  = (const float*)d_in[13];
    const float* ib  = (const float*)d_in[14];
    const float* ow1 = (const float*)d_in[15];
    const float* ob1 = (const float*)d_in[16];
    const float* ow2 = (const float*)d_in[17];
    const float* ob2 = (const float*)d_in[18];
    const float* hw1 = (const float*)d_in[19];
    const float* hb1 = (const float*)d_in[20];
    const float* hw2 = (const float*)d_in[21];
    const float* hb2 = (const float*)d_in[22];
    float* out = (float*)d_out;

    cudaFuncSetAttribute(tab_kernel, cudaFuncAttributeMaxDynamicSharedMemorySize, TS_TOT);
    cudaFuncSetAttribute(xf_kernel, cudaFuncAttributeMaxDynamicSharedMemorySize, 69632);
    cudaFuncSetAttribute(node_kernel, cudaFuncAttributeMaxDynamicSharedMemorySize, NS_TOT);
    cudaFuncSetAttribute(readout_kernel, cudaFuncAttributeMaxDynamicSharedMemorySize, RS_TOT);
    cudaFuncSetAttribute(final_kernel, cudaFuncAttributeMaxDynamicSharedMemorySize, 49152);

    const int WTOT = S1 + 4 * S2 + 2 * S6;
    prep_weights<<<(WTOT + 255) / 256, 256>>>(mw1, mw2, cw1, cw2, iw, ow1, ow2);
    gauss_tab_kernel<<<TAB, 64>>>();
    tab_kernel<<<NLAYER * (TAB / 256), 256, TS_TOT>>>(mb1, mb2);
    epre_kernel<<<EDGES / 256, 256>>>(pos, ei);
    hinit_kernel<<<(N_ATOMS * H) / 256, 256>>>(z, emb);

    xf_kernel<<<N_ATOMS / 128, 512, 69632>>>(0);
    for (int l = 0; l < NLAYER; l++) {
        edge_kernel<<<EDGES / 256, 256>>>(l);
        node_kernel<<<N_ATOMS / 128, 512, NS_TOT>>>(cb2, ib, l, l < NLAYER - 1);
    }
    readout_kernel<<<N_ATOMS / 128, 512, RS_TOT>>>(ob1, ob2);
    final_kernel<<<1, 256, 49152>>>(hw1, hb1, hw2, hb2, out);
}